// round 2
// baseline (speedup 1.0000x reference)
#include <cuda_runtime.h>
#include <math.h>
#include <stdint.h>

#define BB 4096
#define NU 6
#define IND 600
#define HH 600
#define VDD 400
#define KD 64
#define KDC 32
#define NHC 4

// ---------------- scratch (device globals; no allocation allowed) ----------------
__device__ float g_xk[BB * KD];                       // x @ Wk
__device__ float g_xv[BB * VDD];                      // x @ Wv
__device__ float g_qry[BB * NU * KD];                 // [b][u][64]
__device__ float g_scale[BB * NU];                    // mask * sigmoid(score)
__device__ float g_mask[BB * NU];
__device__ float g_hb[BB * NU * HH];                  // h_t
__device__ float g_ck[BB * NU * 128];                 // [b][u][128]
__device__ float g_cq[BB * NU * 128];
__device__ float g_big1[(size_t)BB * NU * 2400];      // preact, then reused for cv
__device__ float g_big2[(size_t)BB * NU * 2400];      // ctx

// ---------------- generic batched GEMM: C = A(MxK) @ W(KxN row-major) ------------
// EPI: 0 = store, 1 = row-scale store (C = S[m]*acc), 2 = accumulate (C += acc),
//      3 = masked output: C = S[m]>0.5 ? acc + E1[m,n] : E2[m,n]
template <int BM, int BN, int BK, int TM, int TN, int EPI>
__global__ void __launch_bounds__((BM / TM) * (BN / TN))
gemm_kernel(const float* __restrict__ A, int lda, long long sA,
            const float* __restrict__ W, long long sW,
            float* __restrict__ C, int ldc, long long sC,
            int M, int N, int K,
            const float* __restrict__ S, long long sS, int sRow,
            const float* __restrict__ E1, long long sE1, int e1ld,
            const float* __restrict__ E2, long long sE2, int e2ld)
{
    constexpr int TX = BN / TN;
    constexpr int TY = BM / TM;
    constexpr int NT = TX * TY;

    __shared__ __align__(16) float As[BK][BM];
    __shared__ __align__(16) float Bs[BK][BN];

    const int z = blockIdx.z;
    A += (long long)z * sA;
    W += (long long)z * sW;
    C += (long long)z * sC;
    if (EPI == 1 || EPI == 3) S += (long long)z * sS;
    if (EPI == 3) { E1 += (long long)z * sE1; E2 += (long long)z * sE2; }

    const int tid = threadIdx.x;
    const int tx = tid % TX;
    const int ty = tid / TX;
    const int m0 = blockIdx.y * BM;
    const int n0 = blockIdx.x * BN;

    float acc[TM][TN];
#pragma unroll
    for (int i = 0; i < TM; i++)
#pragma unroll
        for (int j = 0; j < TN; j++) acc[i][j] = 0.0f;

    // A loader: each thread loads float4(s); BK assumed %4==0, K assumed %BK==0
    constexpr int A_TPR = BK / 4;            // threads per A row
    const int ar = tid / A_TPR;
    const int ac = (tid % A_TPR) * 4;
    constexpr int A_RPP = NT / A_TPR;
    // W loader
    constexpr int B_TPR = BN / 4;
    const int wr0 = tid / B_TPR;
    const int wc = (tid % B_TPR) * 4;
    constexpr int B_RPP = NT / B_TPR;

    for (int k0 = 0; k0 < K; k0 += BK) {
        __syncthreads();
#pragma unroll
        for (int r = ar; r < BM; r += A_RPP) {
            float4 v = make_float4(0.f, 0.f, 0.f, 0.f);
            int m = m0 + r;
            if (m < M) v = *(const float4*)(A + (long long)m * lda + k0 + ac);
            As[ac + 0][r] = v.x;
            As[ac + 1][r] = v.y;
            As[ac + 2][r] = v.z;
            As[ac + 3][r] = v.w;
        }
#pragma unroll
        for (int r = wr0; r < BK; r += B_RPP) {
            float4 v = make_float4(0.f, 0.f, 0.f, 0.f);
            int n = n0 + wc;
            if (n < N) v = *(const float4*)(W + (long long)(k0 + r) * N + n);
            *(float4*)&Bs[r][wc] = v;
        }
        __syncthreads();

#pragma unroll
        for (int kk = 0; kk < BK; kk++) {
            float af[TM], bf[TN];
#pragma unroll
            for (int i = 0; i < TM; i += 4)
                *(float4*)&af[i] = *(const float4*)&As[kk][ty * TM + i];
#pragma unroll
            for (int j = 0; j < TN; j += 4)
                *(float4*)&bf[j] = *(const float4*)&Bs[kk][tx * TN + j];
#pragma unroll
            for (int i = 0; i < TM; i++)
#pragma unroll
                for (int j = 0; j < TN; j++)
                    acc[i][j] = fmaf(af[i], bf[j], acc[i][j]);
        }
    }

    const int nb = n0 + tx * TN;
    if (nb >= N) return;  // N % TN == 0 by construction -> whole thread in/out
#pragma unroll
    for (int i = 0; i < TM; i++) {
        int m = m0 + ty * TM + i;
        if (m >= M) break;
        float* crow = C + (long long)m * ldc + nb;
        float sc = 0.f, mk = 0.f;
        const float* e1row = nullptr;
        const float* e2row = nullptr;
        if (EPI == 1) sc = S[m * sRow];
        if (EPI == 3) {
            mk = S[m * sRow];
            e1row = E1 + (long long)m * e1ld + nb;
            e2row = E2 + (long long)m * e2ld + nb;
        }
#pragma unroll
        for (int j = 0; j < TN; j += 4) {
            float4 v;
            v.x = acc[i][j + 0]; v.y = acc[i][j + 1];
            v.z = acc[i][j + 2]; v.w = acc[i][j + 3];
            if (EPI == 1) {
                v.x *= sc; v.y *= sc; v.z *= sc; v.w *= sc;
            } else if (EPI == 2) {
                float4 o = *(const float4*)(crow + j);
                v.x += o.x; v.y += o.y; v.z += o.z; v.w += o.w;
            } else if (EPI == 3) {
                if (mk > 0.5f) {
                    float4 o = *(const float4*)(e1row + j);
                    v.x += o.x; v.y += o.y; v.z += o.z; v.w += o.w;
                } else {
                    v = *(const float4*)(e2row + j);
                }
            }
            *(float4*)(crow + j) = v;
        }
    }
}

// ---------------- score + top-k + gate --------------------------------------------
__global__ void score_topk_kernel(const float* __restrict__ qry,
                                  const float* __restrict__ xk,
                                  float* __restrict__ scale,
                                  float* __restrict__ mask)
{
    int gw = (blockIdx.x * blockDim.x + threadIdx.x) >> 5;
    int lane = threadIdx.x & 31;
    if (gw >= BB) return;
    int b = gw;
    float xk0 = xk[b * 64 + lane];
    float xk1 = xk[b * 64 + 32 + lane];
    float s[NU];
#pragma unroll
    for (int u = 0; u < NU; u++) {
        const float* q = qry + b * (NU * 64) + u * 64;
        float v = q[lane] * xk0 + q[32 + lane] * xk1;
#pragma unroll
        for (int o = 16; o; o >>= 1) v += __shfl_xor_sync(0xffffffffu, v, o);
        s[u] = v * 0.125f;  // / sqrt(64)
    }
    if (lane == 0) {
#pragma unroll
        for (int u = 0; u < NU; u++) {
            int cnt = 0;
#pragma unroll
            for (int v = 0; v < NU; v++)
                if (s[v] > s[u] || (s[v] == s[u] && v < u)) cnt++;
            float m = (cnt < 4) ? 1.0f : 0.0f;
            mask[b * NU + u] = m;
            scale[b * NU + u] = m / (1.0f + expf(-s[u]));
        }
    }
}

// ---------------- LSTM gates -------------------------------------------------------
__global__ void lstm_kernel(const float* __restrict__ preact,
                            const float* __restrict__ cs,
                            const float* __restrict__ mask,
                            float* __restrict__ hb,
                            float* __restrict__ cs_out)
{
    int idx = blockIdx.x * blockDim.x + threadIdx.x;
    if (idx >= BB * NU * HH) return;
    int h = idx % HH;
    int bu = idx / HH;
    const float* p = preact + (size_t)bu * 2400;
    float ig = 1.0f / (1.0f + expf(-p[h]));
    float fg = 1.0f / (1.0f + expf(-p[HH + h]));
    float og = 1.0f / (1.0f + expf(-p[2 * HH + h]));
    float gg = tanhf(p[3 * HH + h]);
    float cp = cs[idx];
    float c = cp * fg + ig * gg;
    float ht = og * tanhf(c);
    hb[idx] = ht;
    cs_out[idx] = (mask[bu] > 0.5f) ? c : cp;
}

// ---------------- communication attention -----------------------------------------
__global__ void comm_attn_kernel(const float* __restrict__ cq,
                                 const float* __restrict__ ck,
                                 const float* __restrict__ cv,
                                 const float* __restrict__ mask,
                                 float* __restrict__ ctx)
{
    int b = blockIdx.x;
    int u = blockIdx.y;
    __shared__ float s_cq[128];
    __shared__ float s_scores[NHC][NU];
    __shared__ float s_probs[NHC][8];

    int t = threadIdx.x;  // 256
    if (t < 128) s_cq[t] = cq[(size_t)b * (NU * 128) + u * 128 + t];
    __syncthreads();

    int w = t >> 5, lane = t & 31;
    for (int p = w; p < NHC * NU; p += 8) {
        int hh = p / NU, m = p % NU;
        float v = s_cq[hh * 32 + lane] *
                  ck[(size_t)b * (NU * 128) + m * 128 + hh * 32 + lane];
#pragma unroll
        for (int o = 16; o; o >>= 1) v += __shfl_xor_sync(0xffffffffu, v, o);
        if (lane == 0) s_scores[hh][m] = v * 0.17677669529663687f;  // 1/sqrt(32)
    }
    __syncthreads();

    if (t < NHC) {
        float mx = -1e30f;
#pragma unroll
        for (int m = 0; m < NU; m++) mx = fmaxf(mx, s_scores[t][m]);
        float e[NU], sum = 0.f;
#pragma unroll
        for (int m = 0; m < NU; m++) { e[m] = expf(s_scores[t][m] - mx); sum += e[m]; }
        float inv = mask[b * NU + u] / sum;
#pragma unroll
        for (int m = 0; m < NU; m++) s_probs[t][m] = e[m] * inv;
    }
    __syncthreads();

    const float* cvb = cv + (size_t)b * (NU * 2400);
    float* outp = ctx + (size_t)b * (NU * 2400) + u * 2400;
    for (int i = t; i < 2400; i += 256) {
        int hh = i / 600;
        float a = 0.f;
#pragma unroll
        for (int m = 0; m < NU; m++) a += s_probs[hh][m] * cvb[m * 2400 + i];
        outp[i] = a;
    }
}

// ---------------- launch -----------------------------------------------------------
typedef void (*gemm_fn)(const float*, int, long long, const float*, long long,
                        float*, int, long long, int, int, int,
                        const float*, long long, int,
                        const float*, long long, int,
                        const float*, long long, int);

static inline dim3 gemm_grid(int M, int N, int BM, int BN, int batch)
{
    return dim3((N + BN - 1) / BN, (M + BM - 1) / BM, batch);
}

extern "C" void kernel_launch(void* const* d_in, const int* in_sizes, int n_in,
                              void* d_out, int out_size)
{
    const float* x    = (const float*)d_in[0];
    const float* hs   = (const float*)d_in[1];
    const float* cs   = (const float*)d_in[2];
    const float* Wk   = (const float*)d_in[3];
    const float* Wv   = (const float*)d_in[4];
    const float* Wq   = (const float*)d_in[5];
    const float* Wi2h = (const float*)d_in[6];
    const float* Wh2h = (const float*)d_in[7];
    const float* Wck  = (const float*)d_in[8];
    const float* Wcq  = (const float*)d_in[9];
    const float* Wcv  = (const float*)d_in[10];
    const float* Wco  = (const float*)d_in[11];

    float* out = (float*)d_out;
    float* hs_out = out;
    float* cs_out = out + (size_t)BB * NU * HH;

    float *xk, *xv, *qry, *scale, *mask, *hb, *ck, *cq, *big1, *big2;
    cudaGetSymbolAddress((void**)&xk, g_xk);
    cudaGetSymbolAddress((void**)&xv, g_xv);
    cudaGetSymbolAddress((void**)&qry, g_qry);
    cudaGetSymbolAddress((void**)&scale, g_scale);
    cudaGetSymbolAddress((void**)&mask, g_mask);
    cudaGetSymbolAddress((void**)&hb, g_hb);
    cudaGetSymbolAddress((void**)&ck, g_ck);
    cudaGetSymbolAddress((void**)&cq, g_cq);
    cudaGetSymbolAddress((void**)&big1, g_big1);
    cudaGetSymbolAddress((void**)&big2, g_big2);

    const int NT_BIG = 256;   // 128x128 tile, 8x8 per thread
    const int NT_SM  = 256;   // 128x64 tile, 8x4 per thread

    // 1. xk = x @ Wk   (4096x600x64)
    gemm_kernel<128, 64, 8, 8, 4, 0><<<gemm_grid(BB, KD, 128, 64, 1), NT_SM>>>(
        x, IND, 0, Wk, 0, xk, KD, 0, BB, KD, IND,
        nullptr, 0, 0, nullptr, 0, 0, nullptr, 0, 0);

    // 2. xv = x @ Wv   (4096x600x400)
    gemm_kernel<128, 128, 8, 8, 8, 0><<<gemm_grid(BB, VDD, 128, 128, 1), NT_BIG>>>(
        x, IND, 0, Wv, 0, xv, VDD, 0, BB, VDD, IND,
        nullptr, 0, 0, nullptr, 0, 0, nullptr, 0, 0);

    // 3. qry[u] = hs[:,u,:] @ Wq[u]  (batched over u)
    gemm_kernel<128, 64, 8, 8, 4, 0><<<gemm_grid(BB, KD, 128, 64, NU), NT_SM>>>(
        hs, NU * HH, HH, Wq, (long long)HH * KD, qry, NU * KD, KD, BB, KD, HH,
        nullptr, 0, 0, nullptr, 0, 0, nullptr, 0, 0);

    // 4. scores, top-4 mask, gate
    score_topk_kernel<<<(BB * 32 + 255) / 256, 256>>>(qry, xk, scale, mask);

    // 5. preact = scale * (xv @ Wi2h[u])    (EPI=1)
    gemm_kernel<128, 128, 8, 8, 8, 1><<<gemm_grid(BB, 2400, 128, 128, NU), NT_BIG>>>(
        xv, VDD, 0, Wi2h, (long long)VDD * 2400, big1, NU * 2400, 2400,
        BB, 2400, VDD, scale, 1, NU, nullptr, 0, 0, nullptr, 0, 0);

    // 6. preact += hs[:,u,:] @ Wh2h[u]      (EPI=2)
    gemm_kernel<128, 128, 8, 8, 8, 2><<<gemm_grid(BB, 2400, 128, 128, NU), NT_BIG>>>(
        hs, NU * HH, HH, Wh2h, (long long)HH * 2400, big1, NU * 2400, 2400,
        BB, 2400, HH, nullptr, 0, 0, nullptr, 0, 0, nullptr, 0, 0);

    // 7. LSTM gates -> h_b, cs_out
    lstm_kernel<<<(BB * NU * HH + 255) / 256, 256>>>(big1, cs, mask, hb, cs_out);

    // 8. ck = h_b @ Wck[u]  (N=128)
    gemm_kernel<128, 128, 8, 8, 8, 0><<<gemm_grid(BB, 128, 128, 128, NU), NT_BIG>>>(
        hb, NU * HH, HH, Wck, (long long)HH * 128, ck, NU * 128, 128, BB, 128, HH,
        nullptr, 0, 0, nullptr, 0, 0, nullptr, 0, 0);

    // 9. cq = h_b @ Wcq[u]
    gemm_kernel<128, 128, 8, 8, 8, 0><<<gemm_grid(BB, 128, 128, 128, NU), NT_BIG>>>(
        hb, NU * HH, HH, Wcq, (long long)HH * 128, cq, NU * 128, 128, BB, 128, HH,
        nullptr, 0, 0, nullptr, 0, 0, nullptr, 0, 0);

    // 10. cv = h_b @ Wcv[u]  (reuse big1; preact already consumed)
    gemm_kernel<128, 128, 8, 8, 8, 0><<<gemm_grid(BB, 2400, 128, 128, NU), NT_BIG>>>(
        hb, NU * HH, HH, Wcv, (long long)HH * 2400, big1, NU * 2400, 2400,
        BB, 2400, HH, nullptr, 0, 0, nullptr, 0, 0, nullptr, 0, 0);

    // 11. communication attention -> ctx (big2)
    comm_attn_kernel<<<dim3(BB, NU), 256>>>(cq, ck, big1, mask, big2);

    // 12. hs_out = mask ? ctx @ Wco[u] + h_b : hs   (EPI=3)
    gemm_kernel<128, 128, 8, 8, 8, 3><<<gemm_grid(BB, HH, 128, 128, NU), NT_BIG>>>(
        big2, NU * 2400, 2400, Wco, (long long)2400 * HH, hs_out, NU * HH, HH,
        BB, HH, 2400, mask, 1, NU, hb, HH, NU * HH, hs, HH, NU * HH);

    (void)in_sizes; (void)n_in; (void)out_size;
}

// round 4
// speedup vs baseline: 1.8539x; 1.8539x over previous
#include <cuda_runtime.h>
#include <cuda_bf16.h>
#include <math.h>
#include <stdint.h>

#define BB 4096
#define NU 6
#define IND 600
#define HH 600
#define VDD 400
#define KD 64
#define KP_PRE 1088   // 448 (xv) + 640 (hs)
#define KP_H   640
#define KP_CTX 2432
#define NP_BIG 2432
#define NP_H   640
#define NP_CK  128

// ------------------------- device scratch -------------------------
__device__ __align__(16) float g_xk[BB * KD];
__device__ __align__(16) float g_xv[BB * VDD];
__device__ __align__(16) float g_qry[BB * NU * KD];
__device__ __align__(16) float g_scale[BB * NU];
__device__ __align__(16) float g_mask[BB * NU];
__device__ __align__(16) float g_hb[(size_t)BB * NU * HH];
__device__ __align__(16) float g_preact[(size_t)BB * NU * 2400];
__device__ __align__(16) float g_cv[(size_t)BB * NU * 2400];
__device__ __align__(16) float g_ck[BB * NU * 128];
__device__ __align__(16) float g_cq[BB * NU * 128];

__device__ __align__(16) __nv_bfloat16 g_aph[(size_t)NU * BB * KP_PRE];
__device__ __align__(16) __nv_bfloat16 g_apl[(size_t)NU * BB * KP_PRE];
__device__ __align__(16) __nv_bfloat16 g_hbh[(size_t)NU * BB * KP_H];
__device__ __align__(16) __nv_bfloat16 g_hbl[(size_t)NU * BB * KP_H];
__device__ __align__(16) __nv_bfloat16 g_cxh[(size_t)NU * BB * KP_CTX];
__device__ __align__(16) __nv_bfloat16 g_cxl[(size_t)NU * BB * KP_CTX];
__device__ __align__(16) __nv_bfloat16 g_w12h[(size_t)NU * NP_BIG * KP_PRE];
__device__ __align__(16) __nv_bfloat16 g_w12l[(size_t)NU * NP_BIG * KP_PRE];
__device__ __align__(16) __nv_bfloat16 g_w3h[(size_t)NU * NP_BIG * KP_H];
__device__ __align__(16) __nv_bfloat16 g_w3l[(size_t)NU * NP_BIG * KP_H];
__device__ __align__(16) __nv_bfloat16 g_w4h[(size_t)NU * NP_H * KP_CTX];
__device__ __align__(16) __nv_bfloat16 g_w4l[(size_t)NU * NP_H * KP_CTX];
__device__ __align__(16) __nv_bfloat16 g_w5h[(size_t)NU * NP_CK * KP_H];
__device__ __align__(16) __nv_bfloat16 g_w5l[(size_t)NU * NP_CK * KP_H];
__device__ __align__(16) __nv_bfloat16 g_w6h[(size_t)NU * NP_CK * KP_H];
__device__ __align__(16) __nv_bfloat16 g_w6l[(size_t)NU * NP_CK * KP_H];

// ------------------------- helpers -------------------------
__device__ __forceinline__ uint32_t smem_u32(const void* p) {
    uint32_t a;
    asm("{ .reg .u64 t; cvta.to.shared.u64 t, %1; cvt.u32.u64 %0, t; }" : "=r"(a) : "l"(p));
    return a;
}
__device__ __forceinline__ void cp16(uint32_t dst, const void* src) {
    asm volatile("cp.async.cg.shared.global [%0], [%1], 16;\n" :: "r"(dst), "l"(src));
}
__device__ __forceinline__ void mma16816(float* c, const uint32_t* a, uint32_t b0, uint32_t b1) {
    asm volatile(
        "mma.sync.aligned.m16n8k16.row.col.f32.bf16.bf16.f32 "
        "{%0,%1,%2,%3}, {%4,%5,%6,%7}, {%8,%9}, {%0,%1,%2,%3};"
        : "+f"(c[0]), "+f"(c[1]), "+f"(c[2]), "+f"(c[3])
        : "r"(a[0]), "r"(a[1]), "r"(a[2]), "r"(a[3]), "r"(b0), "r"(b1));
}

// SMEM: per stage 4 tiles (Ah,Al,Bh,Bl), each 128 rows x 40 bf16 (80B stride)
#define TILE_B   10240
#define STAGE_B  40960
#define NSTAGE   3
#define SMEM_DYN (NSTAGE * STAGE_B + 16)

// ------------------------- HMMA GEMM -------------------------
// C[4096, Nreal] (unit z) = A[4096, Kpad] @ B[Npad, Kpad]^T  (3-term bf16 split)
// EPI 0: store.  EPI 3: C = S[m]>0.5 ? acc + E1 : E2.
template <int EPI>
__global__ void __launch_bounds__(256, 1)
hmma_gemm(const __nv_bfloat16* __restrict__ Ah, const __nv_bfloat16* __restrict__ Al,
          long long sA, int Kpad,
          const __nv_bfloat16* __restrict__ Bh, const __nv_bfloat16* __restrict__ Bl,
          long long sB,
          float* __restrict__ C, int ldc, int sC, int Nreal,
          const float* __restrict__ S,
          const float* __restrict__ E1, const float* __restrict__ E2, int ldE, int sE)
{
    extern __shared__ __align__(16) char dsm[];
    char* tiles = dsm;
    const uint32_t tiles_u32 = smem_u32(dsm);

    const int tid = threadIdx.x;
    const int wid = tid >> 5, lane = tid & 31;
    const int wm = wid >> 1, wn = wid & 1;         // 4 x 2 warps
    const int g = lane >> 2, t = lane & 3;

    const int z = blockIdx.z, m0 = blockIdx.y * 128, n0 = blockIdx.x * 128;
    const __nv_bfloat16* Azh = Ah + (size_t)z * sA + (size_t)m0 * Kpad;
    const __nv_bfloat16* Azl = Al + (size_t)z * sA + (size_t)m0 * Kpad;
    const __nv_bfloat16* Bzh = Bh + (size_t)z * sB + (size_t)n0 * Kpad;
    const __nv_bfloat16* Bzl = Bl + (size_t)z * sB + (size_t)n0 * Kpad;

    const int nch = Kpad >> 5;   // BK = 32

    // loader: per stage, 4 tiles x 512 16B-chunks; 256 thr x 2 chunks/tile
    const int idx0 = tid * 2, idx1 = tid * 2 + 1;
    const int r_0 = idx0 >> 2, c_0 = idx0 & 3;
    const int r_1 = idx1 >> 2, c_1 = idx1 & 3;

    auto load_chunk = [&](int kc, int st) {
        uint32_t sb = tiles_u32 + (uint32_t)st * STAGE_B;
        int k0 = kc << 5;
        const __nv_bfloat16* gp[4] = { Azh, Azl, Bzh, Bzl };
#pragma unroll
        for (int mmat = 0; mmat < 4; mmat++) {
            uint32_t mb = sb + (uint32_t)mmat * TILE_B;
            cp16(mb + r_0 * 80 + c_0 * 16, gp[mmat] + (size_t)r_0 * Kpad + k0 + c_0 * 8);
            cp16(mb + r_1 * 80 + c_1 * 16, gp[mmat] + (size_t)r_1 * Kpad + k0 + c_1 * 8);
        }
    };

    float acc[2][8][4];
#pragma unroll
    for (int a = 0; a < 2; a++)
#pragma unroll
        for (int b = 0; b < 8; b++)
#pragma unroll
            for (int c = 0; c < 4; c++) acc[a][b][c] = 0.f;

    load_chunk(0, 0);
    asm volatile("cp.async.commit_group;" ::: "memory");
    load_chunk(1, 1);
    asm volatile("cp.async.commit_group;" ::: "memory");

    for (int kc = 0; kc < nch; kc++) {
        asm volatile("cp.async.wait_group 1;" ::: "memory");
        __syncthreads();
        if (kc + 2 < nch) {
            load_chunk(kc + 2, (kc + 2) % NSTAGE);
            asm volatile("cp.async.commit_group;" ::: "memory");
        } else {
            // keep group count balanced so wait_group 1 semantics stay simple
            asm volatile("cp.async.commit_group;" ::: "memory");
        }

        const int st = kc % NSTAGE;
        const uint16_t* sAh = (const uint16_t*)(tiles + st * STAGE_B);
        const uint16_t* sAl = sAh + 5120;
        const uint16_t* sBh = sAh + 10240;
        const uint16_t* sBl = sAh + 15360;

#pragma unroll
        for (int s16 = 0; s16 < 2; s16++) {
            const int kb = s16 * 16 + 2 * t;
            uint32_t ah[2][4], al[2][4];
#pragma unroll
            for (int mt = 0; mt < 2; mt++) {
                const int r = wm * 32 + mt * 16 + g;
                const uint16_t* ph = sAh + r * 40 + kb;
                const uint16_t* pl = sAl + r * 40 + kb;
                ah[mt][0] = *(const uint32_t*)ph;
                ah[mt][1] = *(const uint32_t*)(ph + 8 * 40);
                ah[mt][2] = *(const uint32_t*)(ph + 8);
                ah[mt][3] = *(const uint32_t*)(ph + 8 * 40 + 8);
                al[mt][0] = *(const uint32_t*)pl;
                al[mt][1] = *(const uint32_t*)(pl + 8 * 40);
                al[mt][2] = *(const uint32_t*)(pl + 8);
                al[mt][3] = *(const uint32_t*)(pl + 8 * 40 + 8);
            }
#pragma unroll
            for (int nt = 0; nt < 8; nt++) {
                const int n = wn * 64 + nt * 8 + g;
                const uint16_t* qh = sBh + n * 40 + kb;
                const uint16_t* ql = sBl + n * 40 + kb;
                const uint32_t bh0 = *(const uint32_t*)qh;
                const uint32_t bh1 = *(const uint32_t*)(qh + 8);
                const uint32_t bl0 = *(const uint32_t*)ql;
                const uint32_t bl1 = *(const uint32_t*)(ql + 8);
#pragma unroll
                for (int mt = 0; mt < 2; mt++) {
                    mma16816(acc[mt][nt], ah[mt], bh0, bh1);
                    mma16816(acc[mt][nt], ah[mt], bl0, bl1);
                    mma16816(acc[mt][nt], al[mt], bh0, bh1);
                }
            }
        }
        __syncthreads();
    }

    // ----- epilogue -----
#pragma unroll
    for (int mt = 0; mt < 2; mt++) {
        const int r0 = m0 + wm * 32 + mt * 16 + g;
        const int r1 = r0 + 8;
        float mk0 = 0.f, mk1 = 0.f;
        if (EPI == 3) { mk0 = S[r0 * 6 + z]; mk1 = S[r1 * 6 + z]; }
        float* c0row = C + (size_t)r0 * ldc + (size_t)z * sC;
        float* c1row = C + (size_t)r1 * ldc + (size_t)z * sC;
        const float* e10 = (EPI == 3) ? E1 + (size_t)z * sE + (size_t)r0 * ldE : nullptr;
        const float* e11 = (EPI == 3) ? E1 + (size_t)z * sE + (size_t)r1 * ldE : nullptr;
        const float* e20 = (EPI == 3) ? E2 + (size_t)z * sE + (size_t)r0 * ldE : nullptr;
        const float* e21 = (EPI == 3) ? E2 + (size_t)z * sE + (size_t)r1 * ldE : nullptr;
#pragma unroll
        for (int nt = 0; nt < 8; nt++) {
            const int n = n0 + wn * 64 + nt * 8 + 2 * t;
            if (n < Nreal) {
                float2 v0 = make_float2(acc[mt][nt][0], acc[mt][nt][1]);
                float2 v1 = make_float2(acc[mt][nt][2], acc[mt][nt][3]);
                if (EPI == 3) {
                    if (mk0 > 0.5f) {
                        float2 o = *(const float2*)(e10 + n);
                        v0.x += o.x; v0.y += o.y;
                    } else v0 = *(const float2*)(e20 + n);
                    if (mk1 > 0.5f) {
                        float2 o = *(const float2*)(e11 + n);
                        v1.x += o.x; v1.y += o.y;
                    } else v1 = *(const float2*)(e21 + n);
                }
                *(float2*)(c0row + n) = v0;
                *(float2*)(c1row + n) = v1;
            }
        }
    }
}

// ------------------------- SIMT GEMM (small fp32) -------------------------
template <int BM, int BN, int BK, int TM, int TN>
__global__ void __launch_bounds__((BM / TM) * (BN / TN))
gemm_simt(const float* __restrict__ A, int lda, long long sA,
          const float* __restrict__ W, long long sW,
          float* __restrict__ C, int ldc, long long sC, int M, int N, int K)
{
    constexpr int TX = BN / TN, TY = BM / TM, NT = TX * TY;
    __shared__ __align__(16) float As[BK][BM];
    __shared__ __align__(16) float Bs[BK][BN];
    const int z = blockIdx.z;
    A += (long long)z * sA; W += (long long)z * sW; C += (long long)z * sC;
    const int tid = threadIdx.x, tx = tid % TX, ty = tid / TX;
    const int m0 = blockIdx.y * BM, n0 = blockIdx.x * BN;
    float acc[TM][TN];
#pragma unroll
    for (int i = 0; i < TM; i++)
#pragma unroll
        for (int j = 0; j < TN; j++) acc[i][j] = 0.f;
    constexpr int A_TPR = BK / 4;
    const int ar = tid / A_TPR, ac = (tid % A_TPR) * 4;
    constexpr int A_RPP = NT / A_TPR;
    constexpr int B_TPR = BN / 4;
    const int wr0 = tid / B_TPR, wc = (tid % B_TPR) * 4;
    constexpr int B_RPP = NT / B_TPR;
    for (int k0 = 0; k0 < K; k0 += BK) {
        __syncthreads();
#pragma unroll
        for (int r = ar; r < BM; r += A_RPP) {
            float4 v = make_float4(0.f, 0.f, 0.f, 0.f);
            int m = m0 + r;
            if (m < M) v = *(const float4*)(A + (long long)m * lda + k0 + ac);
            As[ac][r] = v.x; As[ac + 1][r] = v.y; As[ac + 2][r] = v.z; As[ac + 3][r] = v.w;
        }
#pragma unroll
        for (int r = wr0; r < BK; r += B_RPP) {
            float4 v = make_float4(0.f, 0.f, 0.f, 0.f);
            int n = n0 + wc;
            if (n < N) v = *(const float4*)(W + (long long)(k0 + r) * N + n);
            *(float4*)&Bs[r][wc] = v;
        }
        __syncthreads();
#pragma unroll
        for (int kk = 0; kk < BK; kk++) {
            float af[TM], bf[TN];
#pragma unroll
            for (int i = 0; i < TM; i += 4) *(float4*)&af[i] = *(const float4*)&As[kk][ty * TM + i];
#pragma unroll
            for (int j = 0; j < TN; j += 4) *(float4*)&bf[j] = *(const float4*)&Bs[kk][tx * TN + j];
#pragma unroll
            for (int i = 0; i < TM; i++)
#pragma unroll
                for (int j = 0; j < TN; j++) acc[i][j] = fmaf(af[i], bf[j], acc[i][j]);
        }
    }
    const int nb = n0 + tx * TN;
    if (nb >= N) return;
#pragma unroll
    for (int i = 0; i < TM; i++) {
        int m = m0 + ty * TM + i;
        if (m >= M) break;
#pragma unroll
        for (int j = 0; j < TN; j += 4) {
            float4 v;
            v.x = acc[i][j]; v.y = acc[i][j + 1]; v.z = acc[i][j + 2]; v.w = acc[i][j + 3];
            *(float4*)(C + (long long)m * ldc + nb + j) = v;
        }
    }
}

// ------------------- weight transpose + split: O[u][n][koff+k] = W[u][k][n] -------------------
__global__ void wtrans(const float* __restrict__ W, __nv_bfloat16* __restrict__ Oh,
                       __nv_bfloat16* __restrict__ Ol, int Kreal, int Nreal,
                       int KpadTot, int Npad, int koff)
{
    __shared__ float t[32][33];
    int u = blockIdx.z, kb = blockIdx.x * 32, nb = blockIdx.y * 32;
    const float* Wu = W + (size_t)u * Kreal * Nreal;
    int tx = threadIdx.x, ty0 = threadIdx.y;
#pragma unroll
    for (int yy = ty0; yy < 32; yy += 8) {
        int k = kb + yy, n = nb + tx;
        t[yy][tx] = (k < Kreal && n < Nreal) ? Wu[(size_t)k * Nreal + n] : 0.f;
    }
    __syncthreads();
    __nv_bfloat16* OhU = Oh + (size_t)u * Npad * KpadTot;
    __nv_bfloat16* OlU = Ol + (size_t)u * Npad * KpadTot;
#pragma unroll
    for (int yy = ty0; yy < 32; yy += 8) {
        int n = nb + yy, k = koff + kb + tx;
        float v = t[tx][yy];
        __nv_bfloat16 h = __float2bfloat16(v);
        OhU[(size_t)n * KpadTot + k] = h;
        OlU[(size_t)n * KpadTot + k] = __float2bfloat16(v - __bfloat162float(h));
    }
}

// ------------------- A_pre = [scale*xv | hs] split -------------------
__global__ void conv_pre(const float* __restrict__ xv, const float* __restrict__ hs,
                         const float* __restrict__ scale,
                         __nv_bfloat16* __restrict__ oh, __nv_bfloat16* __restrict__ ol)
{
    size_t idx = (size_t)blockIdx.x * blockDim.x + threadIdx.x;
    if (idx >= (size_t)NU * BB * KP_PRE) return;
    int k = (int)(idx % KP_PRE);
    int b = (int)((idx / KP_PRE) % BB);
    int u = (int)(idx / ((size_t)KP_PRE * BB));
    float v = 0.f;
    if (k < VDD) v = scale[b * NU + u] * xv[(size_t)b * VDD + k];
    else if (k >= 448 && k < 448 + HH) v = hs[(size_t)b * (NU * HH) + u * HH + (k - 448)];
    __nv_bfloat16 h = __float2bfloat16(v);
    oh[idx] = h;
    ol[idx] = __float2bfloat16(v - __bfloat162float(h));
}

// ------------------- score + top-k -------------------
__global__ void score_topk(const float* __restrict__ qry, const float* __restrict__ xk,
                           float* __restrict__ scale, float* __restrict__ mask)
{
    int gw = (blockIdx.x * blockDim.x + threadIdx.x) >> 5;
    int lane = threadIdx.x & 31;
    if (gw >= BB) return;
    int b = gw;
    float xk0 = xk[b * 64 + lane], xk1 = xk[b * 64 + 32 + lane];
    float s[NU];
#pragma unroll
    for (int u = 0; u < NU; u++) {
        const float* q = qry + b * (NU * 64) + u * 64;
        float v = q[lane] * xk0 + q[32 + lane] * xk1;
#pragma unroll
        for (int o = 16; o; o >>= 1) v += __shfl_xor_sync(~0u, v, o);
        s[u] = v * 0.125f;
    }
    if (lane == 0) {
#pragma unroll
        for (int u = 0; u < NU; u++) {
            int cnt = 0;
#pragma unroll
            for (int v = 0; v < NU; v++)
                if (s[v] > s[u] || (s[v] == s[u] && v < u)) cnt++;
            float m = (cnt < 4) ? 1.f : 0.f;
            mask[b * NU + u] = m;
            scale[b * NU + u] = m / (1.f + expf(-s[u]));
        }
    }
}

// ------------------- LSTM -> hb fp32 + split, cs_out -------------------
__global__ void lstm(const float* __restrict__ preact, const float* __restrict__ cs,
                     const float* __restrict__ mask, float* __restrict__ hb,
                     __nv_bfloat16* __restrict__ hbh, __nv_bfloat16* __restrict__ hbl,
                     float* __restrict__ cs_out)
{
    size_t idx = (size_t)blockIdx.x * blockDim.x + threadIdx.x;
    if (idx >= (size_t)BB * NU * KP_H) return;
    int k = (int)(idx % KP_H);
    int bu = (int)(idx / KP_H);
    int b = bu / NU, u = bu % NU;
    size_t hidx = ((size_t)u * BB + b) * KP_H + k;
    float ht = 0.f;
    if (k < HH) {
        const float* p = preact + (size_t)bu * 2400;
        float ig = 1.f / (1.f + expf(-p[k]));
        float fg = 1.f / (1.f + expf(-p[HH + k]));
        float og = 1.f / (1.f + expf(-p[2 * HH + k]));
        float gg = tanhf(p[3 * HH + k]);
        float cp = cs[(size_t)bu * HH + k];
        float c = cp * fg + ig * gg;
        ht = og * tanhf(c);
        hb[(size_t)bu * HH + k] = ht;
        cs_out[(size_t)bu * HH + k] = (mask[bu] > 0.5f) ? c : cp;
    }
    __nv_bfloat16 h = __float2bfloat16(ht);
    hbh[hidx] = h;
    hbl[hidx] = __float2bfloat16(ht - __bfloat162float(h));
}

// ------------------- comm attention -> ctx split -------------------
__global__ void comm_attn(const float* __restrict__ cq, const float* __restrict__ ck,
                          const float* __restrict__ cv, const float* __restrict__ mask,
                          __nv_bfloat16* __restrict__ cxh, __nv_bfloat16* __restrict__ cxl)
{
    int u = blockIdx.x, b = blockIdx.y;
    __shared__ float s_cq[128], s_sc[4][NU], s_pr[4][8];
    int t = threadIdx.x;
    if (t < 128) s_cq[t] = cq[(size_t)b * (NU * 128) + u * 128 + t];
    __syncthreads();
    int w = t >> 5, lane = t & 31;
    for (int p = w; p < 4 * NU; p += 8) {
        int hh = p / NU, m = p % NU;
        float v = s_cq[hh * 32 + lane] * ck[(size_t)b * (NU * 128) + m * 128 + hh * 32 + lane];
#pragma unroll
        for (int o = 16; o; o >>= 1) v += __shfl_xor_sync(~0u, v, o);
        if (lane == 0) s_sc[hh][m] = v * 0.17677669529663687f;
    }
    __syncthreads();
    if (t < 4) {
        float mx = -1e30f;
#pragma unroll
        for (int m = 0; m < NU; m++) mx = fmaxf(mx, s_sc[t][m]);
        float e[NU], sum = 0.f;
#pragma unroll
        for (int m = 0; m < NU; m++) { e[m] = expf(s_sc[t][m] - mx); sum += e[m]; }
        float inv = mask[b * NU + u] / sum;
#pragma unroll
        for (int m = 0; m < NU; m++) s_pr[t][m] = e[m] * inv;
    }
    __syncthreads();
    const float* cvb = cv + (size_t)b * (NU * 2400);
    size_t ob = ((size_t)u * BB + b) * KP_CTX;
    for (int i = t; i < KP_CTX; i += 256) {
        float a = 0.f;
        if (i < 2400) {
            int hh = i / 600;
#pragma unroll
            for (int m = 0; m < NU; m++) a += s_pr[hh][m] * cvb[m * 2400 + i];
        }
        __nv_bfloat16 h = __float2bfloat16(a);
        cxh[ob + i] = h;
        cxl[ob + i] = __float2bfloat16(a - __bfloat162float(h));
    }
}

// ------------------------- launch -------------------------
extern "C" void kernel_launch(void* const* d_in, const int* in_sizes, int n_in,
                              void* d_out, int out_size)
{
    const float* x    = (const float*)d_in[0];
    const float* hs   = (const float*)d_in[1];
    const float* cs   = (const float*)d_in[2];
    const float* Wk   = (const float*)d_in[3];
    const float* Wv   = (const float*)d_in[4];
    const float* Wq   = (const float*)d_in[5];
    const float* Wi2h = (const float*)d_in[6];
    const float* Wh2h = (const float*)d_in[7];
    const float* Wck  = (const float*)d_in[8];
    const float* Wcq  = (const float*)d_in[9];
    const float* Wcv  = (const float*)d_in[10];
    const float* Wco  = (const float*)d_in[11];

    float* hs_out = (float*)d_out;
    float* cs_out = hs_out + (size_t)BB * NU * HH;

    float *xk, *xv, *qry, *scale, *mask, *hb, *preact, *cv, *ck, *cq;
    __nv_bfloat16 *aph, *apl, *hbh, *hbl, *cxh, *cxl;
    __nv_bfloat16 *w12h, *w12l, *w3h, *w3l, *w4h, *w4l, *w5h, *w5l, *w6h, *w6l;
    cudaGetSymbolAddress((void**)&xk, g_xk);       cudaGetSymbolAddress((void**)&xv, g_xv);
    cudaGetSymbolAddress((void**)&qry, g_qry);     cudaGetSymbolAddress((void**)&scale, g_scale);
    cudaGetSymbolAddress((void**)&mask, g_mask);   cudaGetSymbolAddress((void**)&hb, g_hb);
    cudaGetSymbolAddress((void**)&preact, g_preact); cudaGetSymbolAddress((void**)&cv, g_cv);
    cudaGetSymbolAddress((void**)&ck, g_ck);       cudaGetSymbolAddress((void**)&cq, g_cq);
    cudaGetSymbolAddress((void**)&aph, g_aph);     cudaGetSymbolAddress((void**)&apl, g_apl);
    cudaGetSymbolAddress((void**)&hbh, g_hbh);     cudaGetSymbolAddress((void**)&hbl, g_hbl);
    cudaGetSymbolAddress((void**)&cxh, g_cxh);     cudaGetSymbolAddress((void**)&cxl, g_cxl);
    cudaGetSymbolAddress((void**)&w12h, g_w12h);   cudaGetSymbolAddress((void**)&w12l, g_w12l);
    cudaGetSymbolAddress((void**)&w3h, g_w3h);     cudaGetSymbolAddress((void**)&w3l, g_w3l);
    cudaGetSymbolAddress((void**)&w4h, g_w4h);     cudaGetSymbolAddress((void**)&w4l, g_w4l);
    cudaGetSymbolAddress((void**)&w5h, g_w5h);     cudaGetSymbolAddress((void**)&w5l, g_w5l);
    cudaGetSymbolAddress((void**)&w6h, g_w6h);     cudaGetSymbolAddress((void**)&w6l, g_w6l);

    cudaFuncSetAttribute(hmma_gemm<0>, cudaFuncAttributeMaxDynamicSharedMemorySize, SMEM_DYN);
    cudaFuncSetAttribute(hmma_gemm<3>, cudaFuncAttributeMaxDynamicSharedMemorySize, SMEM_DYN);

    dim3 tb(32, 8);
    wtrans<<<dim3(14, NP_BIG / 32, NU), tb>>>(Wi2h, w12h, w12l, 400, 2400, KP_PRE, NP_BIG, 0);
    wtrans<<<dim3(20, NP_BIG / 32, NU), tb>>>(Wh2h, w12h, w12l, 600, 2400, KP_PRE, NP_BIG, 448);
    wtrans<<<dim3(20, NP_BIG / 32, NU), tb>>>(Wcv, w3h, w3l, 600, 2400, KP_H, NP_BIG, 0);
    wtrans<<<dim3(76, NP_H / 32, NU), tb>>>(Wco, w4h, w4l, 2400, 600, KP_CTX, NP_H, 0);
    wtrans<<<dim3(20, NP_CK / 32, NU), tb>>>(Wck, w5h, w5l, 600, 128, KP_H, NP_CK, 0);
    wtrans<<<dim3(20, NP_CK / 32, NU), tb>>>(Wcq, w6h, w6l, 600, 128, KP_H, NP_CK, 0);

    gemm_simt<128, 64, 8, 8, 4><<<dim3(1, 32, 1), 256>>>(x, IND, 0, Wk, 0, xk, KD, 0, BB, KD, IND);
    gemm_simt<128, 128, 8, 8, 8><<<dim3(4, 32, 1), 256>>>(x, IND, 0, Wv, 0, xv, VDD, 0, BB, VDD, IND);
    gemm_simt<128, 64, 8, 8, 4><<<dim3(1, 32, NU), 256>>>(
        hs, NU * HH, HH, Wq, (long long)HH * KD, qry, NU * KD, KD, BB, KD, HH);

    score_topk<<<(BB * 32 + 255) / 256, 256>>>(qry, xk, scale, mask);
    conv_pre<<<(int)(((size_t)NU * BB * KP_PRE + 255) / 256), 256>>>(xv, hs, scale, aph, apl);

    // preact = scale*(xv@Wi2h) + hs@Wh2h  (fused, K=1088)
    hmma_gemm<0><<<dim3(19, 32, NU), 256, SMEM_DYN>>>(
        aph, apl, (long long)BB * KP_PRE, KP_PRE, w12h, w12l, (long long)NP_BIG * KP_PRE,
        preact, NU * 2400, 2400, 2400, nullptr, nullptr, nullptr, 0, 0);

    lstm<<<(int)(((size_t)BB * NU * KP_H + 255) / 256), 256>>>(
        preact, cs, mask, hb, hbh, hbl, cs_out);

    hmma_gemm<0><<<dim3(1, 32, NU), 256, SMEM_DYN>>>(
        hbh, hbl, (long long)BB * KP_H, KP_H, w5h, w5l, (long long)NP_CK * KP_H,
        ck, NU * 128, 128, 128, nullptr, nullptr, nullptr, 0, 0);
    hmma_gemm<0><<<dim3(1, 32, NU), 256, SMEM_DYN>>>(
        hbh, hbl, (long long)BB * KP_H, KP_H, w6h, w6l, (long long)NP_CK * KP_H,
        cq, NU * 128, 128, 128, nullptr, nullptr, nullptr, 0, 0);
    hmma_gemm<0><<<dim3(19, 32, NU), 256, SMEM_DYN>>>(
        hbh, hbl, (long long)BB * KP_H, KP_H, w3h, w3l, (long long)NP_BIG * KP_H,
        cv, NU * 2400, 2400, 2400, nullptr, nullptr, nullptr, 0, 0);

    comm_attn<<<dim3(NU, BB), 256>>>(cq, ck, cv, mask, cxh, cxl);

    // hs_out = mask ? ctx@Wco + hb : hs
    hmma_gemm<3><<<dim3(5, 32, NU), 256, SMEM_DYN>>>(
        cxh, cxl, (long long)BB * KP_CTX, KP_CTX, w4h, w4l, (long long)NP_H * KP_CTX,
        hs_out, NU * HH, HH, HH, mask, hb, hs, NU * HH, HH);

    (void)in_sizes; (void)n_in; (void)out_size;
}

// round 5
// speedup vs baseline: 3.6078x; 1.9461x over previous
#include <cuda_runtime.h>
#include <cuda_fp16.h>
#include <math.h>
#include <stdint.h>

#define BB 4096
#define NU 6
#define IND 600
#define HH 600
#define VDD 400
#define KD 64
#define KP_PRE 1088   // 448 (xv) + 640 (hs)
#define KP_H   640
#define KP_CTX 2432
#define NP_BIG 2432
#define NP_H   640
#define NP_CK  128

// ------------------------- device scratch -------------------------
__device__ __align__(16) float g_xk[BB * KD];
__device__ __align__(16) float g_xv[BB * VDD];
__device__ __align__(16) float g_qry[BB * NU * KD];
__device__ __align__(16) float g_scale[BB * NU];
__device__ __align__(16) float g_mask[BB * NU];
__device__ __align__(16) float g_hb[(size_t)BB * NU * HH];
__device__ __align__(16) float g_ck[BB * NU * 128];
__device__ __align__(16) float g_cq[BB * NU * 128];

__device__ __align__(16) __half g_preact[(size_t)BB * NU * 2400];
__device__ __align__(16) __half g_cvh[(size_t)BB * NU * 2400];
__device__ __align__(16) __half g_aph[(size_t)NU * BB * KP_PRE];
__device__ __align__(16) __half g_hbh[(size_t)NU * BB * KP_H];
__device__ __align__(16) __half g_cxh[(size_t)NU * BB * KP_CTX];
__device__ __align__(16) __half g_w12h[(size_t)NU * NP_BIG * KP_PRE];
__device__ __align__(16) __half g_w3h[(size_t)NU * NP_BIG * KP_H];
__device__ __align__(16) __half g_w4h[(size_t)NU * NP_H * KP_CTX];
__device__ __align__(16) __half g_w5h[(size_t)NU * NP_CK * KP_H];
__device__ __align__(16) __half g_w6h[(size_t)NU * NP_CK * KP_H];

// ------------------------- helpers -------------------------
__device__ __forceinline__ uint32_t smem_u32(const void* p) {
    uint32_t a;
    asm("{ .reg .u64 t; cvta.to.shared.u64 t, %1; cvt.u32.u64 %0, t; }" : "=r"(a) : "l"(p));
    return a;
}
__device__ __forceinline__ void cp16(uint32_t dst, const void* src) {
    asm volatile("cp.async.cg.shared.global [%0], [%1], 16;\n" :: "r"(dst), "l"(src));
}
__device__ __forceinline__ void mma16816(float* c, const uint32_t* a, uint32_t b0, uint32_t b1) {
    asm volatile(
        "mma.sync.aligned.m16n8k16.row.col.f32.f16.f16.f32 "
        "{%0,%1,%2,%3}, {%4,%5,%6,%7}, {%8,%9}, {%0,%1,%2,%3};"
        : "+f"(c[0]), "+f"(c[1]), "+f"(c[2]), "+f"(c[3])
        : "r"(a[0]), "r"(a[1]), "r"(a[2]), "r"(a[3]), "r"(b0), "r"(b1));
}

// SMEM: per stage 2 tiles (A,B), each 128 rows x 40 halves (80B stride)
#define TILE_B   10240
#define STAGE_B  20480
#define NSTAGE   3
#define SMEM_DYN (NSTAGE * STAGE_B + 16)

// ------------------------- HMMA GEMM (fp16, single term) -------------------------
// C[4096, Nreal] (unit z) = A[4096, Kpad] @ B[Npad, Kpad]^T
// EPI 0: fp32 store. EPI 3: fp32 C = S[m]>0.5 ? acc + E1 : E2. EPI 4: fp16 store.
template <int EPI>
__global__ void __launch_bounds__(256, 2)
hmma_gemm(const __half* __restrict__ A, long long sA, int Kpad,
          const __half* __restrict__ B, long long sB,
          void* __restrict__ Cv, int ldc, int sC, int Nreal,
          const float* __restrict__ S,
          const float* __restrict__ E1, const float* __restrict__ E2, int ldE, int sE)
{
    extern __shared__ __align__(16) char dsm[];
    char* tiles = dsm;
    const uint32_t tiles_u32 = smem_u32(dsm);

    const int tid = threadIdx.x;
    const int wid = tid >> 5, lane = tid & 31;
    const int wm = wid >> 1, wn = wid & 1;         // 4 x 2 warps
    const int g = lane >> 2, t = lane & 3;

    const int z = blockIdx.z, m0 = blockIdx.y * 128, n0 = blockIdx.x * 128;
    const __half* Az = A + (size_t)z * sA + (size_t)m0 * Kpad;
    const __half* Bz = B + (size_t)z * sB + (size_t)n0 * Kpad;

    const int nch = Kpad >> 5;   // BK = 32

    const int idx0 = tid * 2, idx1 = tid * 2 + 1;
    const int r_0 = idx0 >> 2, c_0 = idx0 & 3;
    const int r_1 = idx1 >> 2, c_1 = idx1 & 3;

    auto load_chunk = [&](int kc, int st) {
        uint32_t sb = tiles_u32 + (uint32_t)st * STAGE_B;
        int k0 = kc << 5;
        const __half* gp[2] = { Az, Bz };
#pragma unroll
        for (int mmat = 0; mmat < 2; mmat++) {
            uint32_t mb = sb + (uint32_t)mmat * TILE_B;
            cp16(mb + r_0 * 80 + c_0 * 16, gp[mmat] + (size_t)r_0 * Kpad + k0 + c_0 * 8);
            cp16(mb + r_1 * 80 + c_1 * 16, gp[mmat] + (size_t)r_1 * Kpad + k0 + c_1 * 8);
        }
    };

    float acc[2][8][4];
#pragma unroll
    for (int a = 0; a < 2; a++)
#pragma unroll
        for (int b = 0; b < 8; b++)
#pragma unroll
            for (int c = 0; c < 4; c++) acc[a][b][c] = 0.f;

    load_chunk(0, 0);
    asm volatile("cp.async.commit_group;" ::: "memory");
    load_chunk(1, 1);
    asm volatile("cp.async.commit_group;" ::: "memory");

    for (int kc = 0; kc < nch; kc++) {
        asm volatile("cp.async.wait_group 1;" ::: "memory");
        __syncthreads();
        if (kc + 2 < nch) {
            load_chunk(kc + 2, (kc + 2) % NSTAGE);
            asm volatile("cp.async.commit_group;" ::: "memory");
        } else {
            asm volatile("cp.async.commit_group;" ::: "memory");
        }

        const int st = kc % NSTAGE;
        const uint16_t* sA16 = (const uint16_t*)(tiles + st * STAGE_B);
        const uint16_t* sB16 = sA16 + 5120;

#pragma unroll
        for (int s16 = 0; s16 < 2; s16++) {
            const int kb = s16 * 16 + 2 * t;
            uint32_t ah[2][4];
#pragma unroll
            for (int mt = 0; mt < 2; mt++) {
                const int r = wm * 32 + mt * 16 + g;
                const uint16_t* ph = sA16 + r * 40 + kb;
                ah[mt][0] = *(const uint32_t*)ph;
                ah[mt][1] = *(const uint32_t*)(ph + 8 * 40);
                ah[mt][2] = *(const uint32_t*)(ph + 8);
                ah[mt][3] = *(const uint32_t*)(ph + 8 * 40 + 8);
            }
#pragma unroll
            for (int nt = 0; nt < 8; nt++) {
                const int n = wn * 64 + nt * 8 + g;
                const uint16_t* qh = sB16 + n * 40 + kb;
                const uint32_t b0 = *(const uint32_t*)qh;
                const uint32_t b1 = *(const uint32_t*)(qh + 8);
#pragma unroll
                for (int mt = 0; mt < 2; mt++)
                    mma16816(acc[mt][nt], ah[mt], b0, b1);
            }
        }
        __syncthreads();
    }

    // ----- epilogue -----
#pragma unroll
    for (int mt = 0; mt < 2; mt++) {
        const int r0 = m0 + wm * 32 + mt * 16 + g;
        const int r1 = r0 + 8;
        float mk0 = 0.f, mk1 = 0.f;
        if (EPI == 3) { mk0 = S[r0 * 6 + z]; mk1 = S[r1 * 6 + z]; }
        float* c0row = nullptr; float* c1row = nullptr;
        __half* h0row = nullptr; __half* h1row = nullptr;
        if (EPI == 4) {
            h0row = (__half*)Cv + (size_t)r0 * ldc + (size_t)z * sC;
            h1row = (__half*)Cv + (size_t)r1 * ldc + (size_t)z * sC;
        } else {
            c0row = (float*)Cv + (size_t)r0 * ldc + (size_t)z * sC;
            c1row = (float*)Cv + (size_t)r1 * ldc + (size_t)z * sC;
        }
        const float* e10 = (EPI == 3) ? E1 + (size_t)z * sE + (size_t)r0 * ldE : nullptr;
        const float* e11 = (EPI == 3) ? E1 + (size_t)z * sE + (size_t)r1 * ldE : nullptr;
        const float* e20 = (EPI == 3) ? E2 + (size_t)z * sE + (size_t)r0 * ldE : nullptr;
        const float* e21 = (EPI == 3) ? E2 + (size_t)z * sE + (size_t)r1 * ldE : nullptr;
#pragma unroll
        for (int nt = 0; nt < 8; nt++) {
            const int n = n0 + wn * 64 + nt * 8 + 2 * t;
            if (n < Nreal) {
                float2 v0 = make_float2(acc[mt][nt][0], acc[mt][nt][1]);
                float2 v1 = make_float2(acc[mt][nt][2], acc[mt][nt][3]);
                if (EPI == 3) {
                    if (mk0 > 0.5f) {
                        float2 o = *(const float2*)(e10 + n);
                        v0.x += o.x; v0.y += o.y;
                    } else v0 = *(const float2*)(e20 + n);
                    if (mk1 > 0.5f) {
                        float2 o = *(const float2*)(e11 + n);
                        v1.x += o.x; v1.y += o.y;
                    } else v1 = *(const float2*)(e21 + n);
                }
                if (EPI == 4) {
                    *(__half2*)(h0row + n) = __floats2half2_rn(v0.x, v0.y);
                    *(__half2*)(h1row + n) = __floats2half2_rn(v1.x, v1.y);
                } else {
                    *(float2*)(c0row + n) = v0;
                    *(float2*)(c1row + n) = v1;
                }
            }
        }
    }
}

// ------------------------- SIMT GEMM (small fp32) -------------------------
template <int BM, int BN, int BK, int TM, int TN>
__global__ void __launch_bounds__((BM / TM) * (BN / TN))
gemm_simt(const float* __restrict__ A, int lda, long long sA,
          const float* __restrict__ W, long long sW,
          float* __restrict__ C, int ldc, long long sC, int M, int N, int K)
{
    constexpr int TX = BN / TN, TY = BM / TM, NT = TX * TY;
    __shared__ __align__(16) float As[BK][BM];
    __shared__ __align__(16) float Bs[BK][BN];
    const int z = blockIdx.z;
    A += (long long)z * sA; W += (long long)z * sW; C += (long long)z * sC;
    const int tid = threadIdx.x, tx = tid % TX, ty = tid / TX;
    const int m0 = blockIdx.y * BM, n0 = blockIdx.x * BN;
    float acc[TM][TN];
#pragma unroll
    for (int i = 0; i < TM; i++)
#pragma unroll
        for (int j = 0; j < TN; j++) acc[i][j] = 0.f;
    constexpr int A_TPR = BK / 4;
    const int ar = tid / A_TPR, ac = (tid % A_TPR) * 4;
    constexpr int A_RPP = NT / A_TPR;
    constexpr int B_TPR = BN / 4;
    const int wr0 = tid / B_TPR, wc = (tid % B_TPR) * 4;
    constexpr int B_RPP = NT / B_TPR;
    for (int k0 = 0; k0 < K; k0 += BK) {
        __syncthreads();
#pragma unroll
        for (int r = ar; r < BM; r += A_RPP) {
            float4 v = make_float4(0.f, 0.f, 0.f, 0.f);
            int m = m0 + r;
            if (m < M) v = *(const float4*)(A + (long long)m * lda + k0 + ac);
            As[ac][r] = v.x; As[ac + 1][r] = v.y; As[ac + 2][r] = v.z; As[ac + 3][r] = v.w;
        }
#pragma unroll
        for (int r = wr0; r < BK; r += B_RPP) {
            float4 v = make_float4(0.f, 0.f, 0.f, 0.f);
            int n = n0 + wc;
            if (n < N) v = *(const float4*)(W + (long long)(k0 + r) * N + n);
            *(float4*)&Bs[r][wc] = v;
        }
        __syncthreads();
#pragma unroll
        for (int kk = 0; kk < BK; kk++) {
            float af[TM], bf[TN];
#pragma unroll
            for (int i = 0; i < TM; i += 4) *(float4*)&af[i] = *(const float4*)&As[kk][ty * TM + i];
#pragma unroll
            for (int j = 0; j < TN; j += 4) *(float4*)&bf[j] = *(const float4*)&Bs[kk][tx * TN + j];
#pragma unroll
            for (int i = 0; i < TM; i++)
#pragma unroll
                for (int j = 0; j < TN; j++) acc[i][j] = fmaf(af[i], bf[j], acc[i][j]);
        }
    }
    const int nb = n0 + tx * TN;
    if (nb >= N) return;
#pragma unroll
    for (int i = 0; i < TM; i++) {
        int m = m0 + ty * TM + i;
        if (m >= M) break;
#pragma unroll
        for (int j = 0; j < TN; j += 4) {
            float4 v;
            v.x = acc[i][j]; v.y = acc[i][j + 1]; v.z = acc[i][j + 2]; v.w = acc[i][j + 3];
            *(float4*)(C + (long long)m * ldc + nb + j) = v;
        }
    }
}

// ------------------- weight transpose: O[u][n][koff+k] = W[u][k][n] (fp16) -------------------
__global__ void wtrans(const float* __restrict__ W, __half* __restrict__ Oh,
                       int Kreal, int Nreal, int KpadTot, int Npad, int koff)
{
    __shared__ float t[32][33];
    int u = blockIdx.z, kb = blockIdx.x * 32, nb = blockIdx.y * 32;
    const float* Wu = W + (size_t)u * Kreal * Nreal;
    int tx = threadIdx.x, ty0 = threadIdx.y;
#pragma unroll
    for (int yy = ty0; yy < 32; yy += 8) {
        int k = kb + yy, n = nb + tx;
        t[yy][tx] = (k < Kreal && n < Nreal) ? Wu[(size_t)k * Nreal + n] : 0.f;
    }
    __syncthreads();
    __half* OhU = Oh + (size_t)u * Npad * KpadTot;
#pragma unroll
    for (int yy = ty0; yy < 32; yy += 8) {
        int n = nb + yy, k = koff + kb + tx;
        OhU[(size_t)n * KpadTot + k] = __float2half_rn(t[tx][yy]);
    }
}

// ------------------- A_pre = [scale*xv | hs] fp16 -------------------
__global__ void conv_pre(const float* __restrict__ xv, const float* __restrict__ hs,
                         const float* __restrict__ scale, __half* __restrict__ oh)
{
    size_t idx = (size_t)blockIdx.x * blockDim.x + threadIdx.x;
    if (idx >= (size_t)NU * BB * KP_PRE) return;
    int k = (int)(idx % KP_PRE);
    int b = (int)((idx / KP_PRE) % BB);
    int u = (int)(idx / ((size_t)KP_PRE * BB));
    float v = 0.f;
    if (k < VDD) v = scale[b * NU + u] * xv[(size_t)b * VDD + k];
    else if (k >= 448 && k < 448 + HH) v = hs[(size_t)b * (NU * HH) + u * HH + (k - 448)];
    oh[idx] = __float2half_rn(v);
}

// ------------------- score + top-k (fp32) -------------------
__global__ void score_topk(const float* __restrict__ qry, const float* __restrict__ xk,
                           float* __restrict__ scale, float* __restrict__ mask)
{
    int gw = (blockIdx.x * blockDim.x + threadIdx.x) >> 5;
    int lane = threadIdx.x & 31;
    if (gw >= BB) return;
    int b = gw;
    float xk0 = xk[b * 64 + lane], xk1 = xk[b * 64 + 32 + lane];
    float s[NU];
#pragma unroll
    for (int u = 0; u < NU; u++) {
        const float* q = qry + b * (NU * 64) + u * 64;
        float v = q[lane] * xk0 + q[32 + lane] * xk1;
#pragma unroll
        for (int o = 16; o; o >>= 1) v += __shfl_xor_sync(~0u, v, o);
        s[u] = v * 0.125f;
    }
    if (lane == 0) {
#pragma unroll
        for (int u = 0; u < NU; u++) {
            int cnt = 0;
#pragma unroll
            for (int v = 0; v < NU; v++)
                if (s[v] > s[u] || (s[v] == s[u] && v < u)) cnt++;
            float m = (cnt < 4) ? 1.f : 0.f;
            mask[b * NU + u] = m;
            scale[b * NU + u] = m / (1.f + expf(-s[u]));
        }
    }
}

// ------------------- LSTM (preact fp16 in) -> hb fp32, hbh fp16, cs_out -------------------
__global__ void lstm(const __half* __restrict__ preact, const float* __restrict__ cs,
                     const float* __restrict__ mask, float* __restrict__ hb,
                     __half* __restrict__ hbh, float* __restrict__ cs_out)
{
    size_t idx = (size_t)blockIdx.x * blockDim.x + threadIdx.x;
    if (idx >= (size_t)BB * NU * KP_H) return;
    int k = (int)(idx % KP_H);
    int bu = (int)(idx / KP_H);
    int b = bu / NU, u = bu % NU;
    size_t hidx = ((size_t)u * BB + b) * KP_H + k;
    float ht = 0.f;
    if (k < HH) {
        const __half* p = preact + (size_t)bu * 2400;
        float ig = 1.f / (1.f + expf(-__half2float(p[k])));
        float fg = 1.f / (1.f + expf(-__half2float(p[HH + k])));
        float og = 1.f / (1.f + expf(-__half2float(p[2 * HH + k])));
        float gg = tanhf(__half2float(p[3 * HH + k]));
        float cp = cs[(size_t)bu * HH + k];
        float c = cp * fg + ig * gg;
        ht = og * tanhf(c);
        hb[(size_t)bu * HH + k] = ht;
        cs_out[(size_t)bu * HH + k] = (mask[bu] > 0.5f) ? c : cp;
    }
    hbh[hidx] = __float2half_rn(ht);
}

// ------------------- comm attention (cv fp16 in) -> ctx fp16 -------------------
__global__ void comm_attn(const float* __restrict__ cq, const float* __restrict__ ck,
                          const __half* __restrict__ cv, const float* __restrict__ mask,
                          __half* __restrict__ cxh)
{
    int u = blockIdx.x, b = blockIdx.y;
    __shared__ float s_cq[128], s_sc[4][NU], s_pr[4][8];
    int t = threadIdx.x;
    if (t < 128) s_cq[t] = cq[(size_t)b * (NU * 128) + u * 128 + t];
    __syncthreads();
    int w = t >> 5, lane = t & 31;
    for (int p = w; p < 4 * NU; p += 8) {
        int hh = p / NU, m = p % NU;
        float v = s_cq[hh * 32 + lane] * ck[(size_t)b * (NU * 128) + m * 128 + hh * 32 + lane];
#pragma unroll
        for (int o = 16; o; o >>= 1) v += __shfl_xor_sync(~0u, v, o);
        if (lane == 0) s_sc[hh][m] = v * 0.17677669529663687f;
    }
    __syncthreads();
    if (t < 4) {
        float mx = -1e30f;
#pragma unroll
        for (int m = 0; m < NU; m++) mx = fmaxf(mx, s_sc[t][m]);
        float e[NU], sum = 0.f;
#pragma unroll
        for (int m = 0; m < NU; m++) { e[m] = expf(s_sc[t][m] - mx); sum += e[m]; }
        float inv = mask[b * NU + u] / sum;
#pragma unroll
        for (int m = 0; m < NU; m++) s_pr[t][m] = e[m] * inv;
    }
    __syncthreads();
    const __half* cvb = cv + (size_t)b * (NU * 2400);
    size_t ob = ((size_t)u * BB + b) * KP_CTX;
    for (int i = t; i < KP_CTX; i += 256) {
        float a = 0.f;
        if (i < 2400) {
            int hh = i / 600;
#pragma unroll
            for (int m = 0; m < NU; m++)
                a += s_pr[hh][m] * __half2float(cvb[m * 2400 + i]);
        }
        cxh[ob + i] = __float2half_rn(a);
    }
}

// ------------------------- launch -------------------------
extern "C" void kernel_launch(void* const* d_in, const int* in_sizes, int n_in,
                              void* d_out, int out_size)
{
    const float* x    = (const float*)d_in[0];
    const float* hs   = (const float*)d_in[1];
    const float* cs   = (const float*)d_in[2];
    const float* Wk   = (const float*)d_in[3];
    const float* Wv   = (const float*)d_in[4];
    const float* Wq   = (const float*)d_in[5];
    const float* Wi2h = (const float*)d_in[6];
    const float* Wh2h = (const float*)d_in[7];
    const float* Wck  = (const float*)d_in[8];
    const float* Wcq  = (const float*)d_in[9];
    const float* Wcv  = (const float*)d_in[10];
    const float* Wco  = (const float*)d_in[11];

    float* hs_out = (float*)d_out;
    float* cs_out = hs_out + (size_t)BB * NU * HH;

    float *xk, *xv, *qry, *scale, *mask, *hb, *ck, *cq;
    __half *preact, *cvh, *aph, *hbh, *cxh, *w12h, *w3h, *w4h, *w5h, *w6h;
    cudaGetSymbolAddress((void**)&xk, g_xk);       cudaGetSymbolAddress((void**)&xv, g_xv);
    cudaGetSymbolAddress((void**)&qry, g_qry);     cudaGetSymbolAddress((void**)&scale, g_scale);
    cudaGetSymbolAddress((void**)&mask, g_mask);   cudaGetSymbolAddress((void**)&hb, g_hb);
    cudaGetSymbolAddress((void**)&ck, g_ck);       cudaGetSymbolAddress((void**)&cq, g_cq);
    cudaGetSymbolAddress((void**)&preact, g_preact);
    cudaGetSymbolAddress((void**)&cvh, g_cvh);
    cudaGetSymbolAddress((void**)&aph, g_aph);
    cudaGetSymbolAddress((void**)&hbh, g_hbh);
    cudaGetSymbolAddress((void**)&cxh, g_cxh);
    cudaGetSymbolAddress((void**)&w12h, g_w12h);
    cudaGetSymbolAddress((void**)&w3h, g_w3h);
    cudaGetSymbolAddress((void**)&w4h, g_w4h);
    cudaGetSymbolAddress((void**)&w5h, g_w5h);
    cudaGetSymbolAddress((void**)&w6h, g_w6h);

    cudaFuncSetAttribute(hmma_gemm<0>, cudaFuncAttributeMaxDynamicSharedMemorySize, SMEM_DYN);
    cudaFuncSetAttribute(hmma_gemm<3>, cudaFuncAttributeMaxDynamicSharedMemorySize, SMEM_DYN);
    cudaFuncSetAttribute(hmma_gemm<4>, cudaFuncAttributeMaxDynamicSharedMemorySize, SMEM_DYN);

    dim3 tb(32, 8);
    wtrans<<<dim3(14, NP_BIG / 32, NU), tb>>>(Wi2h, w12h, 400, 2400, KP_PRE, NP_BIG, 0);
    wtrans<<<dim3(20, NP_BIG / 32, NU), tb>>>(Wh2h, w12h, 600, 2400, KP_PRE, NP_BIG, 448);
    wtrans<<<dim3(20, NP_BIG / 32, NU), tb>>>(Wcv, w3h, 600, 2400, KP_H, NP_BIG, 0);
    wtrans<<<dim3(76, NP_H / 32, NU), tb>>>(Wco, w4h, 2400, 600, KP_CTX, NP_H, 0);
    wtrans<<<dim3(20, NP_CK / 32, NU), tb>>>(Wck, w5h, 600, 128, KP_H, NP_CK, 0);
    wtrans<<<dim3(20, NP_CK / 32, NU), tb>>>(Wcq, w6h, 600, 128, KP_H, NP_CK, 0);

    gemm_simt<128, 64, 8, 8, 4><<<dim3(1, 32, 1), 256>>>(x, IND, 0, Wk, 0, xk, KD, 0, BB, KD, IND);
    gemm_simt<128, 128, 8, 8, 8><<<dim3(4, 32, 1), 256>>>(x, IND, 0, Wv, 0, xv, VDD, 0, BB, VDD, IND);
    gemm_simt<128, 64, 8, 8, 4><<<dim3(1, 32, NU), 256>>>(
        hs, NU * HH, HH, Wq, (long long)HH * KD, qry, NU * KD, KD, BB, KD, HH);

    score_topk<<<(BB * 32 + 255) / 256, 256>>>(qry, xk, scale, mask);
    conv_pre<<<(int)(((size_t)NU * BB * KP_PRE + 255) / 256), 256>>>(xv, hs, scale, aph);

    // preact = scale*(xv@Wi2h) + hs@Wh2h  (fused K=1088) -> fp16
    hmma_gemm<4><<<dim3(19, 32, NU), 256, SMEM_DYN>>>(
        aph, (long long)BB * KP_PRE, KP_PRE, w12h, (long long)NP_BIG * KP_PRE,
        preact, NU * 2400, 2400, 2400, nullptr, nullptr, nullptr, 0, 0);

    lstm<<<(int)(((size_t)BB * NU * KP_H + 255) / 256), 256>>>(
        preact, cs, mask, hb, hbh, cs_out);

    hmma_gemm<0><<<dim3(1, 32, NU), 256, SMEM_DYN>>>(
        hbh, (long long)BB * KP_H, KP_H, w5h, (long long)NP_CK * KP_H,
        ck, NU * 128, 128, 128, nullptr, nullptr, nullptr, 0, 0);
    hmma_gemm<0><<<dim3(1, 32, NU), 256, SMEM_DYN>>>(
        hbh, (long long)BB * KP_H, KP_H, w6h, (long long)NP_CK * KP_H,
        cq, NU * 128, 128, 128, nullptr, nullptr, nullptr, 0, 0);
    hmma_gemm<4><<<dim3(19, 32, NU), 256, SMEM_DYN>>>(
        hbh, (long long)BB * KP_H, KP_H, w3h, (long long)NP_BIG * KP_H,
        cvh, NU * 2400, 2400, 2400, nullptr, nullptr, nullptr, 0, 0);

    comm_attn<<<dim3(NU, BB), 256>>>(cq, ck, cvh, mask, cxh);

    // hs_out = mask ? ctx@Wco + hb : hs
    hmma_gemm<3><<<dim3(5, 32, NU), 256, SMEM_DYN>>>(
        cxh, (long long)BB * KP_CTX, KP_CTX, w4h, (long long)NP_H * KP_CTX,
        hs_out, NU * HH, HH, HH, mask, hb, hs, NU * HH, HH);

    (void)in_sizes; (void)n_in; (void)out_size;
}

// round 6
// speedup vs baseline: 3.9943x; 1.1071x over previous
#include <cuda_runtime.h>
#include <cuda_fp16.h>
#include <math.h>
#include <stdint.h>

#define BB 4096
#define NU 6
#define IND 600
#define HH 600
#define VDD 400
#define KD 64
#define KP_PRE 1088
#define KP_H   640
#define KP_X   640
#define KP_CTX 2432
#define NP_BIG 2432
#define NP_H   640
#define NP_CKQ 256
#define NP_V   512

// ------------------------- device scratch -------------------------
__device__ __align__(16) float g_xk[BB * KD];
__device__ __align__(16) float g_xv[BB * VDD];
__device__ __align__(16) float g_qry[BB * NU * KD];
__device__ __align__(16) float g_scale[BB * NU];
__device__ __align__(16) float g_mask[BB * NU];
__device__ __align__(16) float g_hb[(size_t)BB * NU * HH];
__device__ __align__(16) float g_ckq[(size_t)BB * NU * 256];

__device__ __align__(16) __half g_preact[(size_t)BB * NU * 2400];
__device__ __align__(16) __half g_cvh[(size_t)BB * NU * 2400];
__device__ __align__(16) __half g_aph[(size_t)NU * BB * KP_PRE];
__device__ __align__(16) __half g_hbh[(size_t)NU * BB * KP_H];
__device__ __align__(16) __half g_cxh[(size_t)NU * BB * KP_CTX];
__device__ __align__(16) __half g_x16[(size_t)BB * KP_X];
__device__ __align__(16) __half g_w12h[(size_t)NU * NP_BIG * KP_PRE];
__device__ __align__(16) __half g_w3h[(size_t)NU * NP_BIG * KP_H];
__device__ __align__(16) __half g_w4h[(size_t)NU * NP_H * KP_CTX];
__device__ __align__(16) __half g_w56h[(size_t)NU * NP_CKQ * KP_H];
__device__ __align__(16) __half g_wv16[(size_t)NP_V * KP_X];

// ------------------------- helpers -------------------------
__device__ __forceinline__ uint32_t smem_u32(const void* p) {
    uint32_t a;
    asm("{ .reg .u64 t; cvta.to.shared.u64 t, %1; cvt.u32.u64 %0, t; }" : "=r"(a) : "l"(p));
    return a;
}
__device__ __forceinline__ void cp16(uint32_t dst, const void* src) {
    asm volatile("cp.async.cg.shared.global [%0], [%1], 16;\n" :: "r"(dst), "l"(src));
}
__device__ __forceinline__ void mma16816(float* c, const uint32_t* a, uint32_t b0, uint32_t b1) {
    asm volatile(
        "mma.sync.aligned.m16n8k16.row.col.f32.f16.f16.f32 "
        "{%0,%1,%2,%3}, {%4,%5,%6,%7}, {%8,%9}, {%0,%1,%2,%3};"
        : "+f"(c[0]), "+f"(c[1]), "+f"(c[2]), "+f"(c[3])
        : "r"(a[0]), "r"(a[1]), "r"(a[2]), "r"(a[3]), "r"(b0), "r"(b1));
}
__device__ __forceinline__ void ldsm4(uint32_t* r, uint32_t addr) {
    asm volatile("ldmatrix.sync.aligned.m8n8.x4.shared.b16 {%0,%1,%2,%3}, [%4];"
                 : "=r"(r[0]), "=r"(r[1]), "=r"(r[2]), "=r"(r[3]) : "r"(addr));
}

// SMEM: per stage 2 tiles (A,B), each 128 rows x 40 halves (80B stride)
#define TILE_B   10240
#define STAGE_B  20480
#define NSTAGE   3
#define SMEM_DYN (NSTAGE * STAGE_B + 16)

// ------------------------- HMMA GEMM (fp16, ldmatrix) -------------------------
// C[4096, Nreal] (unit z) = A[4096, Kpad] @ B[Npad, Kpad]^T
// EPI 0: fp32 store. EPI 3: fp32 C = S>0.5 ? acc+E1 : E2. EPI 4: fp16 store.
template <int EPI>
__global__ void __launch_bounds__(256, 2)
hmma_gemm(const __half* __restrict__ A, long long sA, int Kpad,
          const __half* __restrict__ B, long long sB,
          void* __restrict__ Cv, int ldc, int sC, int Nreal,
          const float* __restrict__ S,
          const float* __restrict__ E1, const float* __restrict__ E2, int ldE, int sE)
{
    extern __shared__ __align__(16) char dsm[];
    const uint32_t tiles_u32 = smem_u32(dsm);

    const int tid = threadIdx.x;
    const int wid = tid >> 5, lane = tid & 31;
    const int wm = wid >> 1, wn = wid & 1;        // 4 x 2 warps, 32x64 each
    const int g = lane >> 2, t = lane & 3;
    const int lane16 = lane & 15, lanehi = lane >> 4;

    const int z = blockIdx.z, m0 = blockIdx.y * 128, n0 = blockIdx.x * 128;
    const __half* Az = A + (size_t)z * sA + (size_t)m0 * Kpad;
    const __half* Bz = B + (size_t)z * sB + (size_t)n0 * Kpad;

    const int nch = Kpad >> 5;   // BK = 32

    const int idx0 = tid * 2, idx1 = tid * 2 + 1;
    const int r_0 = idx0 >> 2, c_0 = idx0 & 3;
    const int r_1 = idx1 >> 2, c_1 = idx1 & 3;

    auto load_chunk = [&](int kc, int st) {
        uint32_t sb = tiles_u32 + (uint32_t)st * STAGE_B;
        int k0 = kc << 5;
        cp16(sb + r_0 * 80 + c_0 * 16, Az + (size_t)r_0 * Kpad + k0 + c_0 * 8);
        cp16(sb + r_1 * 80 + c_1 * 16, Az + (size_t)r_1 * Kpad + k0 + c_1 * 8);
        cp16(sb + TILE_B + r_0 * 80 + c_0 * 16, Bz + (size_t)r_0 * Kpad + k0 + c_0 * 8);
        cp16(sb + TILE_B + r_1 * 80 + c_1 * 16, Bz + (size_t)r_1 * Kpad + k0 + c_1 * 8);
    };

    float acc[2][8][4];
#pragma unroll
    for (int a = 0; a < 2; a++)
#pragma unroll
        for (int b = 0; b < 8; b++)
#pragma unroll
            for (int c = 0; c < 4; c++) acc[a][b][c] = 0.f;

    // ldmatrix base offsets (bytes within stage)
    const uint32_t aOff = (uint32_t)((wm * 32 + lane16) * 80 + lanehi * 16);
    const uint32_t bOff = (uint32_t)(TILE_B + (wn * 64 + lane16) * 80 + lanehi * 16);

    load_chunk(0, 0);
    asm volatile("cp.async.commit_group;" ::: "memory");
    load_chunk(1, 1);
    asm volatile("cp.async.commit_group;" ::: "memory");

    for (int kc = 0; kc < nch; kc++) {
        asm volatile("cp.async.wait_group 1;" ::: "memory");
        __syncthreads();
        if (kc + 2 < nch) load_chunk(kc + 2, (kc + 2) % NSTAGE);
        asm volatile("cp.async.commit_group;" ::: "memory");

        const uint32_t sb = tiles_u32 + (uint32_t)(kc % NSTAGE) * STAGE_B;
#pragma unroll
        for (int s16 = 0; s16 < 2; s16++) {
            const uint32_t ko = (uint32_t)(s16 * 32);
            uint32_t a0[4], a1[4];
            ldsm4(a0, sb + aOff + ko);
            ldsm4(a1, sb + aOff + 16 * 80 + ko);
#pragma unroll
            for (int nt2 = 0; nt2 < 4; nt2++) {
                uint32_t bb[4];
                ldsm4(bb, sb + bOff + (uint32_t)(nt2 * 16 * 80) + ko);
                mma16816(acc[0][nt2 * 2],     a0, bb[0], bb[2]);
                mma16816(acc[0][nt2 * 2 + 1], a0, bb[1], bb[3]);
                mma16816(acc[1][nt2 * 2],     a1, bb[0], bb[2]);
                mma16816(acc[1][nt2 * 2 + 1], a1, bb[1], bb[3]);
            }
        }
        __syncthreads();
    }

    // ----- epilogue -----
#pragma unroll
    for (int mt = 0; mt < 2; mt++) {
        const int r0 = m0 + wm * 32 + mt * 16 + g;
        const int r1 = r0 + 8;
        float mk0 = 0.f, mk1 = 0.f;
        if (EPI == 3) { mk0 = S[r0 * 6 + z]; mk1 = S[r1 * 6 + z]; }
        float* c0row = nullptr; float* c1row = nullptr;
        __half* h0row = nullptr; __half* h1row = nullptr;
        if (EPI == 4) {
            h0row = (__half*)Cv + (size_t)r0 * ldc + (size_t)z * sC;
            h1row = (__half*)Cv + (size_t)r1 * ldc + (size_t)z * sC;
        } else {
            c0row = (float*)Cv + (size_t)r0 * ldc + (size_t)z * sC;
            c1row = (float*)Cv + (size_t)r1 * ldc + (size_t)z * sC;
        }
        const float* e10 = (EPI == 3) ? E1 + (size_t)z * sE + (size_t)r0 * ldE : nullptr;
        const float* e11 = (EPI == 3) ? E1 + (size_t)z * sE + (size_t)r1 * ldE : nullptr;
        const float* e20 = (EPI == 3) ? E2 + (size_t)z * sE + (size_t)r0 * ldE : nullptr;
        const float* e21 = (EPI == 3) ? E2 + (size_t)z * sE + (size_t)r1 * ldE : nullptr;
#pragma unroll
        for (int nt = 0; nt < 8; nt++) {
            const int n = n0 + wn * 64 + nt * 8 + 2 * t;
            if (n < Nreal) {
                float2 v0 = make_float2(acc[mt][nt][0], acc[mt][nt][1]);
                float2 v1 = make_float2(acc[mt][nt][2], acc[mt][nt][3]);
                if (EPI == 3) {
                    if (mk0 > 0.5f) {
                        float2 o = *(const float2*)(e10 + n);
                        v0.x += o.x; v0.y += o.y;
                    } else v0 = *(const float2*)(e20 + n);
                    if (mk1 > 0.5f) {
                        float2 o = *(const float2*)(e11 + n);
                        v1.x += o.x; v1.y += o.y;
                    } else v1 = *(const float2*)(e21 + n);
                }
                if (EPI == 4) {
                    *(__half2*)(h0row + n) = __floats2half2_rn(v0.x, v0.y);
                    *(__half2*)(h1row + n) = __floats2half2_rn(v1.x, v1.y);
                } else {
                    *(float2*)(c0row + n) = v0;
                    *(float2*)(c1row + n) = v1;
                }
            }
        }
    }
}

// ------------------------- SIMT GEMM (fp32 mask path) -------------------------
template <int BM, int BN, int BK, int TM, int TN>
__global__ void __launch_bounds__((BM / TM) * (BN / TN))
gemm_simt(const float* __restrict__ A, int lda, long long sA,
          const float* __restrict__ W, long long sW,
          float* __restrict__ C, int ldc, long long sC, int M, int N, int K)
{
    constexpr int TX = BN / TN, TY = BM / TM, NT = TX * TY;
    __shared__ __align__(16) float As[BK][BM];
    __shared__ __align__(16) float Bs[BK][BN];
    const int z = blockIdx.z;
    A += (long long)z * sA; W += (long long)z * sW; C += (long long)z * sC;
    const int tid = threadIdx.x, tx = tid % TX, ty = tid / TX;
    const int m0 = blockIdx.y * BM, n0 = blockIdx.x * BN;
    float acc[TM][TN];
#pragma unroll
    for (int i = 0; i < TM; i++)
#pragma unroll
        for (int j = 0; j < TN; j++) acc[i][j] = 0.f;
    constexpr int A_TPR = BK / 4;
    const int ar = tid / A_TPR, ac = (tid % A_TPR) * 4;
    constexpr int A_RPP = NT / A_TPR;
    constexpr int B_TPR = BN / 4;
    const int wr0 = tid / B_TPR, wc = (tid % B_TPR) * 4;
    constexpr int B_RPP = NT / B_TPR;
    for (int k0 = 0; k0 < K; k0 += BK) {
        __syncthreads();
#pragma unroll
        for (int r = ar; r < BM; r += A_RPP) {
            float4 v = make_float4(0.f, 0.f, 0.f, 0.f);
            int m = m0 + r;
            if (m < M) v = *(const float4*)(A + (long long)m * lda + k0 + ac);
            As[ac][r] = v.x; As[ac + 1][r] = v.y; As[ac + 2][r] = v.z; As[ac + 3][r] = v.w;
        }
#pragma unroll
        for (int r = wr0; r < BK; r += B_RPP) {
            float4 v = make_float4(0.f, 0.f, 0.f, 0.f);
            int n = n0 + wc;
            if (n < N) v = *(const float4*)(W + (long long)(k0 + r) * N + n);
            *(float4*)&Bs[r][wc] = v;
        }
        __syncthreads();
#pragma unroll
        for (int kk = 0; kk < BK; kk++) {
            float af[TM], bf[TN];
#pragma unroll
            for (int i = 0; i < TM; i += 4) *(float4*)&af[i] = *(const float4*)&As[kk][ty * TM + i];
#pragma unroll
            for (int j = 0; j < TN; j += 4) *(float4*)&bf[j] = *(const float4*)&Bs[kk][tx * TN + j];
#pragma unroll
            for (int i = 0; i < TM; i++)
#pragma unroll
                for (int j = 0; j < TN; j++) acc[i][j] = fmaf(af[i], bf[j], acc[i][j]);
        }
    }
    const int nb = n0 + tx * TN;
    if (nb >= N) return;
#pragma unroll
    for (int i = 0; i < TM; i++) {
        int m = m0 + ty * TM + i;
        if (m >= M) break;
#pragma unroll
        for (int j = 0; j < TN; j += 4) {
            float4 v;
            v.x = acc[i][j]; v.y = acc[i][j + 1]; v.z = acc[i][j + 2]; v.w = acc[i][j + 3];
            *(float4*)(C + (long long)m * ldc + nb + j) = v;
        }
    }
}

// ------------------- weight transpose: O[u][n][koff+k] = W[u][k][n], half2 stores -------------------
__global__ void wtrans(const float* __restrict__ W, __half* __restrict__ Oh,
                       int Kreal, int Nreal, int KpadTot, int Npad, int koff)
{
    __shared__ float tt[64][33];
    int u = blockIdx.z, kb = blockIdx.x * 64, nb = blockIdx.y * 32;
    const float* Wu = W + (size_t)u * Kreal * Nreal;
    int tx = threadIdx.x, ty = threadIdx.y;  // 32 x 8
#pragma unroll
    for (int yy = ty; yy < 64; yy += 8) {
        int k = kb + yy, n = nb + tx;
        tt[yy][tx] = (k < Kreal && n < Nreal) ? Wu[(size_t)k * Nreal + n] : 0.f;
    }
    __syncthreads();
    __half* OhU = Oh + (size_t)u * Npad * KpadTot + (size_t)(koff + kb);
#pragma unroll
    for (int yy = ty; yy < 32; yy += 8) {
        int n = nb + yy;
        __half2 v = __floats2half2_rn(tt[2 * tx][yy], tt[2 * tx + 1][yy]);
        *(__half2*)(OhU + (size_t)n * KpadTot + 2 * tx) = v;
    }
}

// ------------------- x -> fp16 padded -------------------
__global__ void conv_x(const float* __restrict__ x, __half* __restrict__ o)
{
    int idx = blockIdx.x * blockDim.x + threadIdx.x;
    if (idx >= BB * KP_X) return;
    int k = idx % KP_X, b = idx / KP_X;
    o[idx] = __float2half_rn(k < IND ? x[(size_t)b * IND + k] : 0.f);
}

// ------------------- A_pre = [scale*xv | hs] fp16 -------------------
__global__ void conv_pre(const float* __restrict__ xv, const float* __restrict__ hs,
                         const float* __restrict__ scale, __half* __restrict__ oh)
{
    size_t idx = (size_t)blockIdx.x * blockDim.x + threadIdx.x;
    if (idx >= (size_t)NU * BB * KP_PRE) return;
    int k = (int)(idx % KP_PRE);
    int b = (int)((idx / KP_PRE) % BB);
    int u = (int)(idx / ((size_t)KP_PRE * BB));
    float v = 0.f;
    if (k < VDD) v = scale[b * NU + u] * xv[(size_t)b * VDD + k];
    else if (k >= 448 && k < 448 + HH) v = hs[(size_t)b * (NU * HH) + u * HH + (k - 448)];
    oh[idx] = __float2half_rn(v);
}

// ------------------- score + top-k (fp32) -------------------
__global__ void score_topk(const float* __restrict__ qry, const float* __restrict__ xk,
                           float* __restrict__ scale, float* __restrict__ mask)
{
    int gw = (blockIdx.x * blockDim.x + threadIdx.x) >> 5;
    int lane = threadIdx.x & 31;
    if (gw >= BB) return;
    int b = gw;
    float xk0 = xk[b * 64 + lane], xk1 = xk[b * 64 + 32 + lane];
    float s[NU];
#pragma unroll
    for (int u = 0; u < NU; u++) {
        const float* q = qry + b * (NU * 64) + u * 64;
        float v = q[lane] * xk0 + q[32 + lane] * xk1;
#pragma unroll
        for (int o = 16; o; o >>= 1) v += __shfl_xor_sync(~0u, v, o);
        s[u] = v * 0.125f;
    }
    if (lane == 0) {
#pragma unroll
        for (int u = 0; u < NU; u++) {
            int cnt = 0;
#pragma unroll
            for (int v = 0; v < NU; v++)
                if (s[v] > s[u] || (s[v] == s[u] && v < u)) cnt++;
            float m = (cnt < 4) ? 1.f : 0.f;
            mask[b * NU + u] = m;
            scale[b * NU + u] = m / (1.f + expf(-s[u]));
        }
    }
}

// ------------------- LSTM -------------------
__global__ void lstm(const __half* __restrict__ preact, const float* __restrict__ cs,
                     const float* __restrict__ mask, float* __restrict__ hb,
                     __half* __restrict__ hbh, float* __restrict__ cs_out)
{
    size_t idx = (size_t)blockIdx.x * blockDim.x + threadIdx.x;
    if (idx >= (size_t)BB * NU * KP_H) return;
    int k = (int)(idx % KP_H);
    int bu = (int)(idx / KP_H);
    int b = bu / NU, u = bu % NU;
    size_t hidx = ((size_t)u * BB + b) * KP_H + k;
    float ht = 0.f;
    if (k < HH) {
        const __half* p = preact + (size_t)bu * 2400;
        float ig = 1.f / (1.f + expf(-__half2float(p[k])));
        float fg = 1.f / (1.f + expf(-__half2float(p[HH + k])));
        float og = 1.f / (1.f + expf(-__half2float(p[2 * HH + k])));
        float gg = tanhf(__half2float(p[3 * HH + k]));
        float cp = cs[(size_t)bu * HH + k];
        float c = cp * fg + ig * gg;
        ht = og * tanhf(c);
        hb[(size_t)bu * HH + k] = ht;
        cs_out[(size_t)bu * HH + k] = (mask[bu] > 0.5f) ? c : cp;
    }
    hbh[hidx] = __float2half_rn(ht);
}

// ------------------- comm attention (ckq fused fp32 in, cv fp16) -> ctx fp16 -------------------
__global__ void comm_attn(const float* __restrict__ ckq, const __half* __restrict__ cv,
                          const float* __restrict__ mask, __half* __restrict__ cxh)
{
    int u = blockIdx.x, b = blockIdx.y;
    __shared__ float s_cq[128], s_sc[4][NU], s_pr[4][8];
    int t = threadIdx.x;
    const float* ckqb = ckq + (size_t)b * (NU * 256);
    if (t < 128) s_cq[t] = ckqb[u * 256 + 128 + t];
    __syncthreads();
    int w = t >> 5, lane = t & 31;
    for (int p = w; p < 4 * NU; p += 8) {
        int hh = p / NU, m = p % NU;
        float v = s_cq[hh * 32 + lane] * ckqb[m * 256 + hh * 32 + lane];
#pragma unroll
        for (int o = 16; o; o >>= 1) v += __shfl_xor_sync(~0u, v, o);
        if (lane == 0) s_sc[hh][m] = v * 0.17677669529663687f;
    }
    __syncthreads();
    if (t < 4) {
        float mx = -1e30f;
#pragma unroll
        for (int m = 0; m < NU; m++) mx = fmaxf(mx, s_sc[t][m]);
        float e[NU], sum = 0.f;
#pragma unroll
        for (int m = 0; m < NU; m++) { e[m] = expf(s_sc[t][m] - mx); sum += e[m]; }
        float inv = mask[b * NU + u] / sum;
#pragma unroll
        for (int m = 0; m < NU; m++) s_pr[t][m] = e[m] * inv;
    }
    __syncthreads();
    const __half* cvb = cv + (size_t)b * (NU * 2400);
    size_t ob = ((size_t)u * BB + b) * KP_CTX;
    for (int i = t; i < KP_CTX; i += 256) {
        float a = 0.f;
        if (i < 2400) {
            int hh = i / 600;
#pragma unroll
            for (int m = 0; m < NU; m++)
                a += s_pr[hh][m] * __half2float(cvb[m * 2400 + i]);
        }
        cxh[ob + i] = __float2half_rn(a);
    }
}

// ------------------------- launch -------------------------
extern "C" void kernel_launch(void* const* d_in, const int* in_sizes, int n_in,
                              void* d_out, int out_size)
{
    const float* x    = (const float*)d_in[0];
    const float* hs   = (const float*)d_in[1];
    const float* cs   = (const float*)d_in[2];
    const float* Wk   = (const float*)d_in[3];
    const float* Wv   = (const float*)d_in[4];
    const float* Wq   = (const float*)d_in[5];
    const float* Wi2h = (const float*)d_in[6];
    const float* Wh2h = (const float*)d_in[7];
    const float* Wck  = (const float*)d_in[8];
    const float* Wcq  = (const float*)d_in[9];
    const float* Wcv  = (const float*)d_in[10];
    const float* Wco  = (const float*)d_in[11];

    float* hs_out = (float*)d_out;
    float* cs_out = hs_out + (size_t)BB * NU * HH;

    float *xk, *xv, *qry, *scale, *mask, *hb, *ckq;
    __half *preact, *cvh, *aph, *hbh, *cxh, *x16, *w12h, *w3h, *w4h, *w56h, *wv16;
    cudaGetSymbolAddress((void**)&xk, g_xk);       cudaGetSymbolAddress((void**)&xv, g_xv);
    cudaGetSymbolAddress((void**)&qry, g_qry);     cudaGetSymbolAddress((void**)&scale, g_scale);
    cudaGetSymbolAddress((void**)&mask, g_mask);   cudaGetSymbolAddress((void**)&hb, g_hb);
    cudaGetSymbolAddress((void**)&ckq, g_ckq);
    cudaGetSymbolAddress((void**)&preact, g_preact);
    cudaGetSymbolAddress((void**)&cvh, g_cvh);
    cudaGetSymbolAddress((void**)&aph, g_aph);
    cudaGetSymbolAddress((void**)&hbh, g_hbh);
    cudaGetSymbolAddress((void**)&cxh, g_cxh);
    cudaGetSymbolAddress((void**)&x16, g_x16);
    cudaGetSymbolAddress((void**)&w12h, g_w12h);
    cudaGetSymbolAddress((void**)&w3h, g_w3h);
    cudaGetSymbolAddress((void**)&w4h, g_w4h);
    cudaGetSymbolAddress((void**)&w56h, g_w56h);
    cudaGetSymbolAddress((void**)&wv16, g_wv16);

    cudaFuncSetAttribute(hmma_gemm<0>, cudaFuncAttributeMaxDynamicSharedMemorySize, SMEM_DYN);
    cudaFuncSetAttribute(hmma_gemm<3>, cudaFuncAttributeMaxDynamicSharedMemorySize, SMEM_DYN);
    cudaFuncSetAttribute(hmma_gemm<4>, cudaFuncAttributeMaxDynamicSharedMemorySize, SMEM_DYN);

    dim3 tb(32, 8);
    // weight transposes (fp16, [u][n][k])
    wtrans<<<dim3(7,  NP_BIG / 32, NU), tb>>>(Wi2h, w12h, 400, 2400, KP_PRE, NP_BIG, 0);
    wtrans<<<dim3(10, NP_BIG / 32, NU), tb>>>(Wh2h, w12h, 600, 2400, KP_PRE, NP_BIG, 448);
    wtrans<<<dim3(10, NP_BIG / 32, NU), tb>>>(Wcv, w3h, 600, 2400, KP_H, NP_BIG, 0);
    wtrans<<<dim3(38, NP_H / 32, NU), tb>>>(Wco, w4h, 2400, 600, KP_CTX, NP_H, 0);
    wtrans<<<dim3(10, 4, NU), tb>>>(Wck, w56h, 600, 128, KP_H, NP_CKQ, 0);
    wtrans<<<dim3(10, 4, NU), tb>>>(Wcq, w56h + (size_t)128 * KP_H, 600, 128, KP_H, NP_CKQ, 0);
    wtrans<<<dim3(10, NP_V / 32, 1), tb>>>(Wv, wv16, 600, 400, KP_X, NP_V, 0);

    conv_x<<<(BB * KP_X + 255) / 256, 256>>>(x, x16);

    // fp32 mask path
    gemm_simt<128, 64, 8, 8, 4><<<dim3(1, 32, 1), 256>>>(x, IND, 0, Wk, 0, xk, KD, 0, BB, KD, IND);
    gemm_simt<128, 64, 8, 8, 4><<<dim3(1, 32, NU), 256>>>(
        hs, NU * HH, HH, Wq, (long long)HH * KD, qry, NU * KD, KD, BB, KD, HH);

    // xv = x @ Wv  (fp16 HMMA, fp32 out)
    hmma_gemm<0><<<dim3(4, 32, 1), 256, SMEM_DYN>>>(
        x16, 0LL, KP_X, wv16, 0LL, xv, VDD, 0, VDD, nullptr, nullptr, nullptr, 0, 0);

    score_topk<<<(BB * 32 + 255) / 256, 256>>>(qry, xk, scale, mask);
    conv_pre<<<(int)(((size_t)NU * BB * KP_PRE + 255) / 256), 256>>>(xv, hs, scale, aph);

    // preact = scale*(xv@Wi2h) + hs@Wh2h  (fused K=1088) -> fp16
    hmma_gemm<4><<<dim3(19, 32, NU), 256, SMEM_DYN>>>(
        aph, (long long)BB * KP_PRE, KP_PRE, w12h, (long long)NP_BIG * KP_PRE,
        preact, NU * 2400, 2400, 2400, nullptr, nullptr, nullptr, 0, 0);

    lstm<<<(int)(((size_t)BB * NU * KP_H + 255) / 256), 256>>>(
        preact, cs, mask, hb, hbh, cs_out);

    // ck|cq fused (N=256, fp32 out)
    hmma_gemm<0><<<dim3(2, 32, NU), 256, SMEM_DYN>>>(
        hbh, (long long)BB * KP_H, KP_H, w56h, (long long)NP_CKQ * KP_H,
        ckq, NU * 256, 256, 256, nullptr, nullptr, nullptr, 0, 0);

    // cv -> fp16
    hmma_gemm<4><<<dim3(19, 32, NU), 256, SMEM_DYN>>>(
        hbh, (long long)BB * KP_H, KP_H, w3h, (long long)NP_BIG * KP_H,
        cvh, NU * 2400, 2400, 2400, nullptr, nullptr, nullptr, 0, 0);

    comm_attn<<<dim3(NU, BB), 256>>>(ckq, cvh, mask, cxh);

    // hs_out = mask ? ctx@Wco + hb : hs
    hmma_gemm<3><<<dim3(5, 32, NU), 256, SMEM_DYN>>>(
        cxh, (long long)BB * KP_CTX, KP_CTX, w4h, (long long)NP_H * KP_CTX,
        hs_out, NU * HH, HH, HH, mask, hb, hs, NU * HH, HH);

    (void)in_sizes; (void)n_in; (void)out_size;
}

// round 7
// speedup vs baseline: 4.2373x; 1.0608x over previous
#include <cuda_runtime.h>
#include <cuda_fp16.h>
#include <math.h>
#include <stdint.h>

#define BB 4096
#define NU 6
#define IND 600
#define HH 600
#define VDD 400
#define KD 64
#define KP_PRE 1088
#define KP_H   640
#define KP_X   640
#define KP_CTX 2432
#define NP_BIG 2432
#define NP_H   640
#define NP_CKQ 256
#define NP_V   512

// ------------------------- device scratch -------------------------
__device__ __align__(16) float g_xk[BB * KD];
__device__ __align__(16) float g_qry[BB * NU * KD];
__device__ __align__(16) float g_scale[BB * NU];
__device__ __align__(16) float g_mask[BB * NU];
__device__ __align__(16) float g_hb[(size_t)BB * NU * HH];
__device__ __align__(16) float g_ckq[(size_t)BB * NU * 256];

__device__ __align__(16) __half g_xvh[(size_t)BB * VDD];
__device__ __align__(16) __half g_cvh[(size_t)BB * NU * 2400];
__device__ __align__(16) __half g_aph[(size_t)NU * BB * KP_PRE];
__device__ __align__(16) __half g_hbh[(size_t)NU * BB * KP_H];
__device__ __align__(16) __half g_cxh[(size_t)NU * BB * KP_CTX];
__device__ __align__(16) __half g_x16[(size_t)BB * KP_X];
__device__ __align__(16) __half g_w12h[(size_t)NU * NP_BIG * KP_PRE];
__device__ __align__(16) __half g_w3h[(size_t)NU * NP_BIG * KP_H];
__device__ __align__(16) __half g_w4h[(size_t)NU * NP_H * KP_CTX];
__device__ __align__(16) __half g_w56h[(size_t)NU * NP_CKQ * KP_H];
__device__ __align__(16) __half g_wv16[(size_t)NP_V * KP_X];

// ------------------------- helpers -------------------------
__device__ __forceinline__ uint32_t smem_u32(const void* p) {
    uint32_t a;
    asm("{ .reg .u64 t; cvta.to.shared.u64 t, %1; cvt.u32.u64 %0, t; }" : "=r"(a) : "l"(p));
    return a;
}
__device__ __forceinline__ void cp16(uint32_t dst, const void* src) {
    asm volatile("cp.async.cg.shared.global [%0], [%1], 16;\n" :: "r"(dst), "l"(src));
}
__device__ __forceinline__ void mma16816(float* c, const uint32_t* a, uint32_t b0, uint32_t b1) {
    asm volatile(
        "mma.sync.aligned.m16n8k16.row.col.f32.f16.f16.f32 "
        "{%0,%1,%2,%3}, {%4,%5,%6,%7}, {%8,%9}, {%0,%1,%2,%3};"
        : "+f"(c[0]), "+f"(c[1]), "+f"(c[2]), "+f"(c[3])
        : "r"(a[0]), "r"(a[1]), "r"(a[2]), "r"(a[3]), "r"(b0), "r"(b1));
}
__device__ __forceinline__ void ldsm4(uint32_t* r, uint32_t addr) {
    asm volatile("ldmatrix.sync.aligned.m8n8.x4.shared.b16 {%0,%1,%2,%3}, [%4];"
                 : "=r"(r[0]), "=r"(r[1]), "=r"(r[2]), "=r"(r[3]) : "r"(addr));
}
__device__ __forceinline__ float sigf(float x) { return 1.f / (1.f + expf(-x)); }

// SMEM: per stage 2 tiles (A,B), each 128 rows x 40 halves (80B stride)
#define TILE_B   10240
#define STAGE_B  20480
#define NSTAGE   4
#define SMEM_DYN (NSTAGE * STAGE_B + 16)

// ------------------------- HMMA GEMM (fp16, ldmatrix, 4-stage) -------------------------
// C[4096, Nreal] (unit z) = A[4096, Kpad] @ B[Npad, Kpad]^T
// EPI 0: fp32 store. EPI 3: fp32 C = S>0.5 ? acc+E1 : E2. EPI 4: fp16 store.
// EPI 5: fused LSTM (gate-interleaved cols): Cv=hb(f32), S=mask, E1=cs, X2=cs_out, X3=hbh.
template <int EPI>
__global__ void __launch_bounds__(256, 2)
hmma_gemm(const __half* __restrict__ A, long long sA, int Kpad,
          const __half* __restrict__ B, long long sB,
          void* __restrict__ Cv, int ldc, int sC, int Nreal,
          const float* __restrict__ S,
          const float* __restrict__ E1, const float* __restrict__ E2, int ldE, int sE,
          float* __restrict__ X2, __half* __restrict__ X3)
{
    extern __shared__ __align__(16) char dsm[];
    const uint32_t tiles_u32 = smem_u32(dsm);

    const int tid = threadIdx.x;
    const int wid = tid >> 5, lane = tid & 31;
    const int wm = wid >> 1, wn = wid & 1;        // 4 x 2 warps, 32x64 each
    const int g = lane >> 2, t = lane & 3;
    const int lane16 = lane & 15, lanehi = lane >> 4;

    const int z = blockIdx.z, m0 = blockIdx.y * 128, n0 = blockIdx.x * 128;
    const __half* Az = A + (size_t)z * sA + (size_t)m0 * Kpad;
    const __half* Bz = B + (size_t)z * sB + (size_t)n0 * Kpad;

    const int nch = Kpad >> 5;   // BK = 32

    const int idx0 = tid * 2, idx1 = tid * 2 + 1;
    const int r_0 = idx0 >> 2, c_0 = idx0 & 3;
    const int r_1 = idx1 >> 2, c_1 = idx1 & 3;

    auto load_chunk = [&](int kc) {
        uint32_t sb = tiles_u32 + (uint32_t)(kc & 3) * STAGE_B;
        int k0 = kc << 5;
        cp16(sb + r_0 * 80 + c_0 * 16, Az + (size_t)r_0 * Kpad + k0 + c_0 * 8);
        cp16(sb + r_1 * 80 + c_1 * 16, Az + (size_t)r_1 * Kpad + k0 + c_1 * 8);
        cp16(sb + TILE_B + r_0 * 80 + c_0 * 16, Bz + (size_t)r_0 * Kpad + k0 + c_0 * 8);
        cp16(sb + TILE_B + r_1 * 80 + c_1 * 16, Bz + (size_t)r_1 * Kpad + k0 + c_1 * 8);
    };

    float acc[2][8][4];
#pragma unroll
    for (int a = 0; a < 2; a++)
#pragma unroll
        for (int b = 0; b < 8; b++)
#pragma unroll
            for (int c = 0; c < 4; c++) acc[a][b][c] = 0.f;

    const uint32_t aOff = (uint32_t)((wm * 32 + lane16) * 80 + lanehi * 16);
    const uint32_t bOff = (uint32_t)(TILE_B + (wn * 64 + lane16) * 80 + lanehi * 16);

    load_chunk(0);
    asm volatile("cp.async.commit_group;" ::: "memory");
    load_chunk(1);
    asm volatile("cp.async.commit_group;" ::: "memory");
    load_chunk(2);
    asm volatile("cp.async.commit_group;" ::: "memory");

    for (int kc = 0; kc < nch; kc++) {
        asm volatile("cp.async.wait_group 2;" ::: "memory");
        __syncthreads();
        if (kc + 3 < nch) load_chunk(kc + 3);
        asm volatile("cp.async.commit_group;" ::: "memory");

        const uint32_t sb = tiles_u32 + (uint32_t)(kc & 3) * STAGE_B;
#pragma unroll
        for (int s16 = 0; s16 < 2; s16++) {
            const uint32_t ko = (uint32_t)(s16 * 32);
            uint32_t a0[4], a1[4];
            ldsm4(a0, sb + aOff + ko);
            ldsm4(a1, sb + aOff + 16 * 80 + ko);
#pragma unroll
            for (int nt2 = 0; nt2 < 4; nt2++) {
                uint32_t bb[4];
                ldsm4(bb, sb + bOff + (uint32_t)(nt2 * 16 * 80) + ko);
                mma16816(acc[0][nt2 * 2],     a0, bb[0], bb[2]);
                mma16816(acc[0][nt2 * 2 + 1], a0, bb[1], bb[3]);
                mma16816(acc[1][nt2 * 2],     a1, bb[0], bb[2]);
                mma16816(acc[1][nt2 * 2 + 1], a1, bb[1], bb[3]);
            }
        }
    }

    // ----- epilogue -----
    if (EPI == 5) {
        // gate-interleaved: global col = 4*j + q (q: 0=i,1=f,2=o,3=g), j = hidden idx
        float* hb = (float*)Cv;
#pragma unroll
        for (int mt = 0; mt < 2; mt++) {
            const int b0r = m0 + wm * 32 + mt * 16 + g;   // batch index row0
            const int b1r = b0r + 8;
#pragma unroll
            for (int nt = 0; nt < 8; nt++) {
                float i0 = acc[mt][nt][0], f0 = acc[mt][nt][1];
                float i1 = acc[mt][nt][2], f1 = acc[mt][nt][3];
                float o0 = __shfl_xor_sync(~0u, i0, 1);
                float g0 = __shfl_xor_sync(~0u, f0, 1);
                float o1 = __shfl_xor_sync(~0u, i1, 1);
                float g1 = __shfl_xor_sync(~0u, f1, 1);
                if ((t & 1) == 0) {
                    const int c0 = n0 + wn * 64 + nt * 8 + 2 * t;
                    const int j = c0 >> 2;
                    if (j < HH) {
                        size_t i00 = ((size_t)b0r * NU + z) * HH + j;
                        size_t i10 = ((size_t)b1r * NU + z) * HH + j;
                        size_t h00 = ((size_t)z * BB + b0r) * KP_H + j;
                        size_t h10 = ((size_t)z * BB + b1r) * KP_H + j;
                        float mk0 = S[b0r * NU + z], mk1 = S[b1r * NU + z];
                        float cp0 = E1[i00], cp1 = E1[i10];
                        float c0v = cp0 * sigf(f0) + sigf(i0) * tanhf(g0);
                        float c1v = cp1 * sigf(f1) + sigf(i1) * tanhf(g1);
                        float h0v = sigf(o0) * tanhf(c0v);
                        float h1v = sigf(o1) * tanhf(c1v);
                        hb[i00] = h0v;  hb[i10] = h1v;
                        X2[i00] = (mk0 > 0.5f) ? c0v : cp0;
                        X2[i10] = (mk1 > 0.5f) ? c1v : cp1;
                        X3[h00] = __float2half_rn(h0v);
                        X3[h10] = __float2half_rn(h1v);
                    }
                }
            }
        }
        return;
    }

#pragma unroll
    for (int mt = 0; mt < 2; mt++) {
        const int r0 = m0 + wm * 32 + mt * 16 + g;
        const int r1 = r0 + 8;
        float mk0 = 0.f, mk1 = 0.f;
        if (EPI == 3) { mk0 = S[r0 * 6 + z]; mk1 = S[r1 * 6 + z]; }
        float* c0row = nullptr; float* c1row = nullptr;
        __half* h0row = nullptr; __half* h1row = nullptr;
        if (EPI == 4) {
            h0row = (__half*)Cv + (size_t)r0 * ldc + (size_t)z * sC;
            h1row = (__half*)Cv + (size_t)r1 * ldc + (size_t)z * sC;
        } else {
            c0row = (float*)Cv + (size_t)r0 * ldc + (size_t)z * sC;
            c1row = (float*)Cv + (size_t)r1 * ldc + (size_t)z * sC;
        }
        const float* e10 = (EPI == 3) ? E1 + (size_t)z * sE + (size_t)r0 * ldE : nullptr;
        const float* e11 = (EPI == 3) ? E1 + (size_t)z * sE + (size_t)r1 * ldE : nullptr;
        const float* e20 = (EPI == 3) ? E2 + (size_t)z * sE + (size_t)r0 * ldE : nullptr;
        const float* e21 = (EPI == 3) ? E2 + (size_t)z * sE + (size_t)r1 * ldE : nullptr;
#pragma unroll
        for (int nt = 0; nt < 8; nt++) {
            const int n = n0 + wn * 64 + nt * 8 + 2 * t;
            if (n < Nreal) {
                float2 v0 = make_float2(acc[mt][nt][0], acc[mt][nt][1]);
                float2 v1 = make_float2(acc[mt][nt][2], acc[mt][nt][3]);
                if (EPI == 3) {
                    if (mk0 > 0.5f) {
                        float2 o = *(const float2*)(e10 + n);
                        v0.x += o.x; v0.y += o.y;
                    } else v0 = *(const float2*)(e20 + n);
                    if (mk1 > 0.5f) {
                        float2 o = *(const float2*)(e11 + n);
                        v1.x += o.x; v1.y += o.y;
                    } else v1 = *(const float2*)(e21 + n);
                }
                if (EPI == 4) {
                    *(__half2*)(h0row + n) = __floats2half2_rn(v0.x, v0.y);
                    *(__half2*)(h1row + n) = __floats2half2_rn(v1.x, v1.y);
                } else {
                    *(float2*)(c0row + n) = v0;
                    *(float2*)(c1row + n) = v1;
                }
            }
        }
    }
}

// ------------------------- SIMT GEMM (fp32 mask path) -------------------------
template <int BM, int BN, int BK, int TM, int TN>
__global__ void __launch_bounds__((BM / TM) * (BN / TN))
gemm_simt(const float* __restrict__ A, int lda, long long sA,
          const float* __restrict__ W, long long sW,
          float* __restrict__ C, int ldc, long long sC, int M, int N, int K)
{
    constexpr int TX = BN / TN, TY = BM / TM, NT = TX * TY;
    __shared__ __align__(16) float As[BK][BM];
    __shared__ __align__(16) float Bs[BK][BN];
    const int z = blockIdx.z;
    A += (long long)z * sA; W += (long long)z * sW; C += (long long)z * sC;
    const int tid = threadIdx.x, tx = tid % TX, ty = tid / TX;
    const int m0 = blockIdx.y * BM, n0 = blockIdx.x * BN;
    float acc[TM][TN];
#pragma unroll
    for (int i = 0; i < TM; i++)
#pragma unroll
        for (int j = 0; j < TN; j++) acc[i][j] = 0.f;
    constexpr int A_TPR = BK / 4;
    const int ar = tid / A_TPR, ac = (tid % A_TPR) * 4;
    constexpr int A_RPP = NT / A_TPR;
    constexpr int B_TPR = BN / 4;
    const int wr0 = tid / B_TPR, wc = (tid % B_TPR) * 4;
    constexpr int B_RPP = NT / B_TPR;
    for (int k0 = 0; k0 < K; k0 += BK) {
        __syncthreads();
#pragma unroll
        for (int r = ar; r < BM; r += A_RPP) {
            float4 v = make_float4(0.f, 0.f, 0.f, 0.f);
            int m = m0 + r;
            if (m < M) v = *(const float4*)(A + (long long)m * lda + k0 + ac);
            As[ac][r] = v.x; As[ac + 1][r] = v.y; As[ac + 2][r] = v.z; As[ac + 3][r] = v.w;
        }
#pragma unroll
        for (int r = wr0; r < BK; r += B_RPP) {
            float4 v = make_float4(0.f, 0.f, 0.f, 0.f);
            int n = n0 + wc;
            if (n < N) v = *(const float4*)(W + (long long)(k0 + r) * N + n);
            *(float4*)&Bs[r][wc] = v;
        }
        __syncthreads();
#pragma unroll
        for (int kk = 0; kk < BK; kk++) {
            float af[TM], bf[TN];
#pragma unroll
            for (int i = 0; i < TM; i += 4) *(float4*)&af[i] = *(const float4*)&As[kk][ty * TM + i];
#pragma unroll
            for (int j = 0; j < TN; j += 4) *(float4*)&bf[j] = *(const float4*)&Bs[kk][tx * TN + j];
#pragma unroll
            for (int i = 0; i < TM; i++)
#pragma unroll
                for (int j = 0; j < TN; j++) acc[i][j] = fmaf(af[i], bf[j], acc[i][j]);
        }
    }
    const int nb = n0 + tx * TN;
    if (nb >= N) return;
#pragma unroll
    for (int i = 0; i < TM; i++) {
        int m = m0 + ty * TM + i;
        if (m >= M) break;
#pragma unroll
        for (int j = 0; j < TN; j += 4) {
            float4 v;
            v.x = acc[i][j]; v.y = acc[i][j + 1]; v.z = acc[i][j + 2]; v.w = acc[i][j + 3];
            *(float4*)(C + (long long)m * ldc + nb + j) = v;
        }
    }
}

// ------------------- weight transpose: O[u][pn][koff+k] = W[u][k][n] -------------------
__global__ void wtrans(const float* __restrict__ W, __half* __restrict__ Oh,
                       int Kreal, int Nreal, int KpadTot, int Npad, int koff, int gatePerm)
{
    __shared__ float tt[64][33];
    int u = blockIdx.z, kb = blockIdx.x * 64, nb = blockIdx.y * 32;
    const float* Wu = W + (size_t)u * Kreal * Nreal;
    int tx = threadIdx.x, ty = threadIdx.y;  // 32 x 8
#pragma unroll
    for (int yy = ty; yy < 64; yy += 8) {
        int k = kb + yy, n = nb + tx;
        tt[yy][tx] = (k < Kreal && n < Nreal) ? Wu[(size_t)k * Nreal + n] : 0.f;
    }
    __syncthreads();
    __half* OhU = Oh + (size_t)u * Npad * KpadTot + (size_t)(koff + kb);
#pragma unroll
    for (int yy = ty; yy < 32; yy += 8) {
        int n = nb + yy;
        int pn = gatePerm ? ((n % 600) * 4 + n / 600) : n;
        __half2 v = __floats2half2_rn(tt[2 * tx][yy], tt[2 * tx + 1][yy]);
        *(__half2*)(OhU + (size_t)pn * KpadTot + 2 * tx) = v;
    }
}

// ------------------- x -> fp16 padded -------------------
__global__ void conv_x(const float* __restrict__ x, __half* __restrict__ o)
{
    int idx = blockIdx.x * blockDim.x + threadIdx.x;
    if (idx >= BB * KP_X) return;
    int k = idx % KP_X, b = idx / KP_X;
    o[idx] = __float2half_rn(k < IND ? x[(size_t)b * IND + k] : 0.f);
}

// ------------------- A_pre = [scale*xv | hs] fp16 -------------------
__global__ void conv_pre(const __half* __restrict__ xv, const float* __restrict__ hs,
                         const float* __restrict__ scale, __half* __restrict__ oh)
{
    size_t idx = (size_t)blockIdx.x * blockDim.x + threadIdx.x;
    if (idx >= (size_t)NU * BB * KP_PRE) return;
    int k = (int)(idx % KP_PRE);
    int b = (int)((idx / KP_PRE) % BB);
    int u = (int)(idx / ((size_t)KP_PRE * BB));
    float v = 0.f;
    if (k < VDD) v = scale[b * NU + u] * __half2float(xv[(size_t)b * VDD + k]);
    else if (k >= 448 && k < 448 + HH) v = hs[(size_t)b * (NU * HH) + u * HH + (k - 448)];
    oh[idx] = __float2half_rn(v);
}

// ------------------- score + top-k (fp32) -------------------
__global__ void score_topk(const float* __restrict__ qry, const float* __restrict__ xk,
                           float* __restrict__ scale, float* __restrict__ mask)
{
    int gw = (blockIdx.x * blockDim.x + threadIdx.x) >> 5;
    int lane = threadIdx.x & 31;
    if (gw >= BB) return;
    int b = gw;
    float xk0 = xk[b * 64 + lane], xk1 = xk[b * 64 + 32 + lane];
    float s[NU];
#pragma unroll
    for (int u = 0; u < NU; u++) {
        const float* q = qry + b * (NU * 64) + u * 64;
        float v = q[lane] * xk0 + q[32 + lane] * xk1;
#pragma unroll
        for (int o = 16; o; o >>= 1) v += __shfl_xor_sync(~0u, v, o);
        s[u] = v * 0.125f;
    }
    if (lane == 0) {
#pragma unroll
        for (int u = 0; u < NU; u++) {
            int cnt = 0;
#pragma unroll
            for (int v = 0; v < NU; v++)
                if (s[v] > s[u] || (s[v] == s[u] && v < u)) cnt++;
            float m = (cnt < 4) ? 1.f : 0.f;
            mask[b * NU + u] = m;
            scale[b * NU + u] = m / (1.f + expf(-s[u]));
        }
    }
}

// ------------------- comm attention -------------------
__global__ void comm_attn(const float* __restrict__ ckq, const __half* __restrict__ cv,
                          const float* __restrict__ mask, __half* __restrict__ cxh)
{
    int u = blockIdx.x, b = blockIdx.y;
    __shared__ float s_cq[128], s_sc[4][NU], s_pr[4][8];
    int t = threadIdx.x;
    const float* ckqb = ckq + (size_t)b * (NU * 256);
    if (t < 128) s_cq[t] = ckqb[u * 256 + 128 + t];
    __syncthreads();
    int w = t >> 5, lane = t & 31;
    for (int p = w; p < 4 * NU; p += 8) {
        int hh = p / NU, m = p % NU;
        float v = s_cq[hh * 32 + lane] * ckqb[m * 256 + hh * 32 + lane];
#pragma unroll
        for (int o = 16; o; o >>= 1) v += __shfl_xor_sync(~0u, v, o);
        if (lane == 0) s_sc[hh][m] = v * 0.17677669529663687f;
    }
    __syncthreads();
    if (t < 4) {
        float mx = -1e30f;
#pragma unroll
        for (int m = 0; m < NU; m++) mx = fmaxf(mx, s_sc[t][m]);
        float e[NU], sum = 0.f;
#pragma unroll
        for (int m = 0; m < NU; m++) { e[m] = expf(s_sc[t][m] - mx); sum += e[m]; }
        float inv = mask[b * NU + u] / sum;
#pragma unroll
        for (int m = 0; m < NU; m++) s_pr[t][m] = e[m] * inv;
    }
    __syncthreads();
    const __half* cvb = cv + (size_t)b * (NU * 2400);
    size_t ob = ((size_t)u * BB + b) * KP_CTX;
    for (int i = t; i < KP_CTX; i += 256) {
        float a = 0.f;
        if (i < 2400) {
            int hh = i / 600;
#pragma unroll
            for (int m = 0; m < NU; m++)
                a += s_pr[hh][m] * __half2float(cvb[m * 2400 + i]);
        }
        cxh[ob + i] = __float2half_rn(a);
    }
}

// ------------------------- launch -------------------------
extern "C" void kernel_launch(void* const* d_in, const int* in_sizes, int n_in,
                              void* d_out, int out_size)
{
    const float* x    = (const float*)d_in[0];
    const float* hs   = (const float*)d_in[1];
    const float* cs   = (const float*)d_in[2];
    const float* Wk   = (const float*)d_in[3];
    const float* Wv   = (const float*)d_in[4];
    const float* Wq   = (const float*)d_in[5];
    const float* Wi2h = (const float*)d_in[6];
    const float* Wh2h = (const float*)d_in[7];
    const float* Wck  = (const float*)d_in[8];
    const float* Wcq  = (const float*)d_in[9];
    const float* Wcv  = (const float*)d_in[10];
    const float* Wco  = (const float*)d_in[11];

    float* hs_out = (float*)d_out;
    float* cs_out = hs_out + (size_t)BB * NU * HH;

    float *xk, *qry, *scale, *mask, *hb, *ckq;
    __half *xvh, *cvh, *aph, *hbh, *cxh, *x16, *w12h, *w3h, *w4h, *w56h, *wv16;
    cudaGetSymbolAddress((void**)&xk, g_xk);
    cudaGetSymbolAddress((void**)&qry, g_qry);     cudaGetSymbolAddress((void**)&scale, g_scale);
    cudaGetSymbolAddress((void**)&mask, g_mask);   cudaGetSymbolAddress((void**)&hb, g_hb);
    cudaGetSymbolAddress((void**)&ckq, g_ckq);
    cudaGetSymbolAddress((void**)&xvh, g_xvh);
    cudaGetSymbolAddress((void**)&cvh, g_cvh);
    cudaGetSymbolAddress((void**)&aph, g_aph);
    cudaGetSymbolAddress((void**)&hbh, g_hbh);
    cudaGetSymbolAddress((void**)&cxh, g_cxh);
    cudaGetSymbolAddress((void**)&x16, g_x16);
    cudaGetSymbolAddress((void**)&w12h, g_w12h);
    cudaGetSymbolAddress((void**)&w3h, g_w3h);
    cudaGetSymbolAddress((void**)&w4h, g_w4h);
    cudaGetSymbolAddress((void**)&w56h, g_w56h);
    cudaGetSymbolAddress((void**)&wv16, g_wv16);

    cudaFuncSetAttribute(hmma_gemm<0>, cudaFuncAttributeMaxDynamicSharedMemorySize, SMEM_DYN);
    cudaFuncSetAttribute(hmma_gemm<3>, cudaFuncAttributeMaxDynamicSharedMemorySize, SMEM_DYN);
    cudaFuncSetAttribute(hmma_gemm<4>, cudaFuncAttributeMaxDynamicSharedMemorySize, SMEM_DYN);
    cudaFuncSetAttribute(hmma_gemm<5>, cudaFuncAttributeMaxDynamicSharedMemorySize, SMEM_DYN);

    dim3 tb(32, 8);
    // weight transposes; w12 gate-interleaved
    wtrans<<<dim3(7,  2400 / 32, NU), tb>>>(Wi2h, w12h, 400, 2400, KP_PRE, NP_BIG, 0, 1);
    wtrans<<<dim3(10, 2400 / 32, NU), tb>>>(Wh2h, w12h, 600, 2400, KP_PRE, NP_BIG, 448, 1);
    wtrans<<<dim3(10, NP_BIG / 32, NU), tb>>>(Wcv, w3h, 600, 2400, KP_H, NP_BIG, 0, 0);
    wtrans<<<dim3(38, NP_H / 32, NU), tb>>>(Wco, w4h, 2400, 600, KP_CTX, NP_H, 0, 0);
    wtrans<<<dim3(10, 4, NU), tb>>>(Wck, w56h, 600, 128, KP_H, NP_CKQ, 0, 0);
    wtrans<<<dim3(10, 4, NU), tb>>>(Wcq, w56h + (size_t)128 * KP_H, 600, 128, KP_H, NP_CKQ, 0, 0);
    wtrans<<<dim3(10, NP_V / 32, 1), tb>>>(Wv, wv16, 600, 400, KP_X, NP_V, 0, 0);

    conv_x<<<(BB * KP_X + 255) / 256, 256>>>(x, x16);

    // fp32 mask path
    gemm_simt<128, 64, 8, 8, 4><<<dim3(1, 32, 1), 256>>>(x, IND, 0, Wk, 0, xk, KD, 0, BB, KD, IND);
    gemm_simt<128, 64, 8, 8, 4><<<dim3(1, 32, NU), 256>>>(
        hs, NU * HH, HH, Wq, (long long)HH * KD, qry, NU * KD, KD, BB, KD, HH);

    // xv = x @ Wv  (fp16 out)
    hmma_gemm<4><<<dim3(4, 32, 1), 256, SMEM_DYN>>>(
        x16, 0LL, KP_X, wv16, 0LL, xvh, VDD, 0, VDD,
        nullptr, nullptr, nullptr, 0, 0, nullptr, nullptr);

    score_topk<<<(BB * 32 + 255) / 256, 256>>>(qry, xk, scale, mask);
    conv_pre<<<(int)(((size_t)NU * BB * KP_PRE + 255) / 256), 256>>>(xvh, hs, scale, aph);

    // preact GEMM + fused LSTM epilogue -> hb, hbh, cs_out
    hmma_gemm<5><<<dim3(19, 32, NU), 256, SMEM_DYN>>>(
        aph, (long long)BB * KP_PRE, KP_PRE, w12h, (long long)NP_BIG * KP_PRE,
        hb, 0, 0, 2400, mask, cs, nullptr, 0, 0, cs_out, hbh);

    // ck|cq fused (N=256, fp32 out)
    hmma_gemm<0><<<dim3(2, 32, NU), 256, SMEM_DYN>>>(
        hbh, (long long)BB * KP_H, KP_H, w56h, (long long)NP_CKQ * KP_H,
        ckq, NU * 256, 256, 256, nullptr, nullptr, nullptr, 0, 0, nullptr, nullptr);

    // cv -> fp16
    hmma_gemm<4><<<dim3(19, 32, NU), 256, SMEM_DYN>>>(
        hbh, (long long)BB * KP_H, KP_H, w3h, (long long)NP_BIG * KP_H,
        cvh, NU * 2400, 2400, 2400, nullptr, nullptr, nullptr, 0, 0, nullptr, nullptr);

    comm_attn<<<dim3(NU, BB), 256>>>(ckq, cvh, mask, cxh);

    // hs_out = mask ? ctx@Wco + hb : hs
    hmma_gemm<3><<<dim3(5, 32, NU), 256, SMEM_DYN>>>(
        cxh, (long long)BB * KP_CTX, KP_CTX, w4h, (long long)NP_H * KP_CTX,
        hs_out, NU * HH, HH, HH, mask, hb, hs, NU * HH, HH, nullptr, nullptr);

    (void)in_sizes; (void)n_in; (void)out_size;
}

// round 8
// speedup vs baseline: 4.6819x; 1.1049x over previous
#include <cuda_runtime.h>
#include <cuda_fp16.h>
#include <math.h>
#include <stdint.h>

#define BB 4096
#define NU 6
#define IND 600
#define HH 600
#define VDD 400
#define KD 64
#define KP_PRE 1024   // 416 (xv) + 608 (hs)
#define KOFF_H 416
#define KP_H   608
#define KP_X   608
#define KP_CTX 2400
#define NP_BIG 2432
#define NP_H   640
#define NP_CKQ 256
#define NP_V   512

// ------------------------- device scratch -------------------------
__device__ __align__(16) float g_xk[BB * KD];
__device__ __align__(16) float g_qry[BB * NU * KD];
__device__ __align__(16) float g_scale[BB * NU];
__device__ __align__(16) float g_mask[BB * NU];
__device__ __align__(16) float g_hb[(size_t)BB * NU * HH];
__device__ __align__(16) float g_ckq[(size_t)BB * NU * 256];

__device__ __align__(16) __half g_xvh[(size_t)BB * VDD];
__device__ __align__(16) __half g_cvh[(size_t)BB * NU * 2400];
__device__ __align__(16) __half g_aph[(size_t)NU * BB * KP_PRE];
__device__ __align__(16) __half g_hbh[(size_t)NU * BB * KP_H];
__device__ __align__(16) __half g_cxh[(size_t)NU * BB * KP_CTX];
__device__ __align__(16) __half g_x16[(size_t)BB * KP_X];
__device__ __align__(16) __half g_w12h[(size_t)NU * NP_BIG * KP_PRE];
__device__ __align__(16) __half g_w3h[(size_t)NU * NP_BIG * KP_H];
__device__ __align__(16) __half g_w4h[(size_t)NU * NP_H * KP_CTX];
__device__ __align__(16) __half g_w56h[(size_t)NU * NP_CKQ * KP_H];
__device__ __align__(16) __half g_wv16[(size_t)NP_V * KP_X];

// ------------------------- helpers -------------------------
__device__ __forceinline__ uint32_t smem_u32(const void* p) {
    uint32_t a;
    asm("{ .reg .u64 t; cvta.to.shared.u64 t, %1; cvt.u32.u64 %0, t; }" : "=r"(a) : "l"(p));
    return a;
}
__device__ __forceinline__ void cp16(uint32_t dst, const void* src) {
    asm volatile("cp.async.cg.shared.global [%0], [%1], 16;\n" :: "r"(dst), "l"(src));
}
__device__ __forceinline__ void mma16816(float* c, const uint32_t* a, uint32_t b0, uint32_t b1) {
    asm volatile(
        "mma.sync.aligned.m16n8k16.row.col.f32.f16.f16.f32 "
        "{%0,%1,%2,%3}, {%4,%5,%6,%7}, {%8,%9}, {%0,%1,%2,%3};"
        : "+f"(c[0]), "+f"(c[1]), "+f"(c[2]), "+f"(c[3])
        : "r"(a[0]), "r"(a[1]), "r"(a[2]), "r"(a[3]), "r"(b0), "r"(b1));
}
__device__ __forceinline__ void ldsm4(uint32_t* r, uint32_t addr) {
    asm volatile("ldmatrix.sync.aligned.m8n8.x4.shared.b16 {%0,%1,%2,%3}, [%4];"
                 : "=r"(r[0]), "=r"(r[1]), "=r"(r[2]), "=r"(r[3]) : "r"(addr));
}
__device__ __forceinline__ float sigf(float x) { return 1.f / (1.f + expf(-x)); }

// SMEM: per stage 2 tiles (A,B), each 128 rows x 40 halves (80B stride)
#define TILE_B   10240
#define STAGE_B  20480
#define NSTAGE   4
#define SMEM_DYN (NSTAGE * STAGE_B + 16)

// ------------------------- HMMA GEMM (fp16, ldmatrix, 4-stage) -------------------------
// C[4096, Nreal] (unit z) = A[4096, Kpad] @ B[Npad, Kpad]^T
// EPI 0: fp32 store. EPI 3: fp32 C = S>0.5 ? acc+E1 : E2. EPI 4: fp16 store.
// EPI 5: fused LSTM (gate-interleaved cols): Cv=hb(f32), S=mask, E1=cs, X2=cs_out, X3=hbh.
template <int EPI>
__global__ void __launch_bounds__(256, 2)
hmma_gemm(const __half* __restrict__ A, long long sA, int Kpad,
          const __half* __restrict__ B, long long sB,
          void* __restrict__ Cv, int ldc, int sC, int Nreal,
          const float* __restrict__ S,
          const float* __restrict__ E1, const float* __restrict__ E2, int ldE, int sE,
          float* __restrict__ X2, __half* __restrict__ X3)
{
    extern __shared__ __align__(16) char dsm[];
    const uint32_t tiles_u32 = smem_u32(dsm);

    const int tid = threadIdx.x;
    const int wid = tid >> 5, lane = tid & 31;
    const int wm = wid >> 1, wn = wid & 1;        // 4 x 2 warps, 32x64 each
    const int g = lane >> 2, t = lane & 3;
    const int lane16 = lane & 15, lanehi = lane >> 4;

    const int z = blockIdx.z, m0 = blockIdx.y * 128, n0 = blockIdx.x * 128;
    const __half* Az = A + (size_t)z * sA + (size_t)m0 * Kpad;
    const __half* Bz = B + (size_t)z * sB + (size_t)n0 * Kpad;

    const int nch = Kpad >> 5;   // BK = 32

    const int idx0 = tid * 2, idx1 = tid * 2 + 1;
    const int r_0 = idx0 >> 2, c_0 = idx0 & 3;
    const int r_1 = idx1 >> 2, c_1 = idx1 & 3;

    auto load_chunk = [&](int kc) {
        uint32_t sb = tiles_u32 + (uint32_t)(kc & 3) * STAGE_B;
        int k0 = kc << 5;
        cp16(sb + r_0 * 80 + c_0 * 16, Az + (size_t)r_0 * Kpad + k0 + c_0 * 8);
        cp16(sb + r_1 * 80 + c_1 * 16, Az + (size_t)r_1 * Kpad + k0 + c_1 * 8);
        cp16(sb + TILE_B + r_0 * 80 + c_0 * 16, Bz + (size_t)r_0 * Kpad + k0 + c_0 * 8);
        cp16(sb + TILE_B + r_1 * 80 + c_1 * 16, Bz + (size_t)r_1 * Kpad + k0 + c_1 * 8);
    };

    float acc[2][8][4];
#pragma unroll
    for (int a = 0; a < 2; a++)
#pragma unroll
        for (int b = 0; b < 8; b++)
#pragma unroll
            for (int c = 0; c < 4; c++) acc[a][b][c] = 0.f;

    const uint32_t aOff = (uint32_t)((wm * 32 + lane16) * 80 + lanehi * 16);
    const uint32_t bOff = (uint32_t)(TILE_B + (wn * 64 + lane16) * 80 + lanehi * 16);

    load_chunk(0);
    asm volatile("cp.async.commit_group;" ::: "memory");
    load_chunk(1);
    asm volatile("cp.async.commit_group;" ::: "memory");
    load_chunk(2);
    asm volatile("cp.async.commit_group;" ::: "memory");

    for (int kc = 0; kc < nch; kc++) {
        asm volatile("cp.async.wait_group 2;" ::: "memory");
        __syncthreads();
        if (kc + 3 < nch) load_chunk(kc + 3);
        asm volatile("cp.async.commit_group;" ::: "memory");

        const uint32_t sb = tiles_u32 + (uint32_t)(kc & 3) * STAGE_B;
#pragma unroll
        for (int s16 = 0; s16 < 2; s16++) {
            const uint32_t ko = (uint32_t)(s16 * 32);
            uint32_t a0[4], a1[4];
            ldsm4(a0, sb + aOff + ko);
            ldsm4(a1, sb + aOff + 16 * 80 + ko);
#pragma unroll
            for (int nt2 = 0; nt2 < 4; nt2++) {
                uint32_t bb[4];
                ldsm4(bb, sb + bOff + (uint32_t)(nt2 * 16 * 80) + ko);
                mma16816(acc[0][nt2 * 2],     a0, bb[0], bb[2]);
                mma16816(acc[0][nt2 * 2 + 1], a0, bb[1], bb[3]);
                mma16816(acc[1][nt2 * 2],     a1, bb[0], bb[2]);
                mma16816(acc[1][nt2 * 2 + 1], a1, bb[1], bb[3]);
            }
        }
    }

    // ----- epilogue -----
    if (EPI == 5) {
        float* hb = (float*)Cv;
#pragma unroll
        for (int mt = 0; mt < 2; mt++) {
            const int b0r = m0 + wm * 32 + mt * 16 + g;
            const int b1r = b0r + 8;
#pragma unroll
            for (int nt = 0; nt < 8; nt++) {
                float i0 = acc[mt][nt][0], f0 = acc[mt][nt][1];
                float i1 = acc[mt][nt][2], f1 = acc[mt][nt][3];
                float o0 = __shfl_xor_sync(~0u, i0, 1);
                float g0 = __shfl_xor_sync(~0u, f0, 1);
                float o1 = __shfl_xor_sync(~0u, i1, 1);
                float g1 = __shfl_xor_sync(~0u, f1, 1);
                if ((t & 1) == 0) {
                    const int c0 = n0 + wn * 64 + nt * 8 + 2 * t;
                    const int j = c0 >> 2;
                    if (j < HH) {
                        size_t i00 = ((size_t)b0r * NU + z) * HH + j;
                        size_t i10 = ((size_t)b1r * NU + z) * HH + j;
                        size_t h00 = ((size_t)z * BB + b0r) * KP_H + j;
                        size_t h10 = ((size_t)z * BB + b1r) * KP_H + j;
                        float mk0 = S[b0r * NU + z], mk1 = S[b1r * NU + z];
                        float cp0 = E1[i00], cp1 = E1[i10];
                        float c0v = cp0 * sigf(f0) + sigf(i0) * tanhf(g0);
                        float c1v = cp1 * sigf(f1) + sigf(i1) * tanhf(g1);
                        float h0v = sigf(o0) * tanhf(c0v);
                        float h1v = sigf(o1) * tanhf(c1v);
                        hb[i00] = h0v;  hb[i10] = h1v;
                        X2[i00] = (mk0 > 0.5f) ? c0v : cp0;
                        X2[i10] = (mk1 > 0.5f) ? c1v : cp1;
                        X3[h00] = __float2half_rn(h0v);
                        X3[h10] = __float2half_rn(h1v);
                    }
                }
            }
        }
        return;
    }

#pragma unroll
    for (int mt = 0; mt < 2; mt++) {
        const int r0 = m0 + wm * 32 + mt * 16 + g;
        const int r1 = r0 + 8;
        float mk0 = 0.f, mk1 = 0.f;
        if (EPI == 3) { mk0 = S[r0 * 6 + z]; mk1 = S[r1 * 6 + z]; }
        float* c0row = nullptr; float* c1row = nullptr;
        __half* h0row = nullptr; __half* h1row = nullptr;
        if (EPI == 4) {
            h0row = (__half*)Cv + (size_t)r0 * ldc + (size_t)z * sC;
            h1row = (__half*)Cv + (size_t)r1 * ldc + (size_t)z * sC;
        } else {
            c0row = (float*)Cv + (size_t)r0 * ldc + (size_t)z * sC;
            c1row = (float*)Cv + (size_t)r1 * ldc + (size_t)z * sC;
        }
        const float* e10 = (EPI == 3) ? E1 + (size_t)z * sE + (size_t)r0 * ldE : nullptr;
        const float* e11 = (EPI == 3) ? E1 + (size_t)z * sE + (size_t)r1 * ldE : nullptr;
        const float* e20 = (EPI == 3) ? E2 + (size_t)z * sE + (size_t)r0 * ldE : nullptr;
        const float* e21 = (EPI == 3) ? E2 + (size_t)z * sE + (size_t)r1 * ldE : nullptr;
#pragma unroll
        for (int nt = 0; nt < 8; nt++) {
            const int n = n0 + wn * 64 + nt * 8 + 2 * t;
            if (n < Nreal) {
                float2 v0 = make_float2(acc[mt][nt][0], acc[mt][nt][1]);
                float2 v1 = make_float2(acc[mt][nt][2], acc[mt][nt][3]);
                if (EPI == 3) {
                    if (mk0 > 0.5f) {
                        float2 o = *(const float2*)(e10 + n);
                        v0.x += o.x; v0.y += o.y;
                    } else v0 = *(const float2*)(e20 + n);
                    if (mk1 > 0.5f) {
                        float2 o = *(const float2*)(e11 + n);
                        v1.x += o.x; v1.y += o.y;
                    } else v1 = *(const float2*)(e21 + n);
                }
                if (EPI == 4) {
                    *(__half2*)(h0row + n) = __floats2half2_rn(v0.x, v0.y);
                    *(__half2*)(h1row + n) = __floats2half2_rn(v1.x, v1.y);
                } else {
                    *(float2*)(c0row + n) = v0;
                    *(float2*)(c1row + n) = v1;
                }
            }
        }
    }
}

// ------------------------- SIMT GEMM (fp32 mask path) -------------------------
template <int BM, int BN, int BK, int TM, int TN>
__global__ void __launch_bounds__((BM / TM) * (BN / TN))
gemm_simt(const float* __restrict__ A, int lda, long long sA,
          const float* __restrict__ W, long long sW,
          float* __restrict__ C, int ldc, long long sC, int M, int N, int K)
{
    constexpr int TX = BN / TN, TY = BM / TM, NT = TX * TY;
    __shared__ __align__(16) float As[BK][BM];
    __shared__ __align__(16) float Bs[BK][BN];
    const int z = blockIdx.z;
    A += (long long)z * sA; W += (long long)z * sW; C += (long long)z * sC;
    const int tid = threadIdx.x, tx = tid % TX, ty = tid / TX;
    const int m0 = blockIdx.y * BM, n0 = blockIdx.x * BN;
    float acc[TM][TN];
#pragma unroll
    for (int i = 0; i < TM; i++)
#pragma unroll
        for (int j = 0; j < TN; j++) acc[i][j] = 0.f;
    constexpr int A_TPR = BK / 4;
    const int ar = tid / A_TPR, ac = (tid % A_TPR) * 4;
    constexpr int A_RPP = NT / A_TPR;
    constexpr int B_TPR = BN / 4;
    const int wr0 = tid / B_TPR, wc = (tid % B_TPR) * 4;
    constexpr int B_RPP = NT / B_TPR;
    for (int k0 = 0; k0 < K; k0 += BK) {
        __syncthreads();
#pragma unroll
        for (int r = ar; r < BM; r += A_RPP) {
            float4 v = make_float4(0.f, 0.f, 0.f, 0.f);
            int m = m0 + r;
            if (m < M) v = *(const float4*)(A + (long long)m * lda + k0 + ac);
            As[ac][r] = v.x; As[ac + 1][r] = v.y; As[ac + 2][r] = v.z; As[ac + 3][r] = v.w;
        }
#pragma unroll
        for (int r = wr0; r < BK; r += B_RPP) {
            float4 v = make_float4(0.f, 0.f, 0.f, 0.f);
            int n = n0 + wc;
            if (n < N) v = *(const float4*)(W + (long long)(k0 + r) * N + n);
            *(float4*)&Bs[r][wc] = v;
        }
        __syncthreads();
#pragma unroll
        for (int kk = 0; kk < BK; kk++) {
            float af[TM], bf[TN];
#pragma unroll
            for (int i = 0; i < TM; i += 4) *(float4*)&af[i] = *(const float4*)&As[kk][ty * TM + i];
#pragma unroll
            for (int j = 0; j < TN; j += 4) *(float4*)&bf[j] = *(const float4*)&Bs[kk][tx * TN + j];
#pragma unroll
            for (int i = 0; i < TM; i++)
#pragma unroll
                for (int j = 0; j < TN; j++) acc[i][j] = fmaf(af[i], bf[j], acc[i][j]);
        }
    }
    const int nb = n0 + tx * TN;
    if (nb >= N) return;
#pragma unroll
    for (int i = 0; i < TM; i++) {
        int m = m0 + ty * TM + i;
        if (m >= M) break;
#pragma unroll
        for (int j = 0; j < TN; j += 4) {
            float4 v;
            v.x = acc[i][j]; v.y = acc[i][j + 1]; v.z = acc[i][j + 2]; v.w = acc[i][j + 3];
            *(float4*)(C + (long long)m * ldc + nb + j) = v;
        }
    }
}

// ------------------- weight transpose: O[u][pn][koff+k] = W[u][k][n], k < klimit -------------------
__global__ void wtrans(const float* __restrict__ W, __half* __restrict__ Oh,
                       int Kreal, int Nreal, int KpadTot, int Npad, int koff,
                       int gatePerm, int klimit)
{
    __shared__ float tt[64][33];
    int u = blockIdx.z, kb = blockIdx.x * 64, nb = blockIdx.y * 32;
    const float* Wu = W + (size_t)u * Kreal * Nreal;
    int tx = threadIdx.x, ty = threadIdx.y;  // 32 x 8
#pragma unroll
    for (int yy = ty; yy < 64; yy += 8) {
        int k = kb + yy, n = nb + tx;
        tt[yy][tx] = (k < Kreal && n < Nreal) ? Wu[(size_t)k * Nreal + n] : 0.f;
    }
    __syncthreads();
    __half* OhU = Oh + (size_t)u * Npad * KpadTot + (size_t)koff;
#pragma unroll
    for (int yy = ty; yy < 32; yy += 8) {
        int n = nb + yy;
        int k = kb + 2 * tx;
        if (k + 1 < klimit) {
            int pn = gatePerm ? ((n % 600) * 4 + n / 600) : n;
            __half2 v = __floats2half2_rn(tt[2 * tx][yy], tt[2 * tx + 1][yy]);
            *(__half2*)(OhU + (size_t)pn * KpadTot + k) = v;
        }
    }
}

// ------------------- x -> fp16 padded -------------------
__global__ void conv_x(const float* __restrict__ x, __half* __restrict__ o)
{
    int idx = blockIdx.x * blockDim.x + threadIdx.x;
    if (idx >= BB * KP_X) return;
    int k = idx % KP_X, b = idx / KP_X;
    o[idx] = __float2half_rn(k < IND ? x[(size_t)b * IND + k] : 0.f);
}

// ------------------- A_pre = [scale*xv | hs] fp16 -------------------
__global__ void conv_pre(const __half* __restrict__ xv, const float* __restrict__ hs,
                         const float* __restrict__ scale, __half* __restrict__ oh)
{
    size_t idx = (size_t)blockIdx.x * blockDim.x + threadIdx.x;
    if (idx >= (size_t)NU * BB * KP_PRE) return;
    int k = (int)(idx % KP_PRE);
    int b = (int)((idx / KP_PRE) % BB);
    int u = (int)(idx / ((size_t)KP_PRE * BB));
    float v = 0.f;
    if (k < VDD) v = scale[b * NU + u] * __half2float(xv[(size_t)b * VDD + k]);
    else if (k >= KOFF_H && k < KOFF_H + HH)
        v = hs[(size_t)b * (NU * HH) + u * HH + (k - KOFF_H)];
    oh[idx] = __float2half_rn(v);
}

// ------------------- score + top-k (fp32) -------------------
__global__ void score_topk(const float* __restrict__ qry, const float* __restrict__ xk,
                           float* __restrict__ scale, float* __restrict__ mask)
{
    int gw = (blockIdx.x * blockDim.x + threadIdx.x) >> 5;
    int lane = threadIdx.x & 31;
    if (gw >= BB) return;
    int b = gw;
    float xk0 = xk[b * 64 + lane], xk1 = xk[b * 64 + 32 + lane];
    float s[NU];
#pragma unroll
    for (int u = 0; u < NU; u++) {
        const float* q = qry + b * (NU * 64) + u * 64;
        float v = q[lane] * xk0 + q[32 + lane] * xk1;
#pragma unroll
        for (int o = 16; o; o >>= 1) v += __shfl_xor_sync(~0u, v, o);
        s[u] = v * 0.125f;
    }
    if (lane == 0) {
#pragma unroll
        for (int u = 0; u < NU; u++) {
            int cnt = 0;
#pragma unroll
            for (int v = 0; v < NU; v++)
                if (s[v] > s[u] || (s[v] == s[u] && v < u)) cnt++;
            float m = (cnt < 4) ? 1.f : 0.f;
            mask[b * NU + u] = m;
            scale[b * NU + u] = m / (1.f + expf(-s[u]));
        }
    }
}

// ------------------- comm attention: one block per b, all 6 units -------------------
__global__ void __launch_bounds__(256)
comm_attn(const float* __restrict__ ckq, const __half* __restrict__ cv,
          const float* __restrict__ mask, __half* __restrict__ cxh)
{
    int b = blockIdx.x;
    __shared__ float s_ckq[NU * 256];
    __shared__ float s_sc[NU][4][NU];
    __shared__ float s_pr[NU][4][8];
    int t = threadIdx.x;
    const float* ckqb = ckq + (size_t)b * (NU * 256);
    for (int i = t; i < NU * 256; i += 256) s_ckq[i] = ckqb[i];
    __syncthreads();

    int w = t >> 5, lane = t & 31;
    for (int p = w; p < NU * 4 * NU; p += 8) {
        int uq = p / 24, rem = p % 24, hh = rem / 6, m = rem % 6;
        float v = s_ckq[uq * 256 + 128 + hh * 32 + lane] * s_ckq[m * 256 + hh * 32 + lane];
#pragma unroll
        for (int o = 16; o; o >>= 1) v += __shfl_xor_sync(~0u, v, o);
        if (lane == 0) s_sc[uq][hh][m] = v * 0.17677669529663687f;
    }
    __syncthreads();

    if (t < NU * 4) {
        int uq = t >> 2, hh = t & 3;
        float mx = -1e30f;
#pragma unroll
        for (int m = 0; m < NU; m++) mx = fmaxf(mx, s_sc[uq][hh][m]);
        float e[NU], sum = 0.f;
#pragma unroll
        for (int m = 0; m < NU; m++) { e[m] = expf(s_sc[uq][hh][m] - mx); sum += e[m]; }
        float inv = mask[b * NU + uq] / sum;
#pragma unroll
        for (int m = 0; m < NU; m++) s_pr[uq][hh][m] = e[m] * inv;
    }
    __syncthreads();

    const __half* cvb = cv + (size_t)b * (NU * 2400);
    for (int i = t; i < 2400; i += 256) {
        int hh = i / 600;
        float c[NU];
#pragma unroll
        for (int m = 0; m < NU; m++) c[m] = __half2float(cvb[m * 2400 + i]);
#pragma unroll
        for (int uq = 0; uq < NU; uq++) {
            float a = 0.f;
#pragma unroll
            for (int m = 0; m < NU; m++) a += s_pr[uq][hh][m] * c[m];
            cxh[((size_t)uq * BB + b) * KP_CTX + i] = __float2half_rn(a);
        }
    }
}

// ------------------------- launch -------------------------
extern "C" void kernel_launch(void* const* d_in, const int* in_sizes, int n_in,
                              void* d_out, int out_size)
{
    const float* x    = (const float*)d_in[0];
    const float* hs   = (const float*)d_in[1];
    const float* cs   = (const float*)d_in[2];
    const float* Wk   = (const float*)d_in[3];
    const float* Wv   = (const float*)d_in[4];
    const float* Wq   = (const float*)d_in[5];
    const float* Wi2h = (const float*)d_in[6];
    const float* Wh2h = (const float*)d_in[7];
    const float* Wck  = (const float*)d_in[8];
    const float* Wcq  = (const float*)d_in[9];
    const float* Wcv  = (const float*)d_in[10];
    const float* Wco  = (const float*)d_in[11];

    float* hs_out = (float*)d_out;
    float* cs_out = hs_out + (size_t)BB * NU * HH;

    float *xk, *qry, *scale, *mask, *hb, *ckq;
    __half *xvh, *cvh, *aph, *hbh, *cxh, *x16, *w12h, *w3h, *w4h, *w56h, *wv16;
    cudaGetSymbolAddress((void**)&xk, g_xk);
    cudaGetSymbolAddress((void**)&qry, g_qry);     cudaGetSymbolAddress((void**)&scale, g_scale);
    cudaGetSymbolAddress((void**)&mask, g_mask);   cudaGetSymbolAddress((void**)&hb, g_hb);
    cudaGetSymbolAddress((void**)&ckq, g_ckq);
    cudaGetSymbolAddress((void**)&xvh, g_xvh);
    cudaGetSymbolAddress((void**)&cvh, g_cvh);
    cudaGetSymbolAddress((void**)&aph, g_aph);
    cudaGetSymbolAddress((void**)&hbh, g_hbh);
    cudaGetSymbolAddress((void**)&cxh, g_cxh);
    cudaGetSymbolAddress((void**)&x16, g_x16);
    cudaGetSymbolAddress((void**)&w12h, g_w12h);
    cudaGetSymbolAddress((void**)&w3h, g_w3h);
    cudaGetSymbolAddress((void**)&w4h, g_w4h);
    cudaGetSymbolAddress((void**)&w56h, g_w56h);
    cudaGetSymbolAddress((void**)&wv16, g_wv16);

    cudaFuncSetAttribute(hmma_gemm<0>, cudaFuncAttributeMaxDynamicSharedMemorySize, SMEM_DYN);
    cudaFuncSetAttribute(hmma_gemm<3>, cudaFuncAttributeMaxDynamicSharedMemorySize, SMEM_DYN);
    cudaFuncSetAttribute(hmma_gemm<4>, cudaFuncAttributeMaxDynamicSharedMemorySize, SMEM_DYN);
    cudaFuncSetAttribute(hmma_gemm<5>, cudaFuncAttributeMaxDynamicSharedMemorySize, SMEM_DYN);

    dim3 tb(32, 8);
    // weight transposes; w12 gate-interleaved; klimit guards the trimmed pads
    wtrans<<<dim3(7,  75, NU), tb>>>(Wi2h, w12h, 400, 2400, KP_PRE, NP_BIG, 0, 1, KOFF_H);
    wtrans<<<dim3(10, 75, NU), tb>>>(Wh2h, w12h, 600, 2400, KP_PRE, NP_BIG, KOFF_H, 1, KP_PRE - KOFF_H);
    wtrans<<<dim3(10, 75, NU), tb>>>(Wcv, w3h, 600, 2400, KP_H, NP_BIG, 0, 0, KP_H);
    wtrans<<<dim3(38, 19, NU), tb>>>(Wco, w4h, 2400, 600, KP_CTX, NP_H, 0, 0, KP_CTX);
    wtrans<<<dim3(10, 4, NU), tb>>>(Wck, w56h, 600, 128, KP_H, NP_CKQ, 0, 0, KP_H);
    wtrans<<<dim3(10, 4, NU), tb>>>(Wcq, w56h + (size_t)128 * KP_H, 600, 128, KP_H, NP_CKQ, 0, 0, KP_H);
    wtrans<<<dim3(10, 13, 1), tb>>>(Wv, wv16, 600, 400, KP_X, NP_V, 0, 0, KP_X);

    conv_x<<<(BB * KP_X + 255) / 256, 256>>>(x, x16);

    // fp32 mask path
    gemm_simt<128, 64, 8, 8, 4><<<dim3(1, 32, 1), 256>>>(x, IND, 0, Wk, 0, xk, KD, 0, BB, KD, IND);
    gemm_simt<128, 64, 8, 8, 4><<<dim3(1, 32, NU), 256>>>(
        hs, NU * HH, HH, Wq, (long long)HH * KD, qry, NU * KD, KD, BB, KD, HH);

    // xv = x @ Wv  (fp16 out)
    hmma_gemm<4><<<dim3(4, 32, 1), 256, SMEM_DYN>>>(
        x16, 0LL, KP_X, wv16, 0LL, xvh, VDD, 0, VDD,
        nullptr, nullptr, nullptr, 0, 0, nullptr, nullptr);

    score_topk<<<(BB * 32 + 255) / 256, 256>>>(qry, xk, scale, mask);
    conv_pre<<<(int)(((size_t)NU * BB * KP_PRE + 255) / 256), 256>>>(xvh, hs, scale, aph);

    // preact GEMM + fused LSTM epilogue -> hb, hbh, cs_out
    hmma_gemm<5><<<dim3(19, 32, NU), 256, SMEM_DYN>>>(
        aph, (long long)BB * KP_PRE, KP_PRE, w12h, (long long)NP_BIG * KP_PRE,
        hb, 0, 0, 2400, mask, cs, nullptr, 0, 0, cs_out, hbh);

    // ck|cq fused (N=256, fp32 out)
    hmma_gemm<0><<<dim3(2, 32, NU), 256, SMEM_DYN>>>(
        hbh, (long long)BB * KP_H, KP_H, w56h, (long long)NP_CKQ * KP_H,
        ckq, NU * 256, 256, 256, nullptr, nullptr, nullptr, 0, 0, nullptr, nullptr);

    // cv -> fp16
    hmma_gemm<4><<<dim3(19, 32, NU), 256, SMEM_DYN>>>(
        hbh, (long long)BB * KP_H, KP_H, w3h, (long long)NP_BIG * KP_H,
        cvh, NU * 2400, 2400, 2400, nullptr, nullptr, nullptr, 0, 0, nullptr, nullptr);

    comm_attn<<<BB, 256>>>(ckq, cvh, mask, cxh);

    // hs_out = mask ? ctx@Wco + hb : hs
    hmma_gemm<3><<<dim3(5, 32, NU), 256, SMEM_DYN>>>(
        cxh, (long long)BB * KP_CTX, KP_CTX, w4h, (long long)NP_H * KP_CTX,
        hs_out, NU * HH, HH, HH, mask, hb, hs, NU * HH, HH, nullptr, nullptr);

    (void)in_sizes; (void)n_in; (void)out_size;
}

// round 9
// speedup vs baseline: 5.4402x; 1.1620x over previous
#include <cuda_runtime.h>
#include <cuda_fp16.h>
#include <math.h>
#include <stdint.h>

#define BB 4096
#define NU 6
#define IND 600
#define HH 600
#define VDD 400
#define KD 64
#define KP_PRE 1024   // 416 (xv) + 608 (hs)
#define KOFF_H 416
#define KP_H   608
#define KP_X   608
#define KP_CTX 2400
#define NP_BIG 2432
#define NP_H   640
#define NP_CKQ 256
#define NP_V   512

// ------------------------- device scratch -------------------------
__device__ __align__(16) float g_xk[BB * KD];
__device__ __align__(16) float g_qry[BB * NU * KD];
__device__ __align__(16) float g_scale[BB * NU];
__device__ __align__(16) float g_mask[BB * NU];
__device__ __align__(16) float g_hb[(size_t)BB * NU * HH];
__device__ __align__(16) float g_ckq[(size_t)BB * NU * 256];
__device__ int g_cnt[NU];
__device__ int g_posmap[BB * NU];
__device__ int g_blist[NU * BB];

__device__ __align__(16) __half g_xvh[(size_t)BB * VDD];
__device__ __align__(16) __half g_cvh[(size_t)BB * NU * 2400];
__device__ __align__(16) __half g_aph[(size_t)NU * BB * KP_PRE];
__device__ __align__(16) __half g_hbh[(size_t)NU * BB * KP_H];
__device__ __align__(16) __half g_cxc[(size_t)NU * BB * KP_CTX];
__device__ __align__(16) __half g_x16[(size_t)BB * KP_X];
__device__ __align__(16) __half g_w12h[(size_t)NU * NP_BIG * KP_PRE];
__device__ __align__(16) __half g_w3h[(size_t)NU * NP_BIG * KP_H];
__device__ __align__(16) __half g_w4h[(size_t)NU * NP_H * KP_CTX];
__device__ __align__(16) __half g_w56h[(size_t)NU * NP_CKQ * KP_H];
__device__ __align__(16) __half g_wv16[(size_t)NP_V * KP_X];

// ------------------------- helpers -------------------------
__device__ __forceinline__ uint32_t smem_u32(const void* p) {
    uint32_t a;
    asm("{ .reg .u64 t; cvta.to.shared.u64 t, %1; cvt.u32.u64 %0, t; }" : "=r"(a) : "l"(p));
    return a;
}
__device__ __forceinline__ void cp16(uint32_t dst, const void* src) {
    asm volatile("cp.async.cg.shared.global [%0], [%1], 16;\n" :: "r"(dst), "l"(src));
}
__device__ __forceinline__ void mma16816(float* c, const uint32_t* a, uint32_t b0, uint32_t b1) {
    asm volatile(
        "mma.sync.aligned.m16n8k16.row.col.f32.f16.f16.f32 "
        "{%0,%1,%2,%3}, {%4,%5,%6,%7}, {%8,%9}, {%0,%1,%2,%3};"
        : "+f"(c[0]), "+f"(c[1]), "+f"(c[2]), "+f"(c[3])
        : "r"(a[0]), "r"(a[1]), "r"(a[2]), "r"(a[3]), "r"(b0), "r"(b1));
}
__device__ __forceinline__ void ldsm4(uint32_t* r, uint32_t addr) {
    asm volatile("ldmatrix.sync.aligned.m8n8.x4.shared.b16 {%0,%1,%2,%3}, [%4];"
                 : "=r"(r[0]), "=r"(r[1]), "=r"(r[2]), "=r"(r[3]) : "r"(addr));
}
__device__ __forceinline__ float sigf(float x) { return 1.f / (1.f + expf(-x)); }

#define TILE_B   10240
#define STAGE_B  20480
#define NSTAGE   4
#define SMEM_DYN (NSTAGE * STAGE_B + 16)

// ------------------------- HMMA GEMM (fp16, ldmatrix, 4-stage) -------------------------
// EPI 0: fp32 store. EPI 4: fp16 store.
// EPI 5: fused LSTM (gate-interleaved cols): Cv=hb(f32), S=mask, E1=cs, X2=cs_out, X3=hbh.
// EPI 6: compact-row scatter: Cv=hs_out, E1=hb, IB=blist, CT=cnt; C[b,z] = acc + hb[b,z].
template <int EPI>
__global__ void __launch_bounds__(256, 2)
hmma_gemm(const __half* __restrict__ A, long long sA, int Kpad,
          const __half* __restrict__ B, long long sB,
          void* __restrict__ Cv, int ldc, int sC, int Nreal,
          const float* __restrict__ S,
          const float* __restrict__ E1,
          float* __restrict__ X2, __half* __restrict__ X3,
          const int* __restrict__ IB, const int* __restrict__ CT)
{
    extern __shared__ __align__(16) char dsm[];
    const uint32_t tiles_u32 = smem_u32(dsm);

    const int tid = threadIdx.x;
    const int wid = tid >> 5, lane = tid & 31;
    const int wm = wid >> 1, wn = wid & 1;        // 4 x 2 warps, 32x64 each
    const int g = lane >> 2, t = lane & 3;
    const int lane16 = lane & 15, lanehi = lane >> 4;

    const int z = blockIdx.z, m0 = blockIdx.y * 128, n0 = blockIdx.x * 128;
    int cntz = 0;
    if (EPI == 6) {
        cntz = CT[z];
        if (m0 >= cntz) return;
    }
    const __half* Az = A + (size_t)z * sA + (size_t)m0 * Kpad;
    const __half* Bz = B + (size_t)z * sB + (size_t)n0 * Kpad;

    const int nch = Kpad >> 5;   // BK = 32

    const int idx0 = tid * 2, idx1 = tid * 2 + 1;
    const int r_0 = idx0 >> 2, c_0 = idx0 & 3;
    const int r_1 = idx1 >> 2, c_1 = idx1 & 3;

    auto load_chunk = [&](int kc) {
        uint32_t sb = tiles_u32 + (uint32_t)(kc & 3) * STAGE_B;
        int k0 = kc << 5;
        cp16(sb + r_0 * 80 + c_0 * 16, Az + (size_t)r_0 * Kpad + k0 + c_0 * 8);
        cp16(sb + r_1 * 80 + c_1 * 16, Az + (size_t)r_1 * Kpad + k0 + c_1 * 8);
        cp16(sb + TILE_B + r_0 * 80 + c_0 * 16, Bz + (size_t)r_0 * Kpad + k0 + c_0 * 8);
        cp16(sb + TILE_B + r_1 * 80 + c_1 * 16, Bz + (size_t)r_1 * Kpad + k0 + c_1 * 8);
    };

    float acc[2][8][4];
#pragma unroll
    for (int a = 0; a < 2; a++)
#pragma unroll
        for (int b = 0; b < 8; b++)
#pragma unroll
            for (int c = 0; c < 4; c++) acc[a][b][c] = 0.f;

    const uint32_t aOff = (uint32_t)((wm * 32 + lane16) * 80 + lanehi * 16);
    const uint32_t bOff = (uint32_t)(TILE_B + (wn * 64 + lane16) * 80 + lanehi * 16);

    load_chunk(0);
    asm volatile("cp.async.commit_group;" ::: "memory");
    load_chunk(1);
    asm volatile("cp.async.commit_group;" ::: "memory");
    load_chunk(2);
    asm volatile("cp.async.commit_group;" ::: "memory");

    for (int kc = 0; kc < nch; kc++) {
        asm volatile("cp.async.wait_group 2;" ::: "memory");
        __syncthreads();
        if (kc + 3 < nch) load_chunk(kc + 3);
        asm volatile("cp.async.commit_group;" ::: "memory");

        const uint32_t sb = tiles_u32 + (uint32_t)(kc & 3) * STAGE_B;
#pragma unroll
        for (int s16 = 0; s16 < 2; s16++) {
            const uint32_t ko = (uint32_t)(s16 * 32);
            uint32_t a0[4], a1[4];
            ldsm4(a0, sb + aOff + ko);
            ldsm4(a1, sb + aOff + 16 * 80 + ko);
#pragma unroll
            for (int nt2 = 0; nt2 < 4; nt2++) {
                uint32_t bb[4];
                ldsm4(bb, sb + bOff + (uint32_t)(nt2 * 16 * 80) + ko);
                mma16816(acc[0][nt2 * 2],     a0, bb[0], bb[2]);
                mma16816(acc[0][nt2 * 2 + 1], a0, bb[1], bb[3]);
                mma16816(acc[1][nt2 * 2],     a1, bb[0], bb[2]);
                mma16816(acc[1][nt2 * 2 + 1], a1, bb[1], bb[3]);
            }
        }
    }

    // ----- epilogue -----
    if (EPI == 5) {
        float* hb = (float*)Cv;
#pragma unroll
        for (int mt = 0; mt < 2; mt++) {
            const int b0r = m0 + wm * 32 + mt * 16 + g;
            const int b1r = b0r + 8;
#pragma unroll
            for (int nt = 0; nt < 8; nt++) {
                float i0 = acc[mt][nt][0], f0 = acc[mt][nt][1];
                float i1 = acc[mt][nt][2], f1 = acc[mt][nt][3];
                float o0 = __shfl_xor_sync(~0u, i0, 1);
                float g0 = __shfl_xor_sync(~0u, f0, 1);
                float o1 = __shfl_xor_sync(~0u, i1, 1);
                float g1 = __shfl_xor_sync(~0u, f1, 1);
                if ((t & 1) == 0) {
                    const int c0 = n0 + wn * 64 + nt * 8 + 2 * t;
                    const int j = c0 >> 2;
                    if (j < HH) {
                        size_t i00 = ((size_t)b0r * NU + z) * HH + j;
                        size_t i10 = ((size_t)b1r * NU + z) * HH + j;
                        size_t h00 = ((size_t)z * BB + b0r) * KP_H + j;
                        size_t h10 = ((size_t)z * BB + b1r) * KP_H + j;
                        float mk0 = S[b0r * NU + z], mk1 = S[b1r * NU + z];
                        float cp0 = E1[i00], cp1 = E1[i10];
                        float c0v = cp0 * sigf(f0) + sigf(i0) * tanhf(g0);
                        float c1v = cp1 * sigf(f1) + sigf(i1) * tanhf(g1);
                        float h0v = sigf(o0) * tanhf(c0v);
                        float h1v = sigf(o1) * tanhf(c1v);
                        hb[i00] = h0v;  hb[i10] = h1v;
                        X2[i00] = (mk0 > 0.5f) ? c0v : cp0;
                        X2[i10] = (mk1 > 0.5f) ? c1v : cp1;
                        X3[h00] = __float2half_rn(h0v);
                        X3[h10] = __float2half_rn(h1v);
                    }
                }
            }
        }
        return;
    }

    if (EPI == 6) {
        float* out = (float*)Cv;
#pragma unroll
        for (int mt = 0; mt < 2; mt++) {
            const int r0 = m0 + wm * 32 + mt * 16 + g;
            const int r1 = r0 + 8;
            const bool v0 = r0 < cntz, v1 = r1 < cntz;
            const int b0 = v0 ? IB[z * BB + r0] : 0;
            const int b1 = v1 ? IB[z * BB + r1] : 0;
            const size_t base0 = ((size_t)b0 * NU + z) * HH;
            const size_t base1 = ((size_t)b1 * NU + z) * HH;
#pragma unroll
            for (int nt = 0; nt < 8; nt++) {
                const int n = n0 + wn * 64 + nt * 8 + 2 * t;
                if (n < Nreal) {
                    if (v0) {
                        float2 o = *(const float2*)(E1 + base0 + n);
                        float2 v = make_float2(acc[mt][nt][0] + o.x, acc[mt][nt][1] + o.y);
                        *(float2*)(out + base0 + n) = v;
                    }
                    if (v1) {
                        float2 o = *(const float2*)(E1 + base1 + n);
                        float2 v = make_float2(acc[mt][nt][2] + o.x, acc[mt][nt][3] + o.y);
                        *(float2*)(out + base1 + n) = v;
                    }
                }
            }
        }
        return;
    }

#pragma unroll
    for (int mt = 0; mt < 2; mt++) {
        const int r0 = m0 + wm * 32 + mt * 16 + g;
        const int r1 = r0 + 8;
        float* c0row = nullptr; float* c1row = nullptr;
        __half* h0row = nullptr; __half* h1row = nullptr;
        if (EPI == 4) {
            h0row = (__half*)Cv + (size_t)r0 * ldc + (size_t)z * sC;
            h1row = (__half*)Cv + (size_t)r1 * ldc + (size_t)z * sC;
        } else {
            c0row = (float*)Cv + (size_t)r0 * ldc + (size_t)z * sC;
            c1row = (float*)Cv + (size_t)r1 * ldc + (size_t)z * sC;
        }
#pragma unroll
        for (int nt = 0; nt < 8; nt++) {
            const int n = n0 + wn * 64 + nt * 8 + 2 * t;
            if (n < Nreal) {
                float2 v0 = make_float2(acc[mt][nt][0], acc[mt][nt][1]);
                float2 v1 = make_float2(acc[mt][nt][2], acc[mt][nt][3]);
                if (EPI == 4) {
                    *(__half2*)(h0row + n) = __floats2half2_rn(v0.x, v0.y);
                    *(__half2*)(h1row + n) = __floats2half2_rn(v1.x, v1.y);
                } else {
                    *(float2*)(c0row + n) = v0;
                    *(float2*)(c1row + n) = v1;
                }
            }
        }
    }
}

// ------------------------- unified xk + qry SIMT GEMM (fp32 mask path) -------------------------
// z<6: qry[:,z,:] = hs[:,z,:] @ Wq[z];  z==6: xk = x @ Wk.  M=4096, N=64, K=600.
__global__ void __launch_bounds__(256)
xkqry_simt(const float* __restrict__ x, const float* __restrict__ hs,
           const float* __restrict__ Wk, const float* __restrict__ Wq,
           float* __restrict__ xk, float* __restrict__ qry)
{
    __shared__ __align__(16) float As[8][64];
    __shared__ __align__(16) float Bs[8][64];
    const int z = blockIdx.z;
    const float* A; int lda; const float* W; float* C; int ldc;
    if (z < NU) {
        A = hs + z * HH; lda = NU * HH;
        W = Wq + (size_t)z * HH * KD;
        C = qry + z * KD; ldc = NU * KD;
    } else {
        A = x; lda = IND; W = Wk; C = xk; ldc = KD;
    }
    const int tid = threadIdx.x;
    const int tx = tid & 15, ty = tid >> 4;
    const int m0 = blockIdx.y * 64;
    float acc[4][4];
#pragma unroll
    for (int i = 0; i < 4; i++)
#pragma unroll
        for (int j = 0; j < 4; j++) acc[i][j] = 0.f;
    const int ar = tid >> 1, ac = (tid & 1) * 4;
    const int wr = tid >> 4, wc = (tid & 15) * 4;
    for (int k0 = 0; k0 < 600; k0 += 8) {
        __syncthreads();
        if (ar < 64) {
            float4 v = *(const float4*)(A + (size_t)(m0 + ar) * lda + k0 + ac);
            As[ac][ar] = v.x; As[ac + 1][ar] = v.y; As[ac + 2][ar] = v.z; As[ac + 3][ar] = v.w;
        }
        if (wr < 8) {
            float4 v = *(const float4*)(W + (size_t)(k0 + wr) * KD + wc);
            *(float4*)&Bs[wr][wc] = v;
        }
        __syncthreads();
#pragma unroll
        for (int kk = 0; kk < 8; kk++) {
            float af[4], bf[4];
            *(float4*)af = *(const float4*)&As[kk][ty * 4];
            *(float4*)bf = *(const float4*)&Bs[kk][tx * 4];
#pragma unroll
            for (int i = 0; i < 4; i++)
#pragma unroll
                for (int j = 0; j < 4; j++) acc[i][j] = fmaf(af[i], bf[j], acc[i][j]);
        }
    }
#pragma unroll
    for (int i = 0; i < 4; i++) {
        float4 v;
        v.x = acc[i][0]; v.y = acc[i][1]; v.z = acc[i][2]; v.w = acc[i][3];
        *(float4*)(C + (size_t)(m0 + ty * 4 + i) * ldc + tx * 4) = v;
    }
}

// ------------------- merged weight transpose (all 7 segments, one launch) -------------------
__global__ void __launch_bounds__(256)
wtrans_all(const float* __restrict__ Wi2h, const float* __restrict__ Wh2h,
           const float* __restrict__ Wcv, const float* __restrict__ Wco,
           const float* __restrict__ Wck, const float* __restrict__ Wcq,
           const float* __restrict__ Wv,
           __half* __restrict__ w12h, __half* __restrict__ w3h, __half* __restrict__ w4h,
           __half* __restrict__ w56h, __half* __restrict__ wv16)
{
    __shared__ float tt[64][33];
    int L = blockIdx.x;
    const float* W; __half* Oh;
    int Kreal, Nreal, Kp, Np, koff, perm, klim, gx, gy;
    if (L < 3150)       { W = Wi2h; Oh = w12h; Kreal = 400;  Nreal = 2400; Kp = KP_PRE; Np = NP_BIG; koff = 0;      perm = 1; klim = KOFF_H; gx = 7;  gy = 75; }
    else if (L < 7650)  { L -= 3150;  W = Wh2h; Oh = w12h; Kreal = 600;  Nreal = 2400; Kp = KP_PRE; Np = NP_BIG; koff = KOFF_H; perm = 1; klim = 608;  gx = 10; gy = 75; }
    else if (L < 12150) { L -= 7650;  W = Wcv;  Oh = w3h;  Kreal = 600;  Nreal = 2400; Kp = KP_H;   Np = NP_BIG; koff = 0;      perm = 0; klim = 608;  gx = 10; gy = 75; }
    else if (L < 16482) { L -= 12150; W = Wco;  Oh = w4h;  Kreal = 2400; Nreal = 600;  Kp = KP_CTX; Np = NP_H;   koff = 0;      perm = 0; klim = 2400; gx = 38; gy = 19; }
    else if (L < 16722) { L -= 16482; W = Wck;  Oh = w56h; Kreal = 600;  Nreal = 128;  Kp = KP_H;   Np = NP_CKQ; koff = 0;      perm = 0; klim = 608;  gx = 10; gy = 4; }
    else if (L < 16962) { L -= 16722; W = Wcq;  Oh = w56h + (size_t)128 * KP_H; Kreal = 600; Nreal = 128; Kp = KP_H; Np = NP_CKQ; koff = 0; perm = 0; klim = 608; gx = 10; gy = 4; }
    else                { L -= 16962; W = Wv;   Oh = wv16; Kreal = 600;  Nreal = 400;  Kp = KP_X;   Np = NP_V;   koff = 0;      perm = 0; klim = 608;  gx = 10; gy = 13; }
    const int seg = gx * gy;
    const int u = L / seg, rem = L % seg;
    const int kb = (rem % gx) * 64, nb = (rem / gx) * 32;
    const float* Wu = W + (size_t)u * Kreal * Nreal;
    const int tx = threadIdx.x & 31, ty = threadIdx.x >> 5;  // 32 x 8
#pragma unroll
    for (int yy = ty; yy < 64; yy += 8) {
        int k = kb + yy, n = nb + tx;
        tt[yy][tx] = (k < Kreal && n < Nreal) ? Wu[(size_t)k * Nreal + n] : 0.f;
    }
    __syncthreads();
    __half* OhU = Oh + (size_t)u * Np * Kp + (size_t)koff;
#pragma unroll
    for (int yy = ty; yy < 32; yy += 8) {
        int n = nb + yy;
        int k = kb + 2 * tx;
        if (k + 1 < klim) {
            int pn = perm ? ((n % 600) * 4 + n / 600) : n;
            __half2 v = __floats2half2_rn(tt[2 * tx][yy], tt[2 * tx + 1][yy]);
            *(__half2*)(OhU + (size_t)pn * Kp + k) = v;
        }
    }
}

// ------------------- x -> fp16 padded -------------------
__global__ void conv_x(const float* __restrict__ x, __half* __restrict__ o)
{
    int idx = blockIdx.x * blockDim.x + threadIdx.x;
    if (idx >= BB * KP_X) return;
    int k = idx % KP_X, b = idx / KP_X;
    o[idx] = __float2half_rn(k < IND ? x[(size_t)b * IND + k] : 0.f);
}

// ------------------- A_pre = [scale*xv | hs] fp16 -------------------
__global__ void conv_pre(const __half* __restrict__ xv, const float* __restrict__ hs,
                         const float* __restrict__ scale, __half* __restrict__ oh)
{
    size_t idx = (size_t)blockIdx.x * blockDim.x + threadIdx.x;
    if (idx >= (size_t)NU * BB * KP_PRE) return;
    int k = (int)(idx % KP_PRE);
    int b = (int)((idx / KP_PRE) % BB);
    int u = (int)(idx / ((size_t)KP_PRE * BB));
    float v = 0.f;
    if (k < VDD) v = scale[b * NU + u] * __half2float(xv[(size_t)b * VDD + k]);
    else if (k >= KOFF_H && k < KOFF_H + HH)
        v = hs[(size_t)b * (NU * HH) + u * HH + (k - KOFF_H)];
    oh[idx] = __float2half_rn(v);
}

// ------------------- zero counters -------------------
__global__ void zero_cnt(int* cnt)
{
    if (threadIdx.x < NU) cnt[threadIdx.x] = 0;
}

// ------------------- score + top-k + compaction lists -------------------
__global__ void score_topk(const float* __restrict__ qry, const float* __restrict__ xk,
                           float* __restrict__ scale, float* __restrict__ mask,
                           int* __restrict__ cnt, int* __restrict__ posmap,
                           int* __restrict__ blist)
{
    int gw = (blockIdx.x * blockDim.x + threadIdx.x) >> 5;
    int lane = threadIdx.x & 31;
    if (gw >= BB) return;
    int b = gw;
    float xk0 = xk[b * 64 + lane], xk1 = xk[b * 64 + 32 + lane];
    float s[NU];
#pragma unroll
    for (int u = 0; u < NU; u++) {
        const float* q = qry + b * (NU * 64) + u * 64;
        float v = q[lane] * xk0 + q[32 + lane] * xk1;
#pragma unroll
        for (int o = 16; o; o >>= 1) v += __shfl_xor_sync(~0u, v, o);
        s[u] = v * 0.125f;
    }
    if (lane == 0) {
#pragma unroll
        for (int u = 0; u < NU; u++) {
            int c = 0;
#pragma unroll
            for (int v = 0; v < NU; v++)
                if (s[v] > s[u] || (s[v] == s[u] && v < u)) c++;
            float m = (c < 4) ? 1.f : 0.f;
            mask[b * NU + u] = m;
            scale[b * NU + u] = m / (1.f + expf(-s[u]));
            if (m > 0.5f) {
                int p = atomicAdd(&cnt[u], 1);
                blist[u * BB + p] = b;
                posmap[b * NU + u] = p;
            } else {
                posmap[b * NU + u] = -1;
            }
        }
    }
}

// ------------------- hs_out = hs for inactive rows -------------------
__global__ void fill_inactive(const float* __restrict__ hs, const int* __restrict__ posmap,
                              float* __restrict__ hs_out)
{
    size_t idx = (size_t)blockIdx.x * blockDim.x + threadIdx.x;
    if (idx >= (size_t)BB * NU * HH) return;
    int bu = (int)(idx / HH);
    if (posmap[bu] < 0) hs_out[idx] = hs[idx];
}

// ------------------- comm attention: one block per b, compact active outputs -------------------
__global__ void __launch_bounds__(256)
comm_attn(const float* __restrict__ ckq, const __half* __restrict__ cv,
          const float* __restrict__ mask, const int* __restrict__ posmap,
          __half* __restrict__ cxc)
{
    int b = blockIdx.x;
    __shared__ float s_ckq[NU * 256];
    __shared__ float s_sc[NU][4][NU];
    __shared__ float s_pr[NU][4][8];
    __shared__ int s_pos[NU];
    int t = threadIdx.x;
    const float* ckqb = ckq + (size_t)b * (NU * 256);
    for (int i = t; i < NU * 256; i += 256) s_ckq[i] = ckqb[i];
    if (t < NU) s_pos[t] = posmap[b * NU + t];
    __syncthreads();

    int w = t >> 5, lane = t & 31;
    for (int p = w; p < NU * 4 * NU; p += 8) {
        int uq = p / 24, rem = p % 24, hh = rem / 6, m = rem % 6;
        float v = s_ckq[uq * 256 + 128 + hh * 32 + lane] * s_ckq[m * 256 + hh * 32 + lane];
#pragma unroll
        for (int o = 16; o; o >>= 1) v += __shfl_xor_sync(~0u, v, o);
        if (lane == 0) s_sc[uq][hh][m] = v * 0.17677669529663687f;
    }
    __syncthreads();

    if (t < NU * 4) {
        int uq = t >> 2, hh = t & 3;
        float mx = -1e30f;
#pragma unroll
        for (int m = 0; m < NU; m++) mx = fmaxf(mx, s_sc[uq][hh][m]);
        float e[NU], sum = 0.f;
#pragma unroll
        for (int m = 0; m < NU; m++) { e[m] = expf(s_sc[uq][hh][m] - mx); sum += e[m]; }
        float inv = mask[b * NU + uq] / sum;
#pragma unroll
        for (int m = 0; m < NU; m++) s_pr[uq][hh][m] = e[m] * inv;
    }
    __syncthreads();

    const __half* cvb = cv + (size_t)b * (NU * 2400);
    for (int i = t; i < 2400; i += 256) {
        int hh = i / 600;
        float c[NU];
#pragma unroll
        for (int m = 0; m < NU; m++) c[m] = __half2float(cvb[m * 2400 + i]);
#pragma unroll
        for (int uq = 0; uq < NU; uq++) {
            int pos = s_pos[uq];
            if (pos >= 0) {
                float a = 0.f;
#pragma unroll
                for (int m = 0; m < NU; m++) a += s_pr[uq][hh][m] * c[m];
                cxc[((size_t)uq * BB + pos) * KP_CTX + i] = __float2half_rn(a);
            }
        }
    }
}

// ------------------------- launch -------------------------
extern "C" void kernel_launch(void* const* d_in, const int* in_sizes, int n_in,
                              void* d_out, int out_size)
{
    const float* x    = (const float*)d_in[0];
    const float* hs   = (const float*)d_in[1];
    const float* cs   = (const float*)d_in[2];
    const float* Wk   = (const float*)d_in[3];
    const float* Wv   = (const float*)d_in[4];
    const float* Wq   = (const float*)d_in[5];
    const float* Wi2h = (const float*)d_in[6];
    const float* Wh2h = (const float*)d_in[7];
    const float* Wck  = (const float*)d_in[8];
    const float* Wcq  = (const float*)d_in[9];
    const float* Wcv  = (const float*)d_in[10];
    const float* Wco  = (const float*)d_in[11];

    float* hs_out = (float*)d_out;
    float* cs_out = hs_out + (size_t)BB * NU * HH;

    float *xk, *qry, *scale, *mask, *hb, *ckq;
    int *cnt, *posmap, *blist;
    __half *xvh, *cvh, *aph, *hbh, *cxc, *x16, *w12h, *w3h, *w4h, *w56h, *wv16;
    cudaGetSymbolAddress((void**)&xk, g_xk);
    cudaGetSymbolAddress((void**)&qry, g_qry);     cudaGetSymbolAddress((void**)&scale, g_scale);
    cudaGetSymbolAddress((void**)&mask, g_mask);   cudaGetSymbolAddress((void**)&hb, g_hb);
    cudaGetSymbolAddress((void**)&ckq, g_ckq);
    cudaGetSymbolAddress((void**)&cnt, g_cnt);
    cudaGetSymbolAddress((void**)&posmap, g_posmap);
    cudaGetSymbolAddress((void**)&blist, g_blist);
    cudaGetSymbolAddress((void**)&xvh, g_xvh);
    cudaGetSymbolAddress((void**)&cvh, g_cvh);
    cudaGetSymbolAddress((void**)&aph, g_aph);
    cudaGetSymbolAddress((void**)&hbh, g_hbh);
    cudaGetSymbolAddress((void**)&cxc, g_cxc);
    cudaGetSymbolAddress((void**)&x16, g_x16);
    cudaGetSymbolAddress((void**)&w12h, g_w12h);
    cudaGetSymbolAddress((void**)&w3h, g_w3h);
    cudaGetSymbolAddress((void**)&w4h, g_w4h);
    cudaGetSymbolAddress((void**)&w56h, g_w56h);
    cudaGetSymbolAddress((void**)&wv16, g_wv16);

    cudaFuncSetAttribute(hmma_gemm<0>, cudaFuncAttributeMaxDynamicSharedMemorySize, SMEM_DYN);
    cudaFuncSetAttribute(hmma_gemm<4>, cudaFuncAttributeMaxDynamicSharedMemorySize, SMEM_DYN);
    cudaFuncSetAttribute(hmma_gemm<5>, cudaFuncAttributeMaxDynamicSharedMemorySize, SMEM_DYN);
    cudaFuncSetAttribute(hmma_gemm<6>, cudaFuncAttributeMaxDynamicSharedMemorySize, SMEM_DYN);

    // all weight transposes in one launch
    wtrans_all<<<17092, 256>>>(Wi2h, Wh2h, Wcv, Wco, Wck, Wcq, Wv,
                               w12h, w3h, w4h, w56h, wv16);
    conv_x<<<(BB * KP_X + 255) / 256, 256>>>(x, x16);
    zero_cnt<<<1, 32>>>(cnt);

    // fp32 mask path: xk + qry in one launch
    xkqry_simt<<<dim3(1, 64, 7), 256>>>(x, hs, Wk, Wq, xk, qry);

    // xv = x @ Wv  (fp16 out)
    hmma_gemm<4><<<dim3(4, 32, 1), 256, SMEM_DYN>>>(
        x16, 0LL, KP_X, wv16, 0LL, xvh, VDD, 0, VDD,
        nullptr, nullptr, nullptr, nullptr, nullptr, nullptr);

    score_topk<<<(BB * 32 + 255) / 256, 256>>>(qry, xk, scale, mask, cnt, posmap, blist);
    fill_inactive<<<(int)(((size_t)BB * NU * HH + 255) / 256), 256>>>(hs, posmap, hs_out);
    conv_pre<<<(int)(((size_t)NU * BB * KP_PRE + 255) / 256), 256>>>(xvh, hs, scale, aph);

    // preact GEMM + fused LSTM epilogue -> hb, hbh, cs_out
    hmma_gemm<5><<<dim3(19, 32, NU), 256, SMEM_DYN>>>(
        aph, (long long)BB * KP_PRE, KP_PRE, w12h, (long long)NP_BIG * KP_PRE,
        hb, 0, 0, 2400, mask, cs, cs_out, hbh, nullptr, nullptr);

    // ck|cq fused (N=256, fp32 out)
    hmma_gemm<0><<<dim3(2, 32, NU), 256, SMEM_DYN>>>(
        hbh, (long long)BB * KP_H, KP_H, w56h, (long long)NP_CKQ * KP_H,
        ckq, NU * 256, 256, 256, nullptr, nullptr, nullptr, nullptr, nullptr, nullptr);

    // cv -> fp16
    hmma_gemm<4><<<dim3(19, 32, NU), 256, SMEM_DYN>>>(
        hbh, (long long)BB * KP_H, KP_H, w3h, (long long)NP_BIG * KP_H,
        cvh, NU * 2400, 2400, 2400, nullptr, nullptr, nullptr, nullptr, nullptr, nullptr);

    comm_attn<<<BB, 256>>>(ckq, cvh, mask, posmap, cxc);

    // hs_out (active rows only) = ctx_compact @ Wco + hb, scattered by blist
    hmma_gemm<6><<<dim3(5, 32, NU), 256, SMEM_DYN>>>(
        cxc, (long long)BB * KP_CTX, KP_CTX, w4h, (long long)NP_H * KP_CTX,
        hs_out, 0, 0, HH, nullptr, hb, nullptr, nullptr, blist, cnt);

    (void)in_sizes; (void)n_in; (void)out_size;
}

// round 10
// speedup vs baseline: 5.6276x; 1.0344x over previous
#include <cuda_runtime.h>
#include <cuda_fp16.h>
#include <math.h>
#include <stdint.h>

#define BB 4096
#define NU 6
#define IND 600
#define HH 600
#define VDD 400
#define KD 64
#define KP_PRE 1024   // 416 (xv) + 608 (hs)
#define KOFF_H 416
#define KP_H   608
#define KP_X   608
#define KP_CTX 2400
#define NP_BIG 2432
#define NP_H   640
#define NP_CVQ 2688   // 2400 cv | 32 pad | 128 ck | 128 cq
#define CK_OFF 2432
#define CQ_OFF 2560
#define NP_V   512

// ------------------------- device scratch -------------------------
__device__ __align__(16) float g_xk[BB * KD];
__device__ __align__(16) float g_qry[BB * NU * KD];
__device__ __align__(16) float g_scale[BB * NU];
__device__ __align__(16) float g_mask[BB * NU];
__device__ __align__(16) float g_hb[(size_t)BB * NU * HH];
__device__ int g_cnt[NU];
__device__ int g_posmap[BB * NU];
__device__ int g_blist[NU * BB];

__device__ __align__(16) __half g_xvh[(size_t)BB * VDD];
__device__ __align__(16) __half g_cvq[(size_t)BB * NU * NP_CVQ];
__device__ __align__(16) __half g_aph[(size_t)NU * BB * KP_PRE];
__device__ __align__(16) __half g_hbh[(size_t)NU * BB * KP_H];
__device__ __align__(16) __half g_cxc[(size_t)NU * BB * KP_CTX];
__device__ __align__(16) __half g_x16[(size_t)BB * KP_X];
__device__ __align__(16) __half g_w12h[(size_t)NU * NP_BIG * KP_PRE];
__device__ __align__(16) __half g_wcvq[(size_t)NU * NP_CVQ * KP_H];
__device__ __align__(16) __half g_w4h[(size_t)NU * NP_H * KP_CTX];
__device__ __align__(16) __half g_wv16[(size_t)NP_V * KP_X];

// ------------------------- helpers -------------------------
__device__ __forceinline__ uint32_t smem_u32(const void* p) {
    uint32_t a;
    asm("{ .reg .u64 t; cvta.to.shared.u64 t, %1; cvt.u32.u64 %0, t; }" : "=r"(a) : "l"(p));
    return a;
}
__device__ __forceinline__ void cp16(uint32_t dst, const void* src) {
    asm volatile("cp.async.cg.shared.global [%0], [%1], 16;\n" :: "r"(dst), "l"(src));
}
__device__ __forceinline__ void mma16816(float* c, const uint32_t* a, uint32_t b0, uint32_t b1) {
    asm volatile(
        "mma.sync.aligned.m16n8k16.row.col.f32.f16.f16.f32 "
        "{%0,%1,%2,%3}, {%4,%5,%6,%7}, {%8,%9}, {%0,%1,%2,%3};"
        : "+f"(c[0]), "+f"(c[1]), "+f"(c[2]), "+f"(c[3])
        : "r"(a[0]), "r"(a[1]), "r"(a[2]), "r"(a[3]), "r"(b0), "r"(b1));
}
__device__ __forceinline__ void ldsm4(uint32_t* r, uint32_t addr) {
    asm volatile("ldmatrix.sync.aligned.m8n8.x4.shared.b16 {%0,%1,%2,%3}, [%4];"
                 : "=r"(r[0]), "=r"(r[1]), "=r"(r[2]), "=r"(r[3]) : "r"(addr));
}
__device__ __forceinline__ float sigf(float x) { return 1.f / (1.f + expf(-x)); }

#define TILE_B   10240
#define STAGE_B  20480
#define NSTAGE   4
#define SMEM_DYN (NSTAGE * STAGE_B + 16)

// ------------------------- HMMA GEMM (fp16, ldmatrix, 4-stage) -------------------------
// EPI 4: fp16 store.
// EPI 5: fused LSTM (gate-interleaved cols): Cv=hb(f32), S=mask, E1=cs, X2=cs_out, X3=hbh.
// EPI 6: compact-row scatter: Cv=hs_out, E1=hb, IB=blist, CT=cnt; C[b,z] = acc + hb[b,z].
template <int EPI>
__global__ void __launch_bounds__(256, 2)
hmma_gemm(const __half* __restrict__ A, long long sA, int Kpad,
          const __half* __restrict__ B, long long sB,
          void* __restrict__ Cv, int ldc, int sC, int Nreal,
          const float* __restrict__ S,
          const float* __restrict__ E1,
          float* __restrict__ X2, __half* __restrict__ X3,
          const int* __restrict__ IB, const int* __restrict__ CT)
{
    extern __shared__ __align__(16) char dsm[];
    const uint32_t tiles_u32 = smem_u32(dsm);

    const int tid = threadIdx.x;
    const int wid = tid >> 5, lane = tid & 31;
    const int wm = wid >> 1, wn = wid & 1;        // 4 x 2 warps, 32x64 each
    const int g = lane >> 2, t = lane & 3;
    const int lane16 = lane & 15, lanehi = lane >> 4;

    const int z = blockIdx.z, m0 = blockIdx.y * 128, n0 = blockIdx.x * 128;
    int cntz = 0;
    if (EPI == 6) {
        cntz = CT[z];
        if (m0 >= cntz) return;
    }
    const __half* Az = A + (size_t)z * sA + (size_t)m0 * Kpad;
    const __half* Bz = B + (size_t)z * sB + (size_t)n0 * Kpad;

    const int nch = Kpad >> 5;   // BK = 32

    const int idx0 = tid * 2, idx1 = tid * 2 + 1;
    const int r_0 = idx0 >> 2, c_0 = idx0 & 3;
    const int r_1 = idx1 >> 2, c_1 = idx1 & 3;

    auto load_chunk = [&](int kc) {
        uint32_t sb = tiles_u32 + (uint32_t)(kc & 3) * STAGE_B;
        int k0 = kc << 5;
        cp16(sb + r_0 * 80 + c_0 * 16, Az + (size_t)r_0 * Kpad + k0 + c_0 * 8);
        cp16(sb + r_1 * 80 + c_1 * 16, Az + (size_t)r_1 * Kpad + k0 + c_1 * 8);
        cp16(sb + TILE_B + r_0 * 80 + c_0 * 16, Bz + (size_t)r_0 * Kpad + k0 + c_0 * 8);
        cp16(sb + TILE_B + r_1 * 80 + c_1 * 16, Bz + (size_t)r_1 * Kpad + k0 + c_1 * 8);
    };

    float acc[2][8][4];
#pragma unroll
    for (int a = 0; a < 2; a++)
#pragma unroll
        for (int b = 0; b < 8; b++)
#pragma unroll
            for (int c = 0; c < 4; c++) acc[a][b][c] = 0.f;

    const uint32_t aOff = (uint32_t)((wm * 32 + lane16) * 80 + lanehi * 16);
    const uint32_t bOff = (uint32_t)(TILE_B + (wn * 64 + lane16) * 80 + lanehi * 16);

    load_chunk(0);
    asm volatile("cp.async.commit_group;" ::: "memory");
    load_chunk(1);
    asm volatile("cp.async.commit_group;" ::: "memory");
    load_chunk(2);
    asm volatile("cp.async.commit_group;" ::: "memory");

    for (int kc = 0; kc < nch; kc++) {
        asm volatile("cp.async.wait_group 2;" ::: "memory");
        __syncthreads();
        if (kc + 3 < nch) load_chunk(kc + 3);
        asm volatile("cp.async.commit_group;" ::: "memory");

        const uint32_t sb = tiles_u32 + (uint32_t)(kc & 3) * STAGE_B;
#pragma unroll
        for (int s16 = 0; s16 < 2; s16++) {
            const uint32_t ko = (uint32_t)(s16 * 32);
            uint32_t a0[4], a1[4];
            ldsm4(a0, sb + aOff + ko);
            ldsm4(a1, sb + aOff + 16 * 80 + ko);
#pragma unroll
            for (int nt2 = 0; nt2 < 4; nt2++) {
                uint32_t bb[4];
                ldsm4(bb, sb + bOff + (uint32_t)(nt2 * 16 * 80) + ko);
                mma16816(acc[0][nt2 * 2],     a0, bb[0], bb[2]);
                mma16816(acc[0][nt2 * 2 + 1], a0, bb[1], bb[3]);
                mma16816(acc[1][nt2 * 2],     a1, bb[0], bb[2]);
                mma16816(acc[1][nt2 * 2 + 1], a1, bb[1], bb[3]);
            }
        }
    }

    // ----- epilogue -----
    if (EPI == 5) {
        float* hb = (float*)Cv;
#pragma unroll
        for (int mt = 0; mt < 2; mt++) {
            const int b0r = m0 + wm * 32 + mt * 16 + g;
            const int b1r = b0r + 8;
#pragma unroll
            for (int nt = 0; nt < 8; nt++) {
                float i0 = acc[mt][nt][0], f0 = acc[mt][nt][1];
                float i1 = acc[mt][nt][2], f1 = acc[mt][nt][3];
                float o0 = __shfl_xor_sync(~0u, i0, 1);
                float g0 = __shfl_xor_sync(~0u, f0, 1);
                float o1 = __shfl_xor_sync(~0u, i1, 1);
                float g1 = __shfl_xor_sync(~0u, f1, 1);
                if ((t & 1) == 0) {
                    const int c0 = n0 + wn * 64 + nt * 8 + 2 * t;
                    const int j = c0 >> 2;
                    if (j < HH) {
                        size_t i00 = ((size_t)b0r * NU + z) * HH + j;
                        size_t i10 = ((size_t)b1r * NU + z) * HH + j;
                        size_t h00 = ((size_t)z * BB + b0r) * KP_H + j;
                        size_t h10 = ((size_t)z * BB + b1r) * KP_H + j;
                        float mk0 = S[b0r * NU + z], mk1 = S[b1r * NU + z];
                        float cp0 = E1[i00], cp1 = E1[i10];
                        float c0v = cp0 * sigf(f0) + sigf(i0) * tanhf(g0);
                        float c1v = cp1 * sigf(f1) + sigf(i1) * tanhf(g1);
                        float h0v = sigf(o0) * tanhf(c0v);
                        float h1v = sigf(o1) * tanhf(c1v);
                        hb[i00] = h0v;  hb[i10] = h1v;
                        X2[i00] = (mk0 > 0.5f) ? c0v : cp0;
                        X2[i10] = (mk1 > 0.5f) ? c1v : cp1;
                        X3[h00] = __float2half_rn(h0v);
                        X3[h10] = __float2half_rn(h1v);
                    }
                }
            }
        }
        return;
    }

    if (EPI == 6) {
        float* out = (float*)Cv;
#pragma unroll
        for (int mt = 0; mt < 2; mt++) {
            const int r0 = m0 + wm * 32 + mt * 16 + g;
            const int r1 = r0 + 8;
            const bool v0 = r0 < cntz, v1 = r1 < cntz;
            const int b0 = v0 ? IB[z * BB + r0] : 0;
            const int b1 = v1 ? IB[z * BB + r1] : 0;
            const size_t base0 = ((size_t)b0 * NU + z) * HH;
            const size_t base1 = ((size_t)b1 * NU + z) * HH;
#pragma unroll
            for (int nt = 0; nt < 8; nt++) {
                const int n = n0 + wn * 64 + nt * 8 + 2 * t;
                if (n < Nreal) {
                    if (v0) {
                        float2 o = *(const float2*)(E1 + base0 + n);
                        float2 v = make_float2(acc[mt][nt][0] + o.x, acc[mt][nt][1] + o.y);
                        *(float2*)(out + base0 + n) = v;
                    }
                    if (v1) {
                        float2 o = *(const float2*)(E1 + base1 + n);
                        float2 v = make_float2(acc[mt][nt][2] + o.x, acc[mt][nt][3] + o.y);
                        *(float2*)(out + base1 + n) = v;
                    }
                }
            }
        }
        return;
    }

    // EPI 4: fp16 store
#pragma unroll
    for (int mt = 0; mt < 2; mt++) {
        const int r0 = m0 + wm * 32 + mt * 16 + g;
        const int r1 = r0 + 8;
        __half* h0row = (__half*)Cv + (size_t)r0 * ldc + (size_t)z * sC;
        __half* h1row = (__half*)Cv + (size_t)r1 * ldc + (size_t)z * sC;
#pragma unroll
        for (int nt = 0; nt < 8; nt++) {
            const int n = n0 + wn * 64 + nt * 8 + 2 * t;
            if (n < Nreal) {
                *(__half2*)(h0row + n) = __floats2half2_rn(acc[mt][nt][0], acc[mt][nt][1]);
                *(__half2*)(h1row + n) = __floats2half2_rn(acc[mt][nt][2], acc[mt][nt][3]);
            }
        }
    }
}

// ------------------------- unified xk + qry SIMT GEMM (fp32 mask path) -------------------------
// z<6: qry[:,z,:] = hs[:,z,:] @ Wq[z];  z==6: xk = x @ Wk.  128x64 tile, 8x4/thread.
__global__ void __launch_bounds__(256)
xkqry_simt(const float* __restrict__ x, const float* __restrict__ hs,
           const float* __restrict__ Wk, const float* __restrict__ Wq,
           float* __restrict__ xk, float* __restrict__ qry)
{
    __shared__ __align__(16) float As[8][128];
    __shared__ __align__(16) float Bs[8][64];
    const int z = blockIdx.z;
    const float* A; int lda; const float* W; float* C; int ldc;
    if (z < NU) {
        A = hs + z * HH; lda = NU * HH;
        W = Wq + (size_t)z * HH * KD;
        C = qry + z * KD; ldc = NU * KD;
    } else {
        A = x; lda = IND; W = Wk; C = xk; ldc = KD;
    }
    const int tid = threadIdx.x;
    const int tx = tid & 15, ty = tid >> 4;      // 16 x 16
    const int m0 = blockIdx.y * 128;
    float acc[8][4];
#pragma unroll
    for (int i = 0; i < 8; i++)
#pragma unroll
        for (int j = 0; j < 4; j++) acc[i][j] = 0.f;
    const int ar = tid >> 1, ac = (tid & 1) * 4;     // 128 rows x 8 cols
    const int wr = tid >> 4, wc = (tid & 15) * 4;    // 16 rows x 64 cols (use wr<8)
    for (int k0 = 0; k0 < 600; k0 += 8) {
        __syncthreads();
        {
            float4 v = *(const float4*)(A + (size_t)(m0 + ar) * lda + k0 + ac);
            As[ac][ar] = v.x; As[ac + 1][ar] = v.y; As[ac + 2][ar] = v.z; As[ac + 3][ar] = v.w;
        }
        if (wr < 8) {
            float4 v = *(const float4*)(W + (size_t)(k0 + wr) * KD + wc);
            *(float4*)&Bs[wr][wc] = v;
        }
        __syncthreads();
#pragma unroll
        for (int kk = 0; kk < 8; kk++) {
            float af[8], bf[4];
            *(float4*)&af[0] = *(const float4*)&As[kk][ty * 8];
            *(float4*)&af[4] = *(const float4*)&As[kk][ty * 8 + 4];
            *(float4*)bf = *(const float4*)&Bs[kk][tx * 4];
#pragma unroll
            for (int i = 0; i < 8; i++)
#pragma unroll
                for (int j = 0; j < 4; j++) acc[i][j] = fmaf(af[i], bf[j], acc[i][j]);
        }
    }
#pragma unroll
    for (int i = 0; i < 8; i++) {
        float4 v;
        v.x = acc[i][0]; v.y = acc[i][1]; v.z = acc[i][2]; v.w = acc[i][3];
        *(float4*)(C + (size_t)(m0 + ty * 8 + i) * ldc + tx * 4) = v;
    }
}

// ------------------- merged weight transpose (all segments, one launch) -------------------
__global__ void __launch_bounds__(256)
wtrans_all(const float* __restrict__ Wi2h, const float* __restrict__ Wh2h,
           const float* __restrict__ Wcv, const float* __restrict__ Wco,
           const float* __restrict__ Wck, const float* __restrict__ Wcq,
           const float* __restrict__ Wv,
           __half* __restrict__ w12h, __half* __restrict__ wcvq, __half* __restrict__ w4h,
           __half* __restrict__ wv16)
{
    __shared__ float tt[64][33];
    int L = blockIdx.x;
    const float* W; __half* Oh;
    int Kreal, Nreal, Kp, Np, koff, perm, klim, gx, gy;
    if (L < 3150)       { W = Wi2h; Oh = w12h; Kreal = 400;  Nreal = 2400; Kp = KP_PRE; Np = NP_BIG; koff = 0;      perm = 1; klim = KOFF_H; gx = 7;  gy = 75; }
    else if (L < 7650)  { L -= 3150;  W = Wh2h; Oh = w12h; Kreal = 600;  Nreal = 2400; Kp = KP_PRE; Np = NP_BIG; koff = KOFF_H; perm = 1; klim = 608;  gx = 10; gy = 75; }
    else if (L < 12150) { L -= 7650;  W = Wcv;  Oh = wcvq; Kreal = 600;  Nreal = 2400; Kp = KP_H;   Np = NP_CVQ; koff = 0;      perm = 0; klim = 608;  gx = 10; gy = 75; }
    else if (L < 16482) { L -= 12150; W = Wco;  Oh = w4h;  Kreal = 2400; Nreal = 600;  Kp = KP_CTX; Np = NP_H;   koff = 0;      perm = 0; klim = 2400; gx = 38; gy = 19; }
    else if (L < 16722) { L -= 16482; W = Wck;  Oh = wcvq + (size_t)CK_OFF * KP_H; Kreal = 600; Nreal = 128; Kp = KP_H; Np = NP_CVQ; koff = 0; perm = 0; klim = 608; gx = 10; gy = 4; }
    else if (L < 16962) { L -= 16722; W = Wcq;  Oh = wcvq + (size_t)CQ_OFF * KP_H; Kreal = 600; Nreal = 128; Kp = KP_H; Np = NP_CVQ; koff = 0; perm = 0; klim = 608; gx = 10; gy = 4; }
    else                { L -= 16962; W = Wv;   Oh = wv16; Kreal = 600;  Nreal = 400;  Kp = KP_X;   Np = NP_V;   koff = 0;      perm = 0; klim = 608;  gx = 10; gy = 13; }
    const int seg = gx * gy;
    const int u = L / seg, rem = L % seg;
    const int kb = (rem % gx) * 64, nb = (rem / gx) * 32;
    const float* Wu = W + (size_t)u * Kreal * Nreal;
    const int tx = threadIdx.x & 31, ty = threadIdx.x >> 5;  // 32 x 8
#pragma unroll
    for (int yy = ty; yy < 64; yy += 8) {
        int k = kb + yy, n = nb + tx;
        tt[yy][tx] = (k < Kreal && n < Nreal) ? Wu[(size_t)k * Nreal + n] : 0.f;
    }
    __syncthreads();
    __half* OhU = Oh + (size_t)u * Np * Kp + (size_t)koff;
#pragma unroll
    for (int yy = ty; yy < 32; yy += 8) {
        int n = nb + yy;
        int k = kb + 2 * tx;
        if (k + 1 < klim) {
            int pn = perm ? ((n % 600) * 4 + n / 600) : n;
            __half2 v = __floats2half2_rn(tt[2 * tx][yy], tt[2 * tx + 1][yy]);
            *(__half2*)(OhU + (size_t)pn * Kp + k) = v;
        }
    }
}

// ------------------- x -> fp16 padded -------------------
__global__ void conv_x(const float* __restrict__ x, __half* __restrict__ o)
{
    int idx = blockIdx.x * blockDim.x + threadIdx.x;
    if (idx >= BB * KP_X) return;
    int k = idx % KP_X, b = idx / KP_X;
    o[idx] = __float2half_rn(k < IND ? x[(size_t)b * IND + k] : 0.f);
}

// ------------------- A_pre = [scale*xv | hs] fp16 (half2 vectorized) -------------------
__global__ void conv_pre(const __half* __restrict__ xv, const float* __restrict__ hs,
                         const float* __restrict__ scale, __half* __restrict__ oh)
{
    size_t idx = (size_t)blockIdx.x * blockDim.x + threadIdx.x;
    const size_t HALF_K = KP_PRE / 2;
    if (idx >= (size_t)NU * BB * HALF_K) return;
    int k = (int)(idx % HALF_K) * 2;
    int b = (int)((idx / HALF_K) % BB);
    int u = (int)(idx / (HALF_K * BB));
    float v0 = 0.f, v1 = 0.f;
    if (k < VDD) {
        float sc = scale[b * NU + u];
        __half2 xp = *(const __half2*)(xv + (size_t)b * VDD + k);
        float2 xf = __half22float2(xp);
        v0 = sc * xf.x; v1 = sc * xf.y;
    } else if (k >= KOFF_H && k < KOFF_H + HH) {
        float2 hf = *(const float2*)(hs + (size_t)b * (NU * HH) + u * HH + (k - KOFF_H));
        v0 = hf.x; v1 = hf.y;
    }
    *(__half2*)(oh + idx * 2) = __floats2half2_rn(v0, v1);
}

// ------------------- zero counters -------------------
__global__ void zero_cnt(int* cnt)
{
    if (threadIdx.x < NU) cnt[threadIdx.x] = 0;
}

// ------------------- score + top-k + compaction lists -------------------
__global__ void score_topk(const float* __restrict__ qry, const float* __restrict__ xk,
                           float* __restrict__ scale, float* __restrict__ mask,
                           int* __restrict__ cnt, int* __restrict__ posmap,
                           int* __restrict__ blist)
{
    int gw = (blockIdx.x * blockDim.x + threadIdx.x) >> 5;
    int lane = threadIdx.x & 31;
    if (gw >= BB) return;
    int b = gw;
    float xk0 = xk[b * 64 + lane], xk1 = xk[b * 64 + 32 + lane];
    float s[NU];
#pragma unroll
    for (int u = 0; u < NU; u++) {
        const float* q = qry + b * (NU * 64) + u * 64;
        float v = q[lane] * xk0 + q[32 + lane] * xk1;
#pragma unroll
        for (int o = 16; o; o >>= 1) v += __shfl_xor_sync(~0u, v, o);
        s[u] = v * 0.125f;
    }
    if (lane == 0) {
#pragma unroll
        for (int u = 0; u < NU; u++) {
            int c = 0;
#pragma unroll
            for (int v = 0; v < NU; v++)
                if (s[v] > s[u] || (s[v] == s[u] && v < u)) c++;
            float m = (c < 4) ? 1.f : 0.f;
            mask[b * NU + u] = m;
            scale[b * NU + u] = m / (1.f + expf(-s[u]));
            if (m > 0.5f) {
                int p = atomicAdd(&cnt[u], 1);
                blist[u * BB + p] = b;
                posmap[b * NU + u] = p;
            } else {
                posmap[b * NU + u] = -1;
            }
        }
    }
}

// ------------------- comm attention + inactive hs copy -------------------
__global__ void __launch_bounds__(256)
comm_attn(const __half* __restrict__ cvq, const float* __restrict__ mask,
          const int* __restrict__ posmap, const float* __restrict__ hs,
          float* __restrict__ hs_out, __half* __restrict__ cxc)
{
    int b = blockIdx.x;
    __shared__ float s_ck[NU * 128], s_cq[NU * 128];
    __shared__ float s_sc[NU][4][NU];
    __shared__ float s_pr[NU][4][8];
    __shared__ int s_pos[NU];
    int t = threadIdx.x;
    const __half* base = cvq + (size_t)b * (NU * NP_CVQ);
    for (int i = t; i < NU * 128; i += 256) {
        int m = i >> 7, c = i & 127;
        s_ck[i] = __half2float(base[m * NP_CVQ + CK_OFF + c]);
        s_cq[i] = __half2float(base[m * NP_CVQ + CQ_OFF + c]);
    }
    if (t < NU) s_pos[t] = posmap[b * NU + t];
    __syncthreads();

    int w = t >> 5, lane = t & 31;
    for (int p = w; p < NU * 4 * NU; p += 8) {
        int uq = p / 24, rem = p % 24, hh = rem / 6, m = rem % 6;
        float v = s_cq[uq * 128 + hh * 32 + lane] * s_ck[m * 128 + hh * 32 + lane];
#pragma unroll
        for (int o = 16; o; o >>= 1) v += __shfl_xor_sync(~0u, v, o);
        if (lane == 0) s_sc[uq][hh][m] = v * 0.17677669529663687f;
    }
    __syncthreads();

    if (t < NU * 4) {
        int uq = t >> 2, hh = t & 3;
        float mx = -1e30f;
#pragma unroll
        for (int m = 0; m < NU; m++) mx = fmaxf(mx, s_sc[uq][hh][m]);
        float e[NU], sum = 0.f;
#pragma unroll
        for (int m = 0; m < NU; m++) { e[m] = expf(s_sc[uq][hh][m] - mx); sum += e[m]; }
        float inv = mask[b * NU + uq] / sum;
#pragma unroll
        for (int m = 0; m < NU; m++) s_pr[uq][hh][m] = e[m] * inv;
    }
    __syncthreads();

    for (int i = t; i < 2400; i += 256) {
        int hh = i / 600;
        float c[NU];
#pragma unroll
        for (int m = 0; m < NU; m++) c[m] = __half2float(base[m * NP_CVQ + i]);
#pragma unroll
        for (int uq = 0; uq < NU; uq++) {
            int pos = s_pos[uq];
            if (pos >= 0) {
                float a = 0.f;
#pragma unroll
                for (int m = 0; m < NU; m++) a += s_pr[uq][hh][m] * c[m];
                cxc[((size_t)uq * BB + pos) * KP_CTX + i] = __float2half_rn(a);
            }
        }
    }

    // inactive rows: hs_out = hs
#pragma unroll
    for (int uq = 0; uq < NU; uq++) {
        if (s_pos[uq] < 0) {
            const float* src = hs + ((size_t)b * NU + uq) * HH;
            float* dst = hs_out + ((size_t)b * NU + uq) * HH;
            for (int i = t; i < HH; i += 256) dst[i] = src[i];
        }
    }
}

// ------------------------- launch -------------------------
extern "C" void kernel_launch(void* const* d_in, const int* in_sizes, int n_in,
                              void* d_out, int out_size)
{
    const float* x    = (const float*)d_in[0];
    const float* hs   = (const float*)d_in[1];
    const float* cs   = (const float*)d_in[2];
    const float* Wk   = (const float*)d_in[3];
    const float* Wv   = (const float*)d_in[4];
    const float* Wq   = (const float*)d_in[5];
    const float* Wi2h = (const float*)d_in[6];
    const float* Wh2h = (const float*)d_in[7];
    const float* Wck  = (const float*)d_in[8];
    const float* Wcq  = (const float*)d_in[9];
    const float* Wcv  = (const float*)d_in[10];
    const float* Wco  = (const float*)d_in[11];

    float* hs_out = (float*)d_out;
    float* cs_out = hs_out + (size_t)BB * NU * HH;

    float *xk, *qry, *scale, *mask, *hb;
    int *cnt, *posmap, *blist;
    __half *xvh, *cvq, *aph, *hbh, *cxc, *x16, *w12h, *wcvq, *w4h, *wv16;
    cudaGetSymbolAddress((void**)&xk, g_xk);
    cudaGetSymbolAddress((void**)&qry, g_qry);     cudaGetSymbolAddress((void**)&scale, g_scale);
    cudaGetSymbolAddress((void**)&mask, g_mask);   cudaGetSymbolAddress((void**)&hb, g_hb);
    cudaGetSymbolAddress((void**)&cnt, g_cnt);
    cudaGetSymbolAddress((void**)&posmap, g_posmap);
    cudaGetSymbolAddress((void**)&blist, g_blist);
    cudaGetSymbolAddress((void**)&xvh, g_xvh);
    cudaGetSymbolAddress((void**)&cvq, g_cvq);
    cudaGetSymbolAddress((void**)&aph, g_aph);
    cudaGetSymbolAddress((void**)&hbh, g_hbh);
    cudaGetSymbolAddress((void**)&cxc, g_cxc);
    cudaGetSymbolAddress((void**)&x16, g_x16);
    cudaGetSymbolAddress((void**)&w12h, g_w12h);
    cudaGetSymbolAddress((void**)&wcvq, g_wcvq);
    cudaGetSymbolAddress((void**)&w4h, g_w4h);
    cudaGetSymbolAddress((void**)&wv16, g_wv16);

    cudaFuncSetAttribute(hmma_gemm<4>, cudaFuncAttributeMaxDynamicSharedMemorySize, SMEM_DYN);
    cudaFuncSetAttribute(hmma_gemm<5>, cudaFuncAttributeMaxDynamicSharedMemorySize, SMEM_DYN);
    cudaFuncSetAttribute(hmma_gemm<6>, cudaFuncAttributeMaxDynamicSharedMemorySize, SMEM_DYN);

    wtrans_all<<<17092, 256>>>(Wi2h, Wh2h, Wcv, Wco, Wck, Wcq, Wv,
                               w12h, wcvq, w4h, wv16);
    conv_x<<<(BB * KP_X + 255) / 256, 256>>>(x, x16);
    zero_cnt<<<1, 32>>>(cnt);

    // fp32 mask path: xk + qry in one launch (128x64 tiles)
    xkqry_simt<<<dim3(1, 32, 7), 256>>>(x, hs, Wk, Wq, xk, qry);

    // xv = x @ Wv  (fp16 out)
    hmma_gemm<4><<<dim3(4, 32, 1), 256, SMEM_DYN>>>(
        x16, 0LL, KP_X, wv16, 0LL, xvh, VDD, 0, VDD,
        nullptr, nullptr, nullptr, nullptr, nullptr, nullptr);

    score_topk<<<(BB * 32 + 255) / 256, 256>>>(qry, xk, scale, mask, cnt, posmap, blist);
    conv_pre<<<(int)(((size_t)NU * BB * (KP_PRE / 2) + 255) / 256), 256>>>(xvh, hs, scale, aph);

    // preact GEMM + fused LSTM epilogue -> hb, hbh, cs_out
    hmma_gemm<5><<<dim3(19, 32, NU), 256, SMEM_DYN>>>(
        aph, (long long)BB * KP_PRE, KP_PRE, w12h, (long long)NP_BIG * KP_PRE,
        hb, 0, 0, 2400, mask, cs, cs_out, hbh, nullptr, nullptr);

    // cv | ck | cq combined (N=2688, fp16 out)
    hmma_gemm<4><<<dim3(21, 32, NU), 256, SMEM_DYN>>>(
        hbh, (long long)BB * KP_H, KP_H, wcvq, (long long)NP_CVQ * KP_H,
        cvq, NU * NP_CVQ, NP_CVQ, NP_CVQ, nullptr, nullptr, nullptr, nullptr, nullptr, nullptr);

    // comm attention (+ inactive hs copy)
    comm_attn<<<BB, 256>>>(cvq, mask, posmap, hs, hs_out, cxc);

    // hs_out (active rows only) = ctx_compact @ Wco + hb, scattered by blist
    hmma_gemm<6><<<dim3(5, 32, NU), 256, SMEM_DYN>>>(
        cxc, (long long)BB * KP_CTX, KP_CTX, w4h, (long long)NP_H * KP_CTX,
        hs_out, 0, 0, HH, nullptr, hb, nullptr, nullptr, blist, cnt);

    (void)in_sizes; (void)n_in; (void)out_size;
}

// round 11
// speedup vs baseline: 5.6586x; 1.0055x over previous
#include <cuda_runtime.h>
#include <cuda_fp16.h>
#include <math.h>
#include <stdint.h>

#define BB 4096
#define NU 6
#define IND 600
#define HH 600
#define VDD 400
#define KD 64
#define KP_PRE 1024   // 416 (xv) + 608 (hs)
#define KOFF_H 416
#define KP_H   608
#define KP_X   608
#define KP_CTX 2400
#define NP_BIG 2432
#define NP_H   640
#define NP_CVQ 2688   // 2400 cv | 32 pad | 128 ck | 128 cq
#define CK_OFF 2432
#define CQ_OFF 2560
#define NP_V   512

// ------------------------- device scratch -------------------------
__device__ __align__(16) float g_xk[BB * KD];
__device__ __align__(16) float g_qry[BB * NU * KD];
__device__ __align__(16) float g_scale[BB * NU];
__device__ __align__(16) float g_mask[BB * NU];
__device__ __align__(16) float g_hb[(size_t)BB * NU * HH];
__device__ int g_cnt[NU];
__device__ int g_posmap[BB * NU];
__device__ int g_blist[NU * BB];

__device__ __align__(16) __half g_xvh[(size_t)BB * VDD];
__device__ __align__(16) __half g_cvq[(size_t)BB * NU * NP_CVQ];
__device__ __align__(16) __half g_aph[(size_t)NU * BB * KP_PRE];
__device__ __align__(16) __half g_hbh[(size_t)NU * BB * KP_H];
__device__ __align__(16) __half g_cxc[(size_t)NU * BB * KP_CTX];
__device__ __align__(16) __half g_x16[(size_t)BB * KP_X];
__device__ __align__(16) __half g_w12h[(size_t)NU * NP_BIG * KP_PRE];
__device__ __align__(16) __half g_wcvq[(size_t)NU * NP_CVQ * KP_H];
__device__ __align__(16) __half g_w4h[(size_t)NU * NP_H * KP_CTX];
__device__ __align__(16) __half g_wv16[(size_t)NP_V * KP_X];

// ------------------------- helpers -------------------------
__device__ __forceinline__ uint32_t smem_u32(const void* p) {
    uint32_t a;
    asm("{ .reg .u64 t; cvta.to.shared.u64 t, %1; cvt.u32.u64 %0, t; }" : "=r"(a) : "l"(p));
    return a;
}
__device__ __forceinline__ void cp16(uint32_t dst, const void* src) {
    asm volatile("cp.async.cg.shared.global [%0], [%1], 16;\n" :: "r"(dst), "l"(src));
}
__device__ __forceinline__ void mma16816(float* c, const uint32_t* a, uint32_t b0, uint32_t b1) {
    asm volatile(
        "mma.sync.aligned.m16n8k16.row.col.f32.f16.f16.f32 "
        "{%0,%1,%2,%3}, {%4,%5,%6,%7}, {%8,%9}, {%0,%1,%2,%3};"
        : "+f"(c[0]), "+f"(c[1]), "+f"(c[2]), "+f"(c[3])
        : "r"(a[0]), "r"(a[1]), "r"(a[2]), "r"(a[3]), "r"(b0), "r"(b1));
}
__device__ __forceinline__ void ldsm4(uint32_t* r, uint32_t addr) {
    asm volatile("ldmatrix.sync.aligned.m8n8.x4.shared.b16 {%0,%1,%2,%3}, [%4];"
                 : "=r"(r[0]), "=r"(r[1]), "=r"(r[2]), "=r"(r[3]) : "r"(addr));
}
__device__ __forceinline__ float sigf(float x) { return 1.f / (1.f + expf(-x)); }

#define TILE_B   10240
#define STAGE_B  20480
#define NSTAGE   4
#define SMEM_DYN (NSTAGE * STAGE_B + 16)

// ------------------------- HMMA GEMM (fp16, ldmatrix, 4-stage) -------------------------
// EPI 4: fp16 store.
// EPI 5: fused LSTM (gate-interleaved cols): Cv=hb(f32), S=mask, E1=cs, X2=cs_out, X3=hbh.
// EPI 6: compact-row scatter: Cv=hs_out, E1=hb, IB=blist, CT=cnt; C[b,z] = acc + hb[b,z].
template <int EPI>
__global__ void __launch_bounds__(256, 2)
hmma_gemm(const __half* __restrict__ A, long long sA, int Kpad,
          const __half* __restrict__ B, long long sB,
          void* __restrict__ Cv, int ldc, int sC, int Nreal,
          const float* __restrict__ S,
          const float* __restrict__ E1,
          float* __restrict__ X2, __half* __restrict__ X3,
          const int* __restrict__ IB, const int* __restrict__ CT)
{
    extern __shared__ __align__(16) char dsm[];
    const uint32_t tiles_u32 = smem_u32(dsm);

    const int tid = threadIdx.x;
    const int wid = tid >> 5, lane = tid & 31;
    const int wm = wid >> 1, wn = wid & 1;        // 4 x 2 warps, 32x64 each
    const int g = lane >> 2, t = lane & 3;
    const int lane16 = lane & 15, lanehi = lane >> 4;

    const int z = blockIdx.z, m0 = blockIdx.y * 128, n0 = blockIdx.x * 128;
    int cntz = 0;
    if (EPI == 6) {
        cntz = CT[z];
        if (m0 >= cntz) return;
    }
    const __half* Az = A + (size_t)z * sA + (size_t)m0 * Kpad;
    const __half* Bz = B + (size_t)z * sB + (size_t)n0 * Kpad;

    const int nch = Kpad >> 5;   // BK = 32

    const int idx0 = tid * 2, idx1 = tid * 2 + 1;
    const int r_0 = idx0 >> 2, c_0 = idx0 & 3;
    const int r_1 = idx1 >> 2, c_1 = idx1 & 3;

    auto load_chunk = [&](int kc) {
        uint32_t sb = tiles_u32 + (uint32_t)(kc & 3) * STAGE_B;
        int k0 = kc << 5;
        cp16(sb + r_0 * 80 + c_0 * 16, Az + (size_t)r_0 * Kpad + k0 + c_0 * 8);
        cp16(sb + r_1 * 80 + c_1 * 16, Az + (size_t)r_1 * Kpad + k0 + c_1 * 8);
        cp16(sb + TILE_B + r_0 * 80 + c_0 * 16, Bz + (size_t)r_0 * Kpad + k0 + c_0 * 8);
        cp16(sb + TILE_B + r_1 * 80 + c_1 * 16, Bz + (size_t)r_1 * Kpad + k0 + c_1 * 8);
    };

    float acc[2][8][4];
#pragma unroll
    for (int a = 0; a < 2; a++)
#pragma unroll
        for (int b = 0; b < 8; b++)
#pragma unroll
            for (int c = 0; c < 4; c++) acc[a][b][c] = 0.f;

    const uint32_t aOff = (uint32_t)((wm * 32 + lane16) * 80 + lanehi * 16);
    const uint32_t bOff = (uint32_t)(TILE_B + (wn * 64 + lane16) * 80 + lanehi * 16);

    load_chunk(0);
    asm volatile("cp.async.commit_group;" ::: "memory");
    load_chunk(1);
    asm volatile("cp.async.commit_group;" ::: "memory");
    load_chunk(2);
    asm volatile("cp.async.commit_group;" ::: "memory");

    for (int kc = 0; kc < nch; kc++) {
        asm volatile("cp.async.wait_group 2;" ::: "memory");
        __syncthreads();
        if (kc + 3 < nch) load_chunk(kc + 3);
        asm volatile("cp.async.commit_group;" ::: "memory");

        const uint32_t sb = tiles_u32 + (uint32_t)(kc & 3) * STAGE_B;
#pragma unroll
        for (int s16 = 0; s16 < 2; s16++) {
            const uint32_t ko = (uint32_t)(s16 * 32);
            uint32_t a0[4], a1[4];
            ldsm4(a0, sb + aOff + ko);
            ldsm4(a1, sb + aOff + 16 * 80 + ko);
#pragma unroll
            for (int nt2 = 0; nt2 < 4; nt2++) {
                uint32_t bb[4];
                ldsm4(bb, sb + bOff + (uint32_t)(nt2 * 16 * 80) + ko);
                mma16816(acc[0][nt2 * 2],     a0, bb[0], bb[2]);
                mma16816(acc[0][nt2 * 2 + 1], a0, bb[1], bb[3]);
                mma16816(acc[1][nt2 * 2],     a1, bb[0], bb[2]);
                mma16816(acc[1][nt2 * 2 + 1], a1, bb[1], bb[3]);
            }
        }
    }

    // ----- epilogue -----
    if (EPI == 5) {
        float* hb = (float*)Cv;
#pragma unroll
        for (int mt = 0; mt < 2; mt++) {
            const int b0r = m0 + wm * 32 + mt * 16 + g;
            const int b1r = b0r + 8;
#pragma unroll
            for (int nt = 0; nt < 8; nt++) {
                float i0 = acc[mt][nt][0], f0 = acc[mt][nt][1];
                float i1 = acc[mt][nt][2], f1 = acc[mt][nt][3];
                float o0 = __shfl_xor_sync(~0u, i0, 1);
                float g0 = __shfl_xor_sync(~0u, f0, 1);
                float o1 = __shfl_xor_sync(~0u, i1, 1);
                float g1 = __shfl_xor_sync(~0u, f1, 1);
                if ((t & 1) == 0) {
                    const int c0 = n0 + wn * 64 + nt * 8 + 2 * t;
                    const int j = c0 >> 2;
                    if (j < HH) {
                        size_t i00 = ((size_t)b0r * NU + z) * HH + j;
                        size_t i10 = ((size_t)b1r * NU + z) * HH + j;
                        size_t h00 = ((size_t)z * BB + b0r) * KP_H + j;
                        size_t h10 = ((size_t)z * BB + b1r) * KP_H + j;
                        float mk0 = S[b0r * NU + z], mk1 = S[b1r * NU + z];
                        float cp0 = E1[i00], cp1 = E1[i10];
                        float c0v = cp0 * sigf(f0) + sigf(i0) * tanhf(g0);
                        float c1v = cp1 * sigf(f1) + sigf(i1) * tanhf(g1);
                        float h0v = sigf(o0) * tanhf(c0v);
                        float h1v = sigf(o1) * tanhf(c1v);
                        hb[i00] = h0v;  hb[i10] = h1v;
                        X2[i00] = (mk0 > 0.5f) ? c0v : cp0;
                        X2[i10] = (mk1 > 0.5f) ? c1v : cp1;
                        X3[h00] = __float2half_rn(h0v);
                        X3[h10] = __float2half_rn(h1v);
                    }
                }
            }
        }
        return;
    }

    if (EPI == 6) {
        float* out = (float*)Cv;
#pragma unroll
        for (int mt = 0; mt < 2; mt++) {
            const int r0 = m0 + wm * 32 + mt * 16 + g;
            const int r1 = r0 + 8;
            const bool v0 = r0 < cntz, v1 = r1 < cntz;
            const int b0 = v0 ? IB[z * BB + r0] : 0;
            const int b1 = v1 ? IB[z * BB + r1] : 0;
            const size_t base0 = ((size_t)b0 * NU + z) * HH;
            const size_t base1 = ((size_t)b1 * NU + z) * HH;
#pragma unroll
            for (int nt = 0; nt < 8; nt++) {
                const int n = n0 + wn * 64 + nt * 8 + 2 * t;
                if (n < Nreal) {
                    if (v0) {
                        float2 o = *(const float2*)(E1 + base0 + n);
                        float2 v = make_float2(acc[mt][nt][0] + o.x, acc[mt][nt][1] + o.y);
                        *(float2*)(out + base0 + n) = v;
                    }
                    if (v1) {
                        float2 o = *(const float2*)(E1 + base1 + n);
                        float2 v = make_float2(acc[mt][nt][2] + o.x, acc[mt][nt][3] + o.y);
                        *(float2*)(out + base1 + n) = v;
                    }
                }
            }
        }
        return;
    }

    // EPI 4: fp16 store
#pragma unroll
    for (int mt = 0; mt < 2; mt++) {
        const int r0 = m0 + wm * 32 + mt * 16 + g;
        const int r1 = r0 + 8;
        __half* h0row = (__half*)Cv + (size_t)r0 * ldc + (size_t)z * sC;
        __half* h1row = (__half*)Cv + (size_t)r1 * ldc + (size_t)z * sC;
#pragma unroll
        for (int nt = 0; nt < 8; nt++) {
            const int n = n0 + wn * 64 + nt * 8 + 2 * t;
            if (n < Nreal) {
                *(__half2*)(h0row + n) = __floats2half2_rn(acc[mt][nt][0], acc[mt][nt][1]);
                *(__half2*)(h1row + n) = __floats2half2_rn(acc[mt][nt][2], acc[mt][nt][3]);
            }
        }
    }
}

// ------------------------- unified xk + qry SIMT GEMM (fp32 mask path) -------------------------
// z<6: qry[:,z,:] = hs[:,z,:] @ Wq[z];  z==6: xk = x @ Wk.  64x64 tile, 4x4/thread, grid 448.
__global__ void __launch_bounds__(256)
xkqry_simt(const float* __restrict__ x, const float* __restrict__ hs,
           const float* __restrict__ Wk, const float* __restrict__ Wq,
           float* __restrict__ xk, float* __restrict__ qry)
{
    __shared__ __align__(16) float As[8][64];
    __shared__ __align__(16) float Bs[8][64];
    const int z = blockIdx.z;
    const float* A; int lda; const float* W; float* C; int ldc;
    if (z < NU) {
        A = hs + z * HH; lda = NU * HH;
        W = Wq + (size_t)z * HH * KD;
        C = qry + z * KD; ldc = NU * KD;
    } else {
        A = x; lda = IND; W = Wk; C = xk; ldc = KD;
    }
    const int tid = threadIdx.x;
    const int tx = tid & 15, ty = tid >> 4;
    const int m0 = blockIdx.y * 64;
    float acc[4][4];
#pragma unroll
    for (int i = 0; i < 4; i++)
#pragma unroll
        for (int j = 0; j < 4; j++) acc[i][j] = 0.f;
    const int ar = tid >> 1, ac = (tid & 1) * 4;
    const int wr = tid >> 4, wc = (tid & 15) * 4;
    for (int k0 = 0; k0 < 600; k0 += 8) {
        __syncthreads();
        if (ar < 64) {
            float4 v = *(const float4*)(A + (size_t)(m0 + ar) * lda + k0 + ac);
            As[ac][ar] = v.x; As[ac + 1][ar] = v.y; As[ac + 2][ar] = v.z; As[ac + 3][ar] = v.w;
        }
        if (wr < 8) {
            float4 v = *(const float4*)(W + (size_t)(k0 + wr) * KD + wc);
            *(float4*)&Bs[wr][wc] = v;
        }
        __syncthreads();
#pragma unroll
        for (int kk = 0; kk < 8; kk++) {
            float af[4], bf[4];
            *(float4*)af = *(const float4*)&As[kk][ty * 4];
            *(float4*)bf = *(const float4*)&Bs[kk][tx * 4];
#pragma unroll
            for (int i = 0; i < 4; i++)
#pragma unroll
                for (int j = 0; j < 4; j++) acc[i][j] = fmaf(af[i], bf[j], acc[i][j]);
        }
    }
#pragma unroll
    for (int i = 0; i < 4; i++) {
        float4 v;
        v.x = acc[i][0]; v.y = acc[i][1]; v.z = acc[i][2]; v.w = acc[i][3];
        *(float4*)(C + (size_t)(m0 + ty * 4 + i) * ldc + tx * 4) = v;
    }
}

// ------------------- merged weight transpose (all segments, one launch) -------------------
__global__ void __launch_bounds__(256)
wtrans_all(const float* __restrict__ Wi2h, const float* __restrict__ Wh2h,
           const float* __restrict__ Wcv, const float* __restrict__ Wco,
           const float* __restrict__ Wck, const float* __restrict__ Wcq,
           const float* __restrict__ Wv,
           __half* __restrict__ w12h, __half* __restrict__ wcvq, __half* __restrict__ w4h,
           __half* __restrict__ wv16)
{
    __shared__ float tt[64][33];
    int L = blockIdx.x;
    const float* W; __half* Oh;
    int Kreal, Nreal, Kp, Np, koff, perm, klim, gx, gy;
    if (L < 3150)       { W = Wi2h; Oh = w12h; Kreal = 400;  Nreal = 2400; Kp = KP_PRE; Np = NP_BIG; koff = 0;      perm = 1; klim = KOFF_H; gx = 7;  gy = 75; }
    else if (L < 7650)  { L -= 3150;  W = Wh2h; Oh = w12h; Kreal = 600;  Nreal = 2400; Kp = KP_PRE; Np = NP_BIG; koff = KOFF_H; perm = 1; klim = 608;  gx = 10; gy = 75; }
    else if (L < 12150) { L -= 7650;  W = Wcv;  Oh = wcvq; Kreal = 600;  Nreal = 2400; Kp = KP_H;   Np = NP_CVQ; koff = 0;      perm = 0; klim = 608;  gx = 10; gy = 75; }
    else if (L < 16482) { L -= 12150; W = Wco;  Oh = w4h;  Kreal = 2400; Nreal = 600;  Kp = KP_CTX; Np = NP_H;   koff = 0;      perm = 0; klim = 2400; gx = 38; gy = 19; }
    else if (L < 16722) { L -= 16482; W = Wck;  Oh = wcvq + (size_t)CK_OFF * KP_H; Kreal = 600; Nreal = 128; Kp = KP_H; Np = NP_CVQ; koff = 0; perm = 0; klim = 608; gx = 10; gy = 4; }
    else if (L < 16962) { L -= 16722; W = Wcq;  Oh = wcvq + (size_t)CQ_OFF * KP_H; Kreal = 600; Nreal = 128; Kp = KP_H; Np = NP_CVQ; koff = 0; perm = 0; klim = 608; gx = 10; gy = 4; }
    else                { L -= 16962; W = Wv;   Oh = wv16; Kreal = 600;  Nreal = 400;  Kp = KP_X;   Np = NP_V;   koff = 0;      perm = 0; klim = 608;  gx = 10; gy = 13; }
    const int seg = gx * gy;
    const int u = L / seg, rem = L % seg;
    const int kb = (rem % gx) * 64, nb = (rem / gx) * 32;
    const float* Wu = W + (size_t)u * Kreal * Nreal;
    const int tx = threadIdx.x & 31, ty = threadIdx.x >> 5;  // 32 x 8
#pragma unroll
    for (int yy = ty; yy < 64; yy += 8) {
        int k = kb + yy, n = nb + tx;
        tt[yy][tx] = (k < Kreal && n < Nreal) ? Wu[(size_t)k * Nreal + n] : 0.f;
    }
    __syncthreads();
    __half* OhU = Oh + (size_t)u * Np * Kp + (size_t)koff;
#pragma unroll
    for (int yy = ty; yy < 32; yy += 8) {
        int n = nb + yy;
        int k = kb + 2 * tx;
        if (k + 1 < klim) {
            int pn = perm ? ((n % 600) * 4 + n / 600) : n;
            __half2 v = __floats2half2_rn(tt[2 * tx][yy], tt[2 * tx + 1][yy]);
            *(__half2*)(OhU + (size_t)pn * Kp + k) = v;
        }
    }
}

// ------------------- x -> fp16 padded -------------------
__global__ void conv_x(const float* __restrict__ x, __half* __restrict__ o)
{
    int idx = blockIdx.x * blockDim.x + threadIdx.x;
    if (idx >= BB * KP_X) return;
    int k = idx % KP_X, b = idx / KP_X;
    o[idx] = __float2half_rn(k < IND ? x[(size_t)b * IND + k] : 0.f);
}

// ------------------- A_pre = [scale*xv | hs] fp16 (half2 vectorized) -------------------
__global__ void conv_pre(const __half* __restrict__ xv, const float* __restrict__ hs,
                         const float* __restrict__ scale, __half* __restrict__ oh)
{
    size_t idx = (size_t)blockIdx.x * blockDim.x + threadIdx.x;
    const size_t HALF_K = KP_PRE / 2;
    if (idx >= (size_t)NU * BB * HALF_K) return;
    int k = (int)(idx % HALF_K) * 2;
    int b = (int)((idx / HALF_K) % BB);
    int u = (int)(idx / (HALF_K * BB));
    float v0 = 0.f, v1 = 0.f;
    if (k < VDD) {
        float sc = scale[b * NU + u];
        __half2 xp = *(const __half2*)(xv + (size_t)b * VDD + k);
        float2 xf = __half22float2(xp);
        v0 = sc * xf.x; v1 = sc * xf.y;
    } else if (k >= KOFF_H && k < KOFF_H + HH) {
        float2 hf = *(const float2*)(hs + (size_t)b * (NU * HH) + u * HH + (k - KOFF_H));
        v0 = hf.x; v1 = hf.y;
    }
    *(__half2*)(oh + idx * 2) = __floats2half2_rn(v0, v1);
}

// ------------------- zero counters -------------------
__global__ void zero_cnt(int* cnt)
{
    if (threadIdx.x < NU) cnt[threadIdx.x] = 0;
}

// ------------------- score + top-k + compaction lists -------------------
__global__ void score_topk(const float* __restrict__ qry, const float* __restrict__ xk,
                           float* __restrict__ scale, float* __restrict__ mask,
                           int* __restrict__ cnt, int* __restrict__ posmap,
                           int* __restrict__ blist)
{
    int gw = (blockIdx.x * blockDim.x + threadIdx.x) >> 5;
    int lane = threadIdx.x & 31;
    if (gw >= BB) return;
    int b = gw;
    float xk0 = xk[b * 64 + lane], xk1 = xk[b * 64 + 32 + lane];
    float s[NU];
#pragma unroll
    for (int u = 0; u < NU; u++) {
        const float* q = qry + b * (NU * 64) + u * 64;
        float v = q[lane] * xk0 + q[32 + lane] * xk1;
#pragma unroll
        for (int o = 16; o; o >>= 1) v += __shfl_xor_sync(~0u, v, o);
        s[u] = v * 0.125f;
    }
    if (lane == 0) {
#pragma unroll
        for (int u = 0; u < NU; u++) {
            int c = 0;
#pragma unroll
            for (int v = 0; v < NU; v++)
                if (s[v] > s[u] || (s[v] == s[u] && v < u)) c++;
            float m = (c < 4) ? 1.f : 0.f;
            mask[b * NU + u] = m;
            scale[b * NU + u] = m / (1.f + expf(-s[u]));
            if (m > 0.5f) {
                int p = atomicAdd(&cnt[u], 1);
                blist[u * BB + p] = b;
                posmap[b * NU + u] = p;
            } else {
                posmap[b * NU + u] = -1;
            }
        }
    }
}

// ------------------- comm attention + inactive hs copy -------------------
__global__ void __launch_bounds__(256)
comm_attn(const __half* __restrict__ cvq, const float* __restrict__ mask,
          const int* __restrict__ posmap, const float* __restrict__ hs,
          float* __restrict__ hs_out, __half* __restrict__ cxc)
{
    int b = blockIdx.x;
    __shared__ float s_ck[NU * 128], s_cq[NU * 128];
    __shared__ float s_sc[NU][4][NU];
    __shared__ float s_pr[NU][4][8];
    __shared__ int s_pos[NU];
    int t = threadIdx.x;
    const __half* base = cvq + (size_t)b * (NU * NP_CVQ);
    for (int i = t; i < NU * 128; i += 256) {
        int m = i >> 7, c = i & 127;
        s_ck[i] = __half2float(base[m * NP_CVQ + CK_OFF + c]);
        s_cq[i] = __half2float(base[m * NP_CVQ + CQ_OFF + c]);
    }
    if (t < NU) s_pos[t] = posmap[b * NU + t];
    __syncthreads();

    int w = t >> 5, lane = t & 31;
    for (int p = w; p < NU * 4 * NU; p += 8) {
        int uq = p / 24, rem = p % 24, hh = rem / 6, m = rem % 6;
        float v = s_cq[uq * 128 + hh * 32 + lane] * s_ck[m * 128 + hh * 32 + lane];
#pragma unroll
        for (int o = 16; o; o >>= 1) v += __shfl_xor_sync(~0u, v, o);
        if (lane == 0) s_sc[uq][hh][m] = v * 0.17677669529663687f;
    }
    __syncthreads();

    if (t < NU * 4) {
        int uq = t >> 2, hh = t & 3;
        float mx = -1e30f;
#pragma unroll
        for (int m = 0; m < NU; m++) mx = fmaxf(mx, s_sc[uq][hh][m]);
        float e[NU], sum = 0.f;
#pragma unroll
        for (int m = 0; m < NU; m++) { e[m] = expf(s_sc[uq][hh][m] - mx); sum += e[m]; }
        float inv = mask[b * NU + uq] / sum;
#pragma unroll
        for (int m = 0; m < NU; m++) s_pr[uq][hh][m] = e[m] * inv;
    }
    __syncthreads();

    for (int i = t; i < 2400; i += 256) {
        int hh = i / 600;
        float c[NU];
#pragma unroll
        for (int m = 0; m < NU; m++) c[m] = __half2float(base[m * NP_CVQ + i]);
#pragma unroll
        for (int uq = 0; uq < NU; uq++) {
            int pos = s_pos[uq];
            if (pos >= 0) {
                float a = 0.f;
#pragma unroll
                for (int m = 0; m < NU; m++) a += s_pr[uq][hh][m] * c[m];
                cxc[((size_t)uq * BB + pos) * KP_CTX + i] = __float2half_rn(a);
            }
        }
    }

    // inactive rows: hs_out = hs
#pragma unroll
    for (int uq = 0; uq < NU; uq++) {
        if (s_pos[uq] < 0) {
            const float* src = hs + ((size_t)b * NU + uq) * HH;
            float* dst = hs_out + ((size_t)b * NU + uq) * HH;
            for (int i = t; i < HH; i += 256) dst[i] = src[i];
        }
    }
}

// ------------------------- launch -------------------------
extern "C" void kernel_launch(void* const* d_in, const int* in_sizes, int n_in,
                              void* d_out, int out_size)
{
    const float* x    = (const float*)d_in[0];
    const float* hs   = (const float*)d_in[1];
    const float* cs   = (const float*)d_in[2];
    const float* Wk   = (const float*)d_in[3];
    const float* Wv   = (const float*)d_in[4];
    const float* Wq   = (const float*)d_in[5];
    const float* Wi2h = (const float*)d_in[6];
    const float* Wh2h = (const float*)d_in[7];
    const float* Wck  = (const float*)d_in[8];
    const float* Wcq  = (const float*)d_in[9];
    const float* Wcv  = (const float*)d_in[10];
    const float* Wco  = (const float*)d_in[11];

    float* hs_out = (float*)d_out;
    float* cs_out = hs_out + (size_t)BB * NU * HH;

    float *xk, *qry, *scale, *mask, *hb;
    int *cnt, *posmap, *blist;
    __half *xvh, *cvq, *aph, *hbh, *cxc, *x16, *w12h, *wcvq, *w4h, *wv16;
    cudaGetSymbolAddress((void**)&xk, g_xk);
    cudaGetSymbolAddress((void**)&qry, g_qry);     cudaGetSymbolAddress((void**)&scale, g_scale);
    cudaGetSymbolAddress((void**)&mask, g_mask);   cudaGetSymbolAddress((void**)&hb, g_hb);
    cudaGetSymbolAddress((void**)&cnt, g_cnt);
    cudaGetSymbolAddress((void**)&posmap, g_posmap);
    cudaGetSymbolAddress((void**)&blist, g_blist);
    cudaGetSymbolAddress((void**)&xvh, g_xvh);
    cudaGetSymbolAddress((void**)&cvq, g_cvq);
    cudaGetSymbolAddress((void**)&aph, g_aph);
    cudaGetSymbolAddress((void**)&hbh, g_hbh);
    cudaGetSymbolAddress((void**)&cxc, g_cxc);
    cudaGetSymbolAddress((void**)&x16, g_x16);
    cudaGetSymbolAddress((void**)&w12h, g_w12h);
    cudaGetSymbolAddress((void**)&wcvq, g_wcvq);
    cudaGetSymbolAddress((void**)&w4h, g_w4h);
    cudaGetSymbolAddress((void**)&wv16, g_wv16);

    cudaFuncSetAttribute(hmma_gemm<4>, cudaFuncAttributeMaxDynamicSharedMemorySize, SMEM_DYN);
    cudaFuncSetAttribute(hmma_gemm<5>, cudaFuncAttributeMaxDynamicSharedMemorySize, SMEM_DYN);
    cudaFuncSetAttribute(hmma_gemm<6>, cudaFuncAttributeMaxDynamicSharedMemorySize, SMEM_DYN);

    // static side stream + events (created on the uncaptured correctness call;
    // reused as-is during graph capture — only record/wait ops are captured)
    static cudaStream_t s_side = nullptr;
    static cudaEvent_t s_fork = nullptr, s_join = nullptr;
    if (!s_side) {
        cudaStreamCreateWithFlags(&s_side, cudaStreamNonBlocking);
        cudaEventCreateWithFlags(&s_fork, cudaEventDisableTiming);
        cudaEventCreateWithFlags(&s_join, cudaEventDisableTiming);
    }

    // fork: side stream runs the fp32 mask path concurrently with weight prep
    cudaEventRecord(s_fork, (cudaStream_t)0);
    cudaStreamWaitEvent(s_side, s_fork, 0);

    zero_cnt<<<1, 32, 0, s_side>>>(cnt);
    xkqry_simt<<<dim3(1, 64, 7), 256, 0, s_side>>>(x, hs, Wk, Wq, xk, qry);
    score_topk<<<(BB * 32 + 255) / 256, 256, 0, s_side>>>(qry, xk, scale, mask, cnt, posmap, blist);
    cudaEventRecord(s_join, s_side);

    // main stream: weight transposes + x conversion + xv GEMM
    wtrans_all<<<17092, 256>>>(Wi2h, Wh2h, Wcv, Wco, Wck, Wcq, Wv,
                               w12h, wcvq, w4h, wv16);
    conv_x<<<(BB * KP_X + 255) / 256, 256>>>(x, x16);
    hmma_gemm<4><<<dim3(4, 32, 1), 256, SMEM_DYN>>>(
        x16, 0LL, KP_X, wv16, 0LL, xvh, VDD, 0, VDD,
        nullptr, nullptr, nullptr, nullptr, nullptr, nullptr);

    // join: conv_pre needs scale (side) + xvh (main)
    cudaStreamWaitEvent((cudaStream_t)0, s_join, 0);

    conv_pre<<<(int)(((size_t)NU * BB * (KP_PRE / 2) + 255) / 256), 256>>>(xvh, hs, scale, aph);

    // preact GEMM + fused LSTM epilogue -> hb, hbh, cs_out
    hmma_gemm<5><<<dim3(19, 32, NU), 256, SMEM_DYN>>>(
        aph, (long long)BB * KP_PRE, KP_PRE, w12h, (long long)NP_BIG * KP_PRE,
        hb, 0, 0, 2400, mask, cs, cs_out, hbh, nullptr, nullptr);

    // cv | ck | cq combined (N=2688, fp16 out)
    hmma_gemm<4><<<dim3(21, 32, NU), 256, SMEM_DYN>>>(
        hbh, (long long)BB * KP_H, KP_H, wcvq, (long long)NP_CVQ * KP_H,
        cvq, NU * NP_CVQ, NP_CVQ, NP_CVQ, nullptr, nullptr, nullptr, nullptr, nullptr, nullptr);

    // comm attention (+ inactive hs copy)
    comm_attn<<<BB, 256>>>(cvq, mask, posmap, hs, hs_out, cxc);

    // hs_out (active rows only) = ctx_compact @ Wco + hb, scattered by blist
    hmma_gemm<6><<<dim3(5, 32, NU), 256, SMEM_DYN>>>(
        cxc, (long long)BB * KP_CTX, KP_CTX, w4h, (long long)NP_H * KP_CTX,
        hs_out, 0, 0, HH, nullptr, hb, nullptr, nullptr, blist, cnt);

    (void)in_sizes; (void)n_in; (void)out_size;
}